// round 6
// baseline (speedup 1.0000x reference)
#include <cuda_runtime.h>
#include <cuda_bf16.h>
#include <math.h>
#include <stdint.h>

// ---------------- problem constants ----------------
#define Bsz   8
#define Tfull 1600
#define Dm    512
#define DIc   1024
#define Nst   16
#define Ll    8
#define Vv    1024
#define T4    400
#define M4    (Bsz*T4)    // 3200
#define M2    (Bsz*800)   // 6400

// ---------------- scratch (single __device__ array, ~235MB) ----------------
__device__ float g_buf[58713984];

#define OFF_FEATSP_T 0
#define OFF_OUT1P_T  1537920
#define OFF_XN_T     6465408
#define OFF_XZ       8923008
#define OFF_XI       15476608
#define OFF_XI_T     18753408
#define OFF_DT       23668608
#define OFF_PROJ     26945408
#define OFF_PROJ_T   27150208
#define OFF_YC_T     27355008
#define OFF_X        32270208
#define OFF_X_T      33908608
#define OFF_W1T      36366208
#define OFF_W2T      36562816
#define OFF_INW      37742464
#define OFF_XW       50325376
#define OFF_DTW      51111808
#define OFF_OUTW     51636096
#define OFF_HEADW    57927552

// ---------------- math helpers ----------------
__device__ __forceinline__ float gelu_f(float x) {
    return 0.5f * x * (1.0f + erff(x * 0.70710678118654752f));
}
__device__ __forceinline__ float softplus_f(float x) {
    return fmaxf(x, 0.0f) + log1pf(expf(-fabsf(x)));
}
// A-side triple (hi, hi, md)
__device__ __forceinline__ void atrip(float v, __nv_bfloat16* p) {
    __nv_bfloat16 h = __float2bfloat16(v);
    p[0] = h; p[1] = h;
    p[2] = __float2bfloat16(v - __bfloat162float(h));
}
// B-side value for position r in (hi, md, hi)
__device__ __forceinline__ __nv_bfloat16 bsplit(float w, int r) {
    __nv_bfloat16 h = __float2bfloat16(w);
    if (r == 1) return __float2bfloat16(w - __bfloat162float(h));
    return h;
}

// ---------------- PTX helpers ----------------
__device__ __forceinline__ uint32_t smem_u32(const void* p) {
    uint32_t a;
    asm("{ .reg .u64 t; cvta.to.shared.u64 t, %1; cvt.u32.u64 %0, t; }" : "=r"(a) : "l"(p));
    return a;
}
#define SW128(x) ((x) ^ (((x) >> 3) & 0x70))
__device__ __forceinline__ void cp16(uint32_t dst, const void* src) {
    asm volatile("cp.async.cg.shared.global [%0], [%1], 16;" :: "r"(dst), "l"(src) : "memory");
}
__device__ __forceinline__ void ldsm4(uint32_t* r, uint32_t addr) {
    asm volatile("ldmatrix.sync.aligned.m8n8.x4.shared.b16 {%0,%1,%2,%3}, [%4];"
                 : "=r"(r[0]), "=r"(r[1]), "=r"(r[2]), "=r"(r[3]) : "r"(addr));
}
__device__ __forceinline__ void mma16(float* c, const uint32_t* a, const uint32_t* b) {
    asm volatile(
        "mma.sync.aligned.m16n8k16.row.col.f32.bf16.bf16.f32 "
        "{%0,%1,%2,%3},{%4,%5,%6,%7},{%8,%9},{%0,%1,%2,%3};"
        : "+f"(c[0]), "+f"(c[1]), "+f"(c[2]), "+f"(c[3])
        : "r"(a[0]), "r"(a[1]), "r"(a[2]), "r"(a[3]), "r"(b[0]), "r"(b[1]));
}

// ---------------- bf16 tensor-core GEMM (legacy mma, 3x-split data) ----------------
// D[m,n] = sum_k' A[arow(m) + k'] * Bw[n*bpitch + k']   (k' = tripled K)
//   arow(m) = (m/a_rpb)*a_bs + (m%a_rpb)*a_rs   (bf16 elements)
//   orow(m) = (m/o_rpb)*o_bs + (m%o_rpb)*o_rs   (f32 elems, or bf16 elems if outmode=1)
// NC = K'/64 chunks. act: 0 none, 1 GELU, 2 softplus. outmode 1: write bf16 triple.
template<int BN>
__global__ void __launch_bounds__(256, 1) bgemm_k(
        const __nv_bfloat16* __restrict__ A,
        const __nv_bfloat16* __restrict__ Bw,
        const float* __restrict__ bias,
        void* __restrict__ Cv,
        int NC, int bpitch,
        int a_rpb, long long a_bs, int a_rs,
        int o_rpb, long long o_bs, int o_rs,
        int act, int outmode, int accum) {
    extern __shared__ char smem_raw[];
    uint32_t sb = (smem_u32(smem_raw) + 1023) & ~1023u;
    const uint32_t Ab0 = sb;
    const uint32_t Ab1 = sb + 16384;
    const uint32_t Bb0 = sb + 32768;
    const uint32_t Bb1 = Bb0 + BN * 128;

    int tid = threadIdx.x, wid = tid >> 5, lane = tid & 31;
    int bm = blockIdx.y * 128, bn = blockIdx.x * BN;

    // global->smem loader precompute (16B granules; tile row = 128B = 64 bf16)
    constexpr int AG = 4;            // 1024 granules / 256 threads
    constexpr int BG = (BN * 8) / 256;
    const char* abase[AG]; uint32_t adst[AG];
#pragma unroll
    for (int i = 0; i < AG; i++) {
        int G = tid + i * 256;
        int row = G >> 3;
        int gm = bm + row;
        long long aoff = (long long)(gm / a_rpb) * a_bs + (long long)(gm % a_rpb) * a_rs;
        abase[i] = (const char*)(A + aoff + (G & 7) * 8);
        adst[i] = SW128((uint32_t)(row * 128 + (G & 7) * 16));
    }
    const char* bbase[BG]; uint32_t bdst[BG];
#pragma unroll
    for (int i = 0; i < BG; i++) {
        int G = tid + i * 256;
        int row = G >> 3;
        bbase[i] = (const char*)(Bw + (long long)(bn + row) * bpitch + (G & 7) * 8);
        bdst[i] = SW128((uint32_t)(row * 128 + (G & 7) * 16));
    }

    auto issue = [&](int c, uint32_t Ax, uint32_t Bx) {
        long long kb = (long long)c * 128;   // 64 bf16 = 128 bytes
#pragma unroll
        for (int i = 0; i < AG; i++) cp16(Ax + adst[i], abase[i] + kb);
#pragma unroll
        for (int i = 0; i < BG; i++) cp16(Bx + bdst[i], bbase[i] + kb);
        asm volatile("cp.async.commit_group;" ::: "memory");
    };

    // warp tiling: 4 m-strips of 32, 2 n-strips of BN/2
    int wm = wid & 3, wn = wid >> 2;
    constexpr int NT = BN / 16;      // 8 (BN=128) or 4 (BN=64)
    float acc[2][NT][4];
#pragma unroll
    for (int i = 0; i < 2; i++)
#pragma unroll
        for (int j = 0; j < NT; j++)
#pragma unroll
            for (int r = 0; r < 4; r++) acc[i][j][r] = 0.0f;

    // ldmatrix per-thread address components
    int a_trow = (lane & 7) + ((lane >> 3) & 1) * 8;    // + m0
    int a_tcol = (lane >> 4) * 16;                      // + ks*32
    int b_trow = ((lane >> 4) << 3) + (lane & 7);       // + n0
    int b_tcol = ((lane >> 3) & 1) * 16;                // + ks*32

    issue(0, Ab0, Bb0);

    for (int c = 0; c < NC; c++) {
        uint32_t Ax = (c & 1) ? Ab1 : Ab0;
        uint32_t Bx = (c & 1) ? Bb1 : Bb0;
        if (c + 1 < NC) {
            issue(c + 1, (c & 1) ? Ab0 : Ab1, (c & 1) ? Bb0 : Bb1);
            asm volatile("cp.async.wait_group 1;" ::: "memory");
        } else {
            asm volatile("cp.async.wait_group 0;" ::: "memory");
        }
        __syncthreads();

#pragma unroll
        for (int ks = 0; ks < 4; ks++) {
            uint32_t a[2][4];
#pragma unroll
            for (int i = 0; i < 2; i++) {
                int trow = wm * 32 + i * 16 + a_trow;
                ldsm4(a[i], Ax + SW128((uint32_t)(trow * 128 + ks * 32 + a_tcol)));
            }
            uint32_t b[NT][2];
#pragma unroll
            for (int jp = 0; jp < NT / 2; jp++) {
                int trow = wn * (NT * 8) + jp * 16 + b_trow;
                uint32_t r[4];
                ldsm4(r, Bx + SW128((uint32_t)(trow * 128 + ks * 32 + b_tcol)));
                b[2 * jp][0] = r[0]; b[2 * jp][1] = r[1];
                b[2 * jp + 1][0] = r[2]; b[2 * jp + 1][1] = r[3];
            }
#pragma unroll
            for (int i = 0; i < 2; i++)
#pragma unroll
                for (int j = 0; j < NT; j++) mma16(acc[i][j], a[i], b[j]);
        }
        __syncthreads();
    }

    // ---------------- epilogue (direct from registers) ----------------
#pragma unroll
    for (int i = 0; i < 2; i++) {
#pragma unroll
        for (int h = 0; h < 2; h++) {   // row halves (+0 / +8)
            int gm = bm + wm * 32 + i * 16 + (lane >> 2) + h * 8;
            long long orow = (long long)(gm / o_rpb) * o_bs + (long long)(gm % o_rpb) * o_rs;
#pragma unroll
            for (int j = 0; j < NT; j++) {
                int gn = bn + wn * (NT * 8) + j * 8 + (lane & 3) * 2;
#pragma unroll
                for (int e = 0; e < 2; e++) {
                    float v = acc[i][j][h * 2 + e];
                    int gne = gn + e;
                    if (bias) v += bias[gne];
                    if (act == 1) v = gelu_f(v);
                    else if (act == 2) v = softplus_f(v);
                    if (outmode == 0) {
                        float* C = (float*)Cv;
                        long long o = orow + gne;
                        if (accum) v += C[o];
                        C[o] = v;
                    } else {
                        __nv_bfloat16* C = (__nv_bfloat16*)Cv;
                        long long o = orow + (long long)gne * 3;
                        __nv_bfloat16 hh = __float2bfloat16(v);
                        C[o] = hh; C[o + 1] = hh;
                        C[o + 2] = __float2bfloat16(v - __bfloat162float(hh));
                    }
                }
            }
        }
    }
}

// ---------------- converters / prep ----------------
__global__ void prep_feats_t_k(const float* __restrict__ feats, __nv_bfloat16* __restrict__ fp) {
    int i = blockIdx.x * 256 + threadIdx.x;
    if (i < Bsz * Tfull * 80) {
        int c = i % 80;
        int t = (i / 80) % Tfull;
        int b = i / (80 * Tfull);
        atrip(feats[i], fp + ((long long)(b * 1602 + t + 1) * 240 + c * 3));
    }
    if (i < Bsz * 2 * 240) {
        int e = i % 240; int r = i / 240;
        int b = r >> 1; int t = (r & 1) ? 1601 : 0;
        fp[(long long)(b * 1602 + t) * 240 + e] = __float2bfloat16(0.0f);
    }
}

__global__ void zero_out1p_t_k(__nv_bfloat16* __restrict__ op) {
    int i = blockIdx.x * 256 + threadIdx.x;
    if (i < Bsz * 2 * 1536) {
        int e = i % 1536; int r = i / 1536;
        int b = r >> 1; int t = (r & 1) ? 801 : 0;
        op[(long long)(b * 802 + t) * 1536 + e] = __float2bfloat16(0.0f);
    }
}

// conv1 weights: rows n (512), kpitch 768 (kp>=720 zero)
__global__ void wconv1_k(const float* __restrict__ w, __nv_bfloat16* __restrict__ wt) {
    int i = blockIdx.x * 256 + threadIdx.x;
    if (i >= 512 * 768) return;
    int n = i / 768, kp = i % 768;
    __nv_bfloat16 v = __float2bfloat16(0.0f);
    if (kp < 720) {
        int k = kp / 3, r = kp % 3;
        int tap = k / 80, c = k % 80;
        v = bsplit(w[n * 240 + c * 3 + tap], r);
    }
    wt[i] = v;
}
// conv2 weights: rows n (512), kpitch 4608
__global__ void wconv2_k(const float* __restrict__ w, __nv_bfloat16* __restrict__ wt) {
    int i = blockIdx.x * 256 + threadIdx.x;
    if (i >= 512 * 4608) return;
    int n = i / 4608, kp = i % 4608;
    int k = kp / 3, r = kp % 3;
    int tap = k / 512, c = k % 512;
    wt[i] = bsplit(w[n * 1536 + c * 3 + tap], r);
}

#define S0 (2048*1536)
#define S1 (64*3072)
#define S2 (1024*128)
#define S3 (512*3072)
__global__ void layer_wconv_k(const float* __restrict__ inw, const float* __restrict__ xw,
                              const float* __restrict__ dtw, const float* __restrict__ outw,
                              __nv_bfloat16* __restrict__ o_in, __nv_bfloat16* __restrict__ o_x,
                              __nv_bfloat16* __restrict__ o_dt, __nv_bfloat16* __restrict__ o_out) {
    int i = blockIdx.x * 256 + threadIdx.x;
    if (i < S0) {
        int n = i / 1536, kp = i % 1536;
        int k = kp / 3, r = kp % 3;
        o_in[i] = bsplit(inw[k * 2048 + n], r);
        return;
    }
    i -= S0;
    if (i < S1) {
        int n = i / 3072, kp = i % 3072;
        int k = kp / 3, r = kp % 3;
        o_x[i] = bsplit(xw[k * 64 + n], r);
        return;
    }
    i -= S1;
    if (i < S2) {
        int n = i / 128, kp = i % 128;
        __nv_bfloat16 v = __float2bfloat16(0.0f);
        if (kp < 96) {
            int k = kp / 3, r = kp % 3;
            v = bsplit(dtw[k * 1024 + n], r);
        }
        o_dt[i] = v;
        return;
    }
    i -= S2;
    if (i < S3) {
        int n = i / 3072, kp = i % 3072;
        int k = kp / 3, r = kp % 3;
        o_out[i] = bsplit(outw[k * 512 + n], r);
    }
}

__global__ void whead_k(const float* __restrict__ w, __nv_bfloat16* __restrict__ wt) {
    int i = blockIdx.x * 256 + threadIdx.x;
    if (i >= 1024 * 1536) return;
    int n = i / 1536, kp = i % 1536;
    int k = kp / 3, r = kp % 3;
    wt[i] = bsplit(w[k * 1024 + n], r);
}

__global__ void proj_t_k(const float* __restrict__ proj, __nv_bfloat16* __restrict__ pt) {
    int i = blockIdx.x * 256 + threadIdx.x;
    if (i >= M4 * 128) return;
    int m = i >> 7, kp = i & 127;
    __nv_bfloat16 v = __float2bfloat16(0.0f);
    if (kp < 96) {
        int k = kp / 3, r = kp % 3;
        float f = proj[m * 64 + k];
        __nv_bfloat16 h = __float2bfloat16(f);
        v = (r == 2) ? __float2bfloat16(f - __bfloat162float(h)) : h;   // A-side (hi,hi,md)
    }
    pt[i] = v;
}

__global__ void x_t_k(const float* __restrict__ x, __nv_bfloat16* __restrict__ xt) {
    int i = blockIdx.x * 256 + threadIdx.x;
    if (i >= M4 * Dm) return;
    atrip(x[i], xt + (long long)i * 3);
}

// ---------------- RMSNorm -> bf16 triple ----------------
__global__ void rmsnorm_t_k(const float* __restrict__ x, const float* __restrict__ w,
                            __nv_bfloat16* __restrict__ xnt) {
    int row = blockIdx.x;
    int tid = threadIdx.x;   // 128
    const float* xr = x + row * Dm;
    float v[4];
    float s = 0.0f;
#pragma unroll
    for (int i = 0; i < 4; i++) { v[i] = xr[tid + 128 * i]; s += v[i] * v[i]; }
#pragma unroll
    for (int o = 16; o; o >>= 1) s += __shfl_xor_sync(0xffffffffu, s, o);
    __shared__ float ws[4];
    if ((tid & 31) == 0) ws[tid >> 5] = s;
    __syncthreads();
    float tot = ws[0] + ws[1] + ws[2] + ws[3];
    float rs = rsqrtf(tot * (1.0f / Dm) + 1e-5f);
#pragma unroll
    for (int i = 0; i < 4; i++) {
        int c = tid + 128 * i;
        atrip(v[i] * rs * w[c], xnt + (long long)row * 1536 + c * 3);
    }
}

// ---------------- depthwise causal conv (K=4) + SiLU ----------------
__global__ void dwconv_k(const float* __restrict__ xz, const float* __restrict__ cw,
                         const float* __restrict__ cb, float* __restrict__ xi,
                         __nv_bfloat16* __restrict__ xit) {
    int idx = blockIdx.x * 256 + threadIdx.x;
    if (idx >= M4 * DIc) return;
    int d = idx & (DIc - 1);
    int m = idx >> 10;
    int t = m % T4;
    float w0 = cw[d * 4 + 0], w1 = cw[d * 4 + 1], w2 = cw[d * 4 + 2], w3 = cw[d * 4 + 3];
    const float* base = xz + (long long)m * 2048 + d;
    float acc = w3 * base[0];
    if (t >= 1) acc = fmaf(w2, base[-2048], acc);
    if (t >= 2) acc = fmaf(w1, base[-2 * 2048], acc);
    if (t >= 3) acc = fmaf(w0, base[-3 * 2048], acc);
    acc += cb[d];
    float s = acc / (1.0f + expf(-acc));
    xi[idx] = s;
    atrip(s, xit + (long long)m * 3072 + d * 3);
}

// ---------------- selective scan -> yc triple ----------------
__global__ void scan_k(const float* __restrict__ dt, const float* __restrict__ xi,
                       const float* __restrict__ proj, const float* __restrict__ xz,
                       const float* __restrict__ A_log, const float* __restrict__ dskip,
                       __nv_bfloat16* __restrict__ yct) {
    int w = (blockIdx.x * blockDim.x + threadIdx.x) >> 5;
    int lane = threadIdx.x & 31;
    int b = w >> 9;
    int dp = w & 511;
    int d = dp * 2 + (lane >> 4);
    int n = lane & 15;
    float Ac = -expf(A_log[d * Nst + n]);
    float dsk = dskip[d];
    float h = 0.0f;
    int mb = b * T4;
    for (int t = 0; t < T4; t++) {
        int m = mb + t;
        float dtv = dt[m * DIc + d];
        float xiv = xi[m * DIc + d];
        float Bv = proj[m * 64 + 32 + n];
        float Cv = proj[m * 64 + 48 + n];
        float dA = __expf(dtv * Ac);
        h = fmaf(dA, h, dtv * xiv * Bv);
        float p = h * Cv;
        p += __shfl_xor_sync(0xffffffffu, p, 8);
        p += __shfl_xor_sync(0xffffffffu, p, 4);
        p += __shfl_xor_sync(0xffffffffu, p, 2);
        p += __shfl_xor_sync(0xffffffffu, p, 1);
        if (n == 0) {
            float zv = xz[(long long)m * 2048 + DIc + d];
            float yv = p + dsk * xiv;
            atrip(yv * zv / (1.0f + __expf(-zv)), yct + (long long)m * 3072 + d * 3);
        }
    }
}

__global__ void lens_k(const int* __restrict__ fl, float* __restrict__ out, int out_size) {
    int b = threadIdx.x;
    if (b < Bsz && out_size >= M4 * Vv + Bsz) {
        int v = fl[b] >> 2;
        if (v < 1) v = 1;
        out[M4 * Vv + b] = (float)v;
    }
}

// ---------------- launcher ----------------
extern "C" void kernel_launch(void* const* d_in, const int* in_sizes, int n_in,
                              void* d_out, int out_size) {
    (void)in_sizes; (void)n_in;
    const float* feats    = (const float*)d_in[0];
    const int*   feat_lens= (const int*)  d_in[1];
    const float* conv1_w  = (const float*)d_in[2];
    const float* conv1_b  = (const float*)d_in[3];
    const float* conv2_w  = (const float*)d_in[4];
    const float* conv2_b  = (const float*)d_in[5];
    const float* norm_w   = (const float*)d_in[6];
    const float* in_proj  = (const float*)d_in[7];
    const float* dwc_w    = (const float*)d_in[8];
    const float* dwc_b    = (const float*)d_in[9];
    const float* x_proj   = (const float*)d_in[10];
    const float* dt_w     = (const float*)d_in[11];
    const float* dt_b     = (const float*)d_in[12];
    const float* A_log    = (const float*)d_in[13];
    const float* D_skip   = (const float*)d_in[14];
    const float* out_proj = (const float*)d_in[15];
    const float* head_w   = (const float*)d_in[16];
    const float* head_b   = (const float*)d_in[17];
    float* out = (float*)d_out;

    void* sym = nullptr;
    cudaGetSymbolAddress(&sym, g_buf);
    float* gb = (float*)sym;
    __nv_bfloat16* featsp_t = (__nv_bfloat16*)(gb + OFF_FEATSP_T);
    __nv_bfloat16* out1p_t  = (__nv_bfloat16*)(gb + OFF_OUT1P_T);
    __nv_bfloat16* xn_t     = (__nv_bfloat16*)(gb + OFF_XN_T);
    float*         xz       = gb + OFF_XZ;
    float*         xi       = gb + OFF_XI;
    __nv_bfloat16* xi_t     = (__nv_bfloat16*)(gb + OFF_XI_T);
    float*         dtbuf    = gb + OFF_DT;
    float*         proj     = gb + OFF_PROJ;
    __nv_bfloat16* proj_t   = (__nv_bfloat16*)(gb + OFF_PROJ_T);
    __nv_bfloat16* yc_t     = (__nv_bfloat16*)(gb + OFF_YC_T);
    float*         x        = gb + OFF_X;
    __nv_bfloat16* x_t      = (__nv_bfloat16*)(gb + OFF_X_T);
    __nv_bfloat16* w1t      = (__nv_bfloat16*)(gb + OFF_W1T);
    __nv_bfloat16* w2t      = (__nv_bfloat16*)(gb + OFF_W2T);
    __nv_bfloat16* inW      = (__nv_bfloat16*)(gb + OFF_INW);
    __nv_bfloat16* xW       = (__nv_bfloat16*)(gb + OFF_XW);
    __nv_bfloat16* dtW      = (__nv_bfloat16*)(gb + OFF_DTW);
    __nv_bfloat16* outW     = (__nv_bfloat16*)(gb + OFF_OUTW);
    __nv_bfloat16* headW    = (__nv_bfloat16*)(gb + OFF_HEADW);

    const int SM128 = 1024 + 65536;  // 66560
    const int SM64  = 1024 + 49152;  // 50176
    cudaFuncSetAttribute(bgemm_k<128>, cudaFuncAttributeMaxDynamicSharedMemorySize, SM128);
    cudaFuncSetAttribute(bgemm_k<64>,  cudaFuncAttributeMaxDynamicSharedMemorySize, SM64);

    // prep + weight conversion
    wconv1_k<<<(512 * 768 + 255) / 256, 256>>>(conv1_w, w1t);
    wconv2_k<<<(512 * 4608 + 255) / 256, 256>>>(conv2_w, w2t);
    prep_feats_t_k<<<(Bsz * Tfull * 80 + 255) / 256, 256>>>(feats, featsp_t);

    // conv1: M=6400, N=512, K'=768 -> out1p_t (triple, rows shifted by +1 pad row)
    bgemm_k<128><<<dim3(4, 50), 256, SM128>>>(
        featsp_t, w1t, conv1_b, out1p_t + 1536,
        12, 768,
        800, 1602LL * 240, 480,
        800, 802LL * 1536, 1536,
        1, 1, 0);

    zero_out1p_t_k<<<(Bsz * 2 * 1536 + 255) / 256, 256>>>(out1p_t);

    // conv2: M=3200, N=512, K'=4608 -> x f32
    bgemm_k<128><<<dim3(4, 25), 256, SM128>>>(
        out1p_t, w2t, conv2_b, x,
        72, 4608,
        400, 802LL * 1536, 3072,
        M4, 0, 512,
        1, 0, 0);

    for (int l = 0; l < Ll; l++)
        layer_wconv_k<<<(S0 + S1 + S2 + S3 + 255) / 256, 256>>>(
            in_proj + (size_t)l * Dm * 2048, x_proj + (size_t)l * DIc * 64,
            dt_w + (size_t)l * 32 * DIc, out_proj + (size_t)l * DIc * Dm,
            inW + (size_t)l * S0, xW + (size_t)l * S1,
            dtW + (size_t)l * S2, outW + (size_t)l * S3);
    whead_k<<<(1024 * 1536 + 255) / 256, 256>>>(head_w, headW);

    for (int l = 0; l < Ll; l++) {
        rmsnorm_t_k<<<M4, 128>>>(x, norm_w + l * Dm, xn_t);

        // xz = xn @ in_proj  (3200x2048, K'=1536)
        bgemm_k<128><<<dim3(16, 25), 256, SM128>>>(
            xn_t, inW + (size_t)l * S0, nullptr, xz,
            24, 1536,
            M4, 0, 1536,
            M4, 0, 2048,
            0, 0, 0);

        dwconv_k<<<(M4 * DIc + 255) / 256, 256>>>(
            xz, dwc_w + l * DIc * 4, dwc_b + l * DIc, xi, xi_t);

        // proj = xi @ x_proj  (3200x64, K'=3072)
        bgemm_k<64><<<dim3(1, 25), 256, SM64>>>(
            xi_t, xW + (size_t)l * S1, nullptr, proj,
            48, 3072,
            M4, 0, 3072,
            M4, 0, 64,
            0, 0, 0);

        proj_t_k<<<(M4 * 128 + 255) / 256, 256>>>(proj, proj_t);

        // dt = softplus(proj @ dt_w + dt_b)  (3200x1024, K'=128)
        bgemm_k<128><<<dim3(8, 25), 256, SM128>>>(
            proj_t, dtW + (size_t)l * S2, dt_b + l * DIc, dtbuf,
            2, 128,
            M4, 0, 128,
            M4, 0, 1024,
            2, 0, 0);

        scan_k<<<512, 256>>>(dtbuf, xi, proj, xz,
                             A_log + (size_t)l * DIc * Nst, D_skip + l * DIc, yc_t);

        // x += yc @ out_proj  (3200x512, K'=3072)
        bgemm_k<128><<<dim3(4, 25), 256, SM128>>>(
            yc_t, outW + (size_t)l * S3, nullptr, x,
            48, 3072,
            M4, 0, 3072,
            M4, 0, 512,
            0, 0, 1);
    }

    x_t_k<<<(M4 * Dm + 255) / 256, 256>>>(x, x_t);

    // logits = x @ head_w + head_b  (3200x1024, K'=1536)
    bgemm_k<128><<<dim3(8, 25), 256, SM128>>>(
        x_t, headW, head_b, out,
        24, 1536,
        M4, 0, 1536,
        M4, 0, 1024,
        0, 0, 0);

    lens_k<<<1, 32>>>(feat_lens, out, out_size);
}

// round 7
// speedup vs baseline: 1.0441x; 1.0441x over previous
#include <cuda_runtime.h>
#include <cuda_bf16.h>
#include <math.h>
#include <stdint.h>

// ---------------- problem constants ----------------
#define Bsz   8
#define Tfull 1600
#define Dm    512
#define DIc   1024
#define Nst   16
#define Ll    8
#define Vv    1024
#define T4    400
#define M4    (Bsz*T4)    // 3200
#define M2    (Bsz*800)   // 6400

// ---------------- scratch (single __device__ array, ~235MB) ----------------
__device__ float g_buf[58713984];

#define OFF_FEATSP_T 0
#define OFF_OUT1P_T  1537920
#define OFF_XN_T     6465408
#define OFF_XZ       8923008
#define OFF_XI       15476608
#define OFF_XI_T     18753408
#define OFF_DT       23668608
#define OFF_PROJ     26945408
#define OFF_PROJ_T   27150208
#define OFF_YC_T     27355008
#define OFF_X        32270208
#define OFF_X_T      33908608
#define OFF_W1T      36366208
#define OFF_W2T      36562816
#define OFF_INW      37742464
#define OFF_XW       50325376
#define OFF_DTW      51111808
#define OFF_OUTW     51636096
#define OFF_HEADW    57927552

// ---------------- math helpers ----------------
__device__ __forceinline__ float gelu_f(float x) {
    return 0.5f * x * (1.0f + erff(x * 0.70710678118654752f));
}
__device__ __forceinline__ float softplus_f(float x) {
    return fmaxf(x, 0.0f) + log1pf(expf(-fabsf(x)));
}
// A-side triple (hi, hi, md)
__device__ __forceinline__ void atrip(float v, __nv_bfloat16* p) {
    __nv_bfloat16 h = __float2bfloat16(v);
    p[0] = h; p[1] = h;
    p[2] = __float2bfloat16(v - __bfloat162float(h));
}
// B-side value for position r in (hi, md, hi)
__device__ __forceinline__ __nv_bfloat16 bsplit(float w, int r) {
    __nv_bfloat16 h = __float2bfloat16(w);
    if (r == 1) return __float2bfloat16(w - __bfloat162float(h));
    return h;
}

// ---------------- PTX helpers ----------------
__device__ __forceinline__ uint32_t smem_u32(const void* p) {
    uint32_t a;
    asm("{ .reg .u64 t; cvta.to.shared.u64 t, %1; cvt.u32.u64 %0, t; }" : "=r"(a) : "l"(p));
    return a;
}
#define SW128(x) ((x) ^ (((x) >> 3) & 0x70))
__device__ __forceinline__ void cp16(uint32_t dst, const void* src) {
    asm volatile("cp.async.cg.shared.global [%0], [%1], 16;" :: "r"(dst), "l"(src) : "memory");
}
__device__ __forceinline__ void ldsm4(uint32_t* r, uint32_t addr) {
    asm volatile("ldmatrix.sync.aligned.m8n8.x4.shared.b16 {%0,%1,%2,%3}, [%4];"
                 : "=r"(r[0]), "=r"(r[1]), "=r"(r[2]), "=r"(r[3]) : "r"(addr));
}
__device__ __forceinline__ void mma16(float* c, const uint32_t* a, const uint32_t* b) {
    asm volatile(
        "mma.sync.aligned.m16n8k16.row.col.f32.bf16.bf16.f32 "
        "{%0,%1,%2,%3},{%4,%5,%6,%7},{%8,%9},{%0,%1,%2,%3};"
        : "+f"(c[0]), "+f"(c[1]), "+f"(c[2]), "+f"(c[3])
        : "r"(a[0]), "r"(a[1]), "r"(a[2]), "r"(a[3]), "r"(b[0]), "r"(b[1]));
}

// ---------------- bf16 tensor-core GEMM (legacy mma, 3x-split data) ----------------
// D[m,n] = sum_k' A[arow(m) + k'] * Bw[n*bpitch + k']   (k' = tripled K)
// 3-stage cp.async pipeline, 2 CTAs/SM.
template<int BN>
__global__ void __launch_bounds__(256, 2) bgemm_k(
        const __nv_bfloat16* __restrict__ A,
        const __nv_bfloat16* __restrict__ Bw,
        const float* __restrict__ bias,
        void* __restrict__ Cv,
        int NC, int bpitch,
        int a_rpb, long long a_bs, int a_rs,
        int o_rpb, long long o_bs, int o_rs,
        int act, int outmode, int accum) {
    extern __shared__ char smem_raw[];
    uint32_t sb = (smem_u32(smem_raw) + 1023) & ~1023u;
    constexpr uint32_t STG = 16384u + BN * 128u;   // A stage + B stage

    int tid = threadIdx.x, wid = tid >> 5, lane = tid & 31;
    int bm = blockIdx.y * 128, bn = blockIdx.x * BN;

    // global->smem loader precompute (16B granules; tile row = 128B = 64 bf16)
    constexpr int AG = 4;            // 1024 granules / 256 threads
    constexpr int BG = (BN * 8) / 256;
    const char* abase[AG]; uint32_t adst[AG];
#pragma unroll
    for (int i = 0; i < AG; i++) {
        int G = tid + i * 256;
        int row = G >> 3;
        int gm = bm + row;
        long long aoff = (long long)(gm / a_rpb) * a_bs + (long long)(gm % a_rpb) * a_rs;
        abase[i] = (const char*)(A + aoff + (G & 7) * 8);
        adst[i] = SW128((uint32_t)(row * 128 + (G & 7) * 16));
    }
    const char* bbase[BG]; uint32_t bdst[BG];
#pragma unroll
    for (int i = 0; i < BG; i++) {
        int G = tid + i * 256;
        int row = G >> 3;
        bbase[i] = (const char*)(Bw + (long long)(bn + row) * bpitch + (G & 7) * 8);
        bdst[i] = SW128((uint32_t)(row * 128 + (G & 7) * 16));
    }

    auto issue = [&](int c) {
        uint32_t Ax = sb + (uint32_t)(c % 3) * STG;
        uint32_t Bx = Ax + 16384u;
        long long kb = (long long)c * 128;   // 64 bf16 = 128 bytes
#pragma unroll
        for (int i = 0; i < AG; i++) cp16(Ax + adst[i], abase[i] + kb);
#pragma unroll
        for (int i = 0; i < BG; i++) cp16(Bx + bdst[i], bbase[i] + kb);
        asm volatile("cp.async.commit_group;" ::: "memory");
    };

    // warp tiling: 4 m-strips of 32, 2 n-strips of BN/2
    int wm = wid & 3, wn = wid >> 2;
    constexpr int NT = BN / 16;      // 8 (BN=128) or 4 (BN=64)
    float acc[2][NT][4];
#pragma unroll
    for (int i = 0; i < 2; i++)
#pragma unroll
        for (int j = 0; j < NT; j++)
#pragma unroll
            for (int r = 0; r < 4; r++) acc[i][j][r] = 0.0f;

    // ldmatrix per-thread address components
    int a_trow = (lane & 7) + ((lane >> 3) & 1) * 8;    // + m0
    int a_tcol = (lane >> 4) * 16;                      // + ks*32
    int b_trow = ((lane >> 4) << 3) + (lane & 7);       // + n0
    int b_tcol = ((lane >> 3) & 1) * 16;                // + ks*32

    issue(0);
    if (NC > 1) issue(1);

    for (int c = 0; c < NC; c++) {
        if (c + 1 < NC) asm volatile("cp.async.wait_group 1;" ::: "memory");
        else            asm volatile("cp.async.wait_group 0;" ::: "memory");
        __syncthreads();
        if (c + 2 < NC) issue(c + 2);

        uint32_t Ax = sb + (uint32_t)(c % 3) * STG;
        uint32_t Bx = Ax + 16384u;
#pragma unroll
        for (int ks = 0; ks < 4; ks++) {
            uint32_t a[2][4];
#pragma unroll
            for (int i = 0; i < 2; i++) {
                int trow = wm * 32 + i * 16 + a_trow;
                ldsm4(a[i], Ax + SW128((uint32_t)(trow * 128 + ks * 32 + a_tcol)));
            }
            uint32_t b[NT][2];
#pragma unroll
            for (int jp = 0; jp < NT / 2; jp++) {
                int trow = wn * (NT * 8) + jp * 16 + b_trow;
                uint32_t r[4];
                ldsm4(r, Bx + SW128((uint32_t)(trow * 128 + ks * 32 + b_tcol)));
                b[2 * jp][0] = r[0]; b[2 * jp][1] = r[1];
                b[2 * jp + 1][0] = r[2]; b[2 * jp + 1][1] = r[3];
            }
#pragma unroll
            for (int i = 0; i < 2; i++)
#pragma unroll
                for (int j = 0; j < NT; j++) mma16(acc[i][j], a[i], b[j]);
        }
    }

    // ---------------- epilogue (direct from registers) ----------------
#pragma unroll
    for (int i = 0; i < 2; i++) {
#pragma unroll
        for (int h = 0; h < 2; h++) {   // row halves (+0 / +8)
            int gm = bm + wm * 32 + i * 16 + (lane >> 2) + h * 8;
            long long orow = (long long)(gm / o_rpb) * o_bs + (long long)(gm % o_rpb) * o_rs;
#pragma unroll
            for (int j = 0; j < NT; j++) {
                int gn = bn + wn * (NT * 8) + j * 8 + (lane & 3) * 2;
#pragma unroll
                for (int e = 0; e < 2; e++) {
                    float v = acc[i][j][h * 2 + e];
                    int gne = gn + e;
                    if (bias) v += bias[gne];
                    if (act == 1) v = gelu_f(v);
                    else if (act == 2) v = softplus_f(v);
                    if (outmode == 0) {
                        float* C = (float*)Cv;
                        long long o = orow + gne;
                        if (accum) v += C[o];
                        C[o] = v;
                    } else {
                        __nv_bfloat16* C = (__nv_bfloat16*)Cv;
                        long long o = orow + (long long)gne * 3;
                        __nv_bfloat16 hh = __float2bfloat16(v);
                        C[o] = hh; C[o + 1] = hh;
                        C[o + 2] = __float2bfloat16(v - __bfloat162float(hh));
                    }
                }
            }
        }
    }
}

// ---------------- converters / prep ----------------
__global__ void prep_feats_t_k(const float* __restrict__ feats, __nv_bfloat16* __restrict__ fp) {
    int i = blockIdx.x * 256 + threadIdx.x;
    if (i < Bsz * Tfull * 80) {
        int c = i % 80;
        int t = (i / 80) % Tfull;
        int b = i / (80 * Tfull);
        atrip(feats[i], fp + ((long long)(b * 1602 + t + 1) * 240 + c * 3));
    }
    if (i < Bsz * 2 * 240) {
        int e = i % 240; int r = i / 240;
        int b = r >> 1; int t = (r & 1) ? 1601 : 0;
        fp[(long long)(b * 1602 + t) * 240 + e] = __float2bfloat16(0.0f);
    }
}

__global__ void zero_out1p_t_k(__nv_bfloat16* __restrict__ op) {
    int i = blockIdx.x * 256 + threadIdx.x;
    if (i < Bsz * 2 * 1536) {
        int e = i % 1536; int r = i / 1536;
        int b = r >> 1; int t = (r & 1) ? 801 : 0;
        op[(long long)(b * 802 + t) * 1536 + e] = __float2bfloat16(0.0f);
    }
}

// conv1 weights: rows n (512), kpitch 768 (kp>=720 zero)
__global__ void wconv1_k(const float* __restrict__ w, __nv_bfloat16* __restrict__ wt) {
    int i = blockIdx.x * 256 + threadIdx.x;
    if (i >= 512 * 768) return;
    int n = i / 768, kp = i % 768;
    __nv_bfloat16 v = __float2bfloat16(0.0f);
    if (kp < 720) {
        int k = kp / 3, r = kp % 3;
        int tap = k / 80, c = k % 80;
        v = bsplit(w[n * 240 + c * 3 + tap], r);
    }
    wt[i] = v;
}
// conv2 weights: rows n (512), kpitch 4608
__global__ void wconv2_k(const float* __restrict__ w, __nv_bfloat16* __restrict__ wt) {
    int i = blockIdx.x * 256 + threadIdx.x;
    if (i >= 512 * 4608) return;
    int n = i / 4608, kp = i % 4608;
    int k = kp / 3, r = kp % 3;
    int tap = k / 512, c = k % 512;
    wt[i] = bsplit(w[n * 1536 + c * 3 + tap], r);
}

#define S0 (2048*1536)
#define S1 (64*3072)
#define S2 (1024*128)
#define S3 (512*3072)
__global__ void layer_wconv_k(const float* __restrict__ inw, const float* __restrict__ xw,
                              const float* __restrict__ dtw, const float* __restrict__ outw,
                              __nv_bfloat16* __restrict__ o_in, __nv_bfloat16* __restrict__ o_x,
                              __nv_bfloat16* __restrict__ o_dt, __nv_bfloat16* __restrict__ o_out) {
    int i = blockIdx.x * 256 + threadIdx.x;
    if (i < S0) {
        int n = i / 1536, kp = i % 1536;
        int k = kp / 3, r = kp % 3;
        o_in[i] = bsplit(inw[k * 2048 + n], r);
        return;
    }
    i -= S0;
    if (i < S1) {
        int n = i / 3072, kp = i % 3072;
        int k = kp / 3, r = kp % 3;
        o_x[i] = bsplit(xw[k * 64 + n], r);
        return;
    }
    i -= S1;
    if (i < S2) {
        int n = i / 128, kp = i % 128;
        __nv_bfloat16 v = __float2bfloat16(0.0f);
        if (kp < 96) {
            int k = kp / 3, r = kp % 3;
            v = bsplit(dtw[k * 1024 + n], r);
        }
        o_dt[i] = v;
        return;
    }
    i -= S2;
    if (i < S3) {
        int n = i / 3072, kp = i % 3072;
        int k = kp / 3, r = kp % 3;
        o_out[i] = bsplit(outw[k * 512 + n], r);
    }
}

__global__ void whead_k(const float* __restrict__ w, __nv_bfloat16* __restrict__ wt) {
    int i = blockIdx.x * 256 + threadIdx.x;
    if (i >= 1024 * 1536) return;
    int n = i / 1536, kp = i % 1536;
    int k = kp / 3, r = kp % 3;
    wt[i] = bsplit(w[k * 1024 + n], r);
}

__global__ void proj_t_k(const float* __restrict__ proj, __nv_bfloat16* __restrict__ pt) {
    int i = blockIdx.x * 256 + threadIdx.x;
    if (i >= M4 * 128) return;
    int m = i >> 7, kp = i & 127;
    __nv_bfloat16 v = __float2bfloat16(0.0f);
    if (kp < 96) {
        int k = kp / 3, r = kp % 3;
        float f = proj[m * 64 + k];
        __nv_bfloat16 h = __float2bfloat16(f);
        v = (r == 2) ? __float2bfloat16(f - __bfloat162float(h)) : h;   // A-side (hi,hi,md)
    }
    pt[i] = v;
}

__global__ void x_t_k(const float* __restrict__ x, __nv_bfloat16* __restrict__ xt) {
    int i = blockIdx.x * 256 + threadIdx.x;
    if (i >= M4 * Dm) return;
    atrip(x[i], xt + (long long)i * 3);
}

// ---------------- RMSNorm -> bf16 triple ----------------
__global__ void rmsnorm_t_k(const float* __restrict__ x, const float* __restrict__ w,
                            __nv_bfloat16* __restrict__ xnt) {
    int row = blockIdx.x;
    int tid = threadIdx.x;   // 128
    const float* xr = x + row * Dm;
    float v[4];
    float s = 0.0f;
#pragma unroll
    for (int i = 0; i < 4; i++) { v[i] = xr[tid + 128 * i]; s += v[i] * v[i]; }
#pragma unroll
    for (int o = 16; o; o >>= 1) s += __shfl_xor_sync(0xffffffffu, s, o);
    __shared__ float ws[4];
    if ((tid & 31) == 0) ws[tid >> 5] = s;
    __syncthreads();
    float tot = ws[0] + ws[1] + ws[2] + ws[3];
    float rs = rsqrtf(tot * (1.0f / Dm) + 1e-5f);
#pragma unroll
    for (int i = 0; i < 4; i++) {
        int c = tid + 128 * i;
        atrip(v[i] * rs * w[c], xnt + (long long)row * 1536 + c * 3);
    }
}

// ---------------- depthwise causal conv (K=4) + SiLU ----------------
__global__ void dwconv_k(const float* __restrict__ xz, const float* __restrict__ cw,
                         const float* __restrict__ cb, float* __restrict__ xi,
                         __nv_bfloat16* __restrict__ xit) {
    int idx = blockIdx.x * 256 + threadIdx.x;
    if (idx >= M4 * DIc) return;
    int d = idx & (DIc - 1);
    int m = idx >> 10;
    int t = m % T4;
    float w0 = cw[d * 4 + 0], w1 = cw[d * 4 + 1], w2 = cw[d * 4 + 2], w3 = cw[d * 4 + 3];
    const float* base = xz + (long long)m * 2048 + d;
    float acc = w3 * base[0];
    if (t >= 1) acc = fmaf(w2, base[-2048], acc);
    if (t >= 2) acc = fmaf(w1, base[-2 * 2048], acc);
    if (t >= 3) acc = fmaf(w0, base[-3 * 2048], acc);
    acc += cb[d];
    float s = acc / (1.0f + expf(-acc));
    xi[idx] = s;
    atrip(s, xit + (long long)m * 3072 + d * 3);
}

// ---------------- selective scan -> yc triple ----------------
__global__ void scan_k(const float* __restrict__ dt, const float* __restrict__ xi,
                       const float* __restrict__ proj, const float* __restrict__ xz,
                       const float* __restrict__ A_log, const float* __restrict__ dskip,
                       __nv_bfloat16* __restrict__ yct) {
    int w = (blockIdx.x * blockDim.x + threadIdx.x) >> 5;
    int lane = threadIdx.x & 31;
    int b = w >> 9;
    int dp = w & 511;
    int d = dp * 2 + (lane >> 4);
    int n = lane & 15;
    float Ac = -expf(A_log[d * Nst + n]);
    float dsk = dskip[d];
    float h = 0.0f;
    int mb = b * T4;
    for (int t = 0; t < T4; t++) {
        int m = mb + t;
        float dtv = dt[m * DIc + d];
        float xiv = xi[m * DIc + d];
        float Bv = proj[m * 64 + 32 + n];
        float Cv = proj[m * 64 + 48 + n];
        float dA = __expf(dtv * Ac);
        h = fmaf(dA, h, dtv * xiv * Bv);
        float p = h * Cv;
        p += __shfl_xor_sync(0xffffffffu, p, 8);
        p += __shfl_xor_sync(0xffffffffu, p, 4);
        p += __shfl_xor_sync(0xffffffffu, p, 2);
        p += __shfl_xor_sync(0xffffffffu, p, 1);
        if (n == 0) {
            float zv = xz[(long long)m * 2048 + DIc + d];
            float yv = p + dsk * xiv;
            atrip(yv * zv / (1.0f + __expf(-zv)), yct + (long long)m * 3072 + d * 3);
        }
    }
}

__global__ void lens_k(const int* __restrict__ fl, float* __restrict__ out, int out_size) {
    int b = threadIdx.x;
    if (b < Bsz && out_size >= M4 * Vv + Bsz) {
        int v = fl[b] >> 2;
        if (v < 1) v = 1;
        out[M4 * Vv + b] = (float)v;
    }
}

// ---------------- launcher ----------------
extern "C" void kernel_launch(void* const* d_in, const int* in_sizes, int n_in,
                              void* d_out, int out_size) {
    (void)in_sizes; (void)n_in;
    const float* feats    = (const float*)d_in[0];
    const int*   feat_lens= (const int*)  d_in[1];
    const float* conv1_w  = (const float*)d_in[2];
    const float* conv1_b  = (const float*)d_in[3];
    const float* conv2_w  = (const float*)d_in[4];
    const float* conv2_b  = (const float*)d_in[5];
    const float* norm_w   = (const float*)d_in[6];
    const float* in_proj  = (const float*)d_in[7];
    const float* dwc_w    = (const float*)d_in[8];
    const float* dwc_b    = (const float*)d_in[9];
    const float* x_proj   = (const float*)d_in[10];
    const float* dt_w     = (const float*)d_in[11];
    const float* dt_b     = (const float*)d_in[12];
    const float* A_log    = (const float*)d_in[13];
    const float* D_skip   = (const float*)d_in[14];
    const float* out_proj = (const float*)d_in[15];
    const float* head_w   = (const float*)d_in[16];
    const float* head_b   = (const float*)d_in[17];
    float* out = (float*)d_out;

    void* sym = nullptr;
    cudaGetSymbolAddress(&sym, g_buf);
    float* gb = (float*)sym;
    __nv_bfloat16* featsp_t = (__nv_bfloat16*)(gb + OFF_FEATSP_T);
    __nv_bfloat16* out1p_t  = (__nv_bfloat16*)(gb + OFF_OUT1P_T);
    __nv_bfloat16* xn_t     = (__nv_bfloat16*)(gb + OFF_XN_T);
    float*         xz       = gb + OFF_XZ;
    float*         xi       = gb + OFF_XI;
    __nv_bfloat16* xi_t     = (__nv_bfloat16*)(gb + OFF_XI_T);
    float*         dtbuf    = gb + OFF_DT;
    float*         proj     = gb + OFF_PROJ;
    __nv_bfloat16* proj_t   = (__nv_bfloat16*)(gb + OFF_PROJ_T);
    __nv_bfloat16* yc_t     = (__nv_bfloat16*)(gb + OFF_YC_T);
    float*         x        = gb + OFF_X;
    __nv_bfloat16* x_t      = (__nv_bfloat16*)(gb + OFF_X_T);
    __nv_bfloat16* w1t      = (__nv_bfloat16*)(gb + OFF_W1T);
    __nv_bfloat16* w2t      = (__nv_bfloat16*)(gb + OFF_W2T);
    __nv_bfloat16* inW      = (__nv_bfloat16*)(gb + OFF_INW);
    __nv_bfloat16* xW       = (__nv_bfloat16*)(gb + OFF_XW);
    __nv_bfloat16* dtW      = (__nv_bfloat16*)(gb + OFF_DTW);
    __nv_bfloat16* outW     = (__nv_bfloat16*)(gb + OFF_OUTW);
    __nv_bfloat16* headW    = (__nv_bfloat16*)(gb + OFF_HEADW);

    const int SM128 = 1024 + 3 * (16384 + 128 * 128);  // 99328
    const int SM64  = 1024 + 3 * (16384 + 64 * 128);   // 74752
    cudaFuncSetAttribute(bgemm_k<128>, cudaFuncAttributeMaxDynamicSharedMemorySize, SM128);
    cudaFuncSetAttribute(bgemm_k<64>,  cudaFuncAttributeMaxDynamicSharedMemorySize, SM64);

    // prep + weight conversion
    wconv1_k<<<(512 * 768 + 255) / 256, 256>>>(conv1_w, w1t);
    wconv2_k<<<(512 * 4608 + 255) / 256, 256>>>(conv2_w, w2t);
    prep_feats_t_k<<<(Bsz * Tfull * 80 + 255) / 256, 256>>>(feats, featsp_t);

    // conv1: M=6400, N=512, K'=768 -> out1p_t (triple, rows shifted by +1 pad row)
    bgemm_k<128><<<dim3(4, 50), 256, SM128>>>(
        featsp_t, w1t, conv1_b, out1p_t + 1536,
        12, 768,
        800, 1602LL * 240, 480,
        800, 802LL * 1536, 1536,
        1, 1, 0);

    zero_out1p_t_k<<<(Bsz * 2 * 1536 + 255) / 256, 256>>>(out1p_t);

    // conv2: M=3200, N=512, K'=4608 -> x f32
    bgemm_k<128><<<dim3(4, 25), 256, SM128>>>(
        out1p_t, w2t, conv2_b, x,
        72, 4608,
        400, 802LL * 1536, 3072,
        M4, 0, 512,
        1, 0, 0);

    for (int l = 0; l < Ll; l++)
        layer_wconv_k<<<(S0 + S1 + S2 + S3 + 255) / 256, 256>>>(
            in_proj + (size_t)l * Dm * 2048, x_proj + (size_t)l * DIc * 64,
            dt_w + (size_t)l * 32 * DIc, out_proj + (size_t)l * DIc * Dm,
            inW + (size_t)l * S0, xW + (size_t)l * S1,
            dtW + (size_t)l * S2, outW + (size_t)l * S3);
    whead_k<<<(1024 * 1536 + 255) / 256, 256>>>(head_w, headW);

    for (int l = 0; l < Ll; l++) {
        rmsnorm_t_k<<<M4, 128>>>(x, norm_w + l * Dm, xn_t);

        // xz = xn @ in_proj  (3200x2048, K'=1536)
        bgemm_k<128><<<dim3(16, 25), 256, SM128>>>(
            xn_t, inW + (size_t)l * S0, nullptr, xz,
            24, 1536,
            M4, 0, 1536,
            M4, 0, 2048,
            0, 0, 0);

        dwconv_k<<<(M4 * DIc + 255) / 256, 256>>>(
            xz, dwc_w + l * DIc * 4, dwc_b + l * DIc, xi, xi_t);

        // proj = xi @ x_proj  (3200x64, K'=3072)
        bgemm_k<64><<<dim3(1, 25), 256, SM64>>>(
            xi_t, xW + (size_t)l * S1, nullptr, proj,
            48, 3072,
            M4, 0, 3072,
            M4, 0, 64,
            0, 0, 0);

        proj_t_k<<<(M4 * 128 + 255) / 256, 256>>>(proj, proj_t);

        // dt = softplus(proj @ dt_w + dt_b)  (3200x1024, K'=128)
        bgemm_k<128><<<dim3(8, 25), 256, SM128>>>(
            proj_t, dtW + (size_t)l * S2, dt_b + l * DIc, dtbuf,
            2, 128,
            M4, 0, 128,
            M4, 0, 1024,
            2, 0, 0);

        scan_k<<<512, 256>>>(dtbuf, xi, proj, xz,
                             A_log + (size_t)l * DIc * Nst, D_skip + l * DIc, yc_t);

        // x += yc @ out_proj  (3200x512, K'=3072)
        bgemm_k<128><<<dim3(4, 25), 256, SM128>>>(
            yc_t, outW + (size_t)l * S3, nullptr, x,
            48, 3072,
            M4, 0, 3072,
            M4, 0, 512,
            0, 0, 1);
    }

    x_t_k<<<(M4 * Dm + 255) / 256, 256>>>(x, x_t);

    // logits = x @ head_w + head_b  (3200x1024, K'=1536)
    bgemm_k<128><<<dim3(8, 25), 256, SM128>>>(
        x_t, headW, head_b, out,
        24, 1536,
        M4, 0, 1536,
        M4, 0, 1024,
        0, 0, 0);

    lens_k<<<1, 32>>>(feat_lens, out, out_size);
}

// round 9
// speedup vs baseline: 1.0902x; 1.0441x over previous
#include <cuda_runtime.h>
#include <cuda_bf16.h>
#include <math.h>
#include <stdint.h>

// ---------------- problem constants ----------------
#define Bsz   8
#define Tfull 1600
#define Dm    512
#define DIc   1024
#define Nst   16
#define Ll    8
#define Vv    1024
#define T4    400
#define M4    (Bsz*T4)    // 3200
#define M2    (Bsz*800)   // 6400

// ---------------- scratch (single __device__ array, ~238MB) ----------------
__device__ float g_buf[59533184];

#define OFF_FEATSP_T 0
#define OFF_OUT1P_T  1537920
#define OFF_XN_T     6465408
#define OFF_XZ       8923008
#define OFF_XI       15476608
#define OFF_XI_T     18753408
#define OFF_DT       23668608
#define OFF_PROJ     26945408
#define OFF_PROJ_T   27150208
#define OFF_YC_T     27355008
#define OFF_X        32270208
#define OFF_X_T      33908608
#define OFF_W1T      36366208
#define OFF_W2T      36562816
#define OFF_INW      37742464
#define OFF_XW       50325376
#define OFF_DTW      51111808
#define OFF_OUTW     51636096
#define OFF_HEADW    57927552
#define OFF_XPART    58713984

// ---------------- math helpers ----------------
__device__ __forceinline__ float gelu_f(float x) {
    return 0.5f * x * (1.0f + erff(x * 0.70710678118654752f));
}
__device__ __forceinline__ float softplus_f(float x) {
    return fmaxf(x, 0.0f) + log1pf(expf(-fabsf(x)));
}
// A-side triple (hi, hi, md)
__device__ __forceinline__ void atrip(float v, __nv_bfloat16* p) {
    __nv_bfloat16 h = __float2bfloat16(v);
    p[0] = h; p[1] = h;
    p[2] = __float2bfloat16(v - __bfloat162float(h));
}
// B-side value for position r in (hi, md, hi)
__device__ __forceinline__ __nv_bfloat16 bsplit(float w, int r) {
    __nv_bfloat16 h = __float2bfloat16(w);
    if (r == 1) return __float2bfloat16(w - __bfloat162float(h));
    return h;
}

// ---------------- PTX helpers ----------------
__device__ __forceinline__ uint32_t smem_u32(const void* p) {
    uint32_t a;
    asm("{ .reg .u64 t; cvta.to.shared.u64 t, %1; cvt.u32.u64 %0, t; }" : "=r"(a) : "l"(p));
    return a;
}
#define SW128(x) ((x) ^ (((x) >> 3) & 0x70))
__device__ __forceinline__ void cp16(uint32_t dst, const void* src) {
    asm volatile("cp.async.cg.shared.global [%0], [%1], 16;" :: "r"(dst), "l"(src) : "memory");
}
__device__ __forceinline__ void ldsm4(uint32_t* r, uint32_t addr) {
    asm volatile("ldmatrix.sync.aligned.m8n8.x4.shared.b16 {%0,%1,%2,%3}, [%4];"
                 : "=r"(r[0]), "=r"(r[1]), "=r"(r[2]), "=r"(r[3]) : "r"(addr));
}
__device__ __forceinline__ void mma16(float* c, const uint32_t* a, const uint32_t* b) {
    asm volatile(
        "mma.sync.aligned.m16n8k16.row.col.f32.bf16.bf16.f32 "
        "{%0,%1,%2,%3},{%4,%5,%6,%7},{%8,%9},{%0,%1,%2,%3};"
        : "+f"(c[0]), "+f"(c[1]), "+f"(c[2]), "+f"(c[3])
        : "r"(a[0]), "r"(a[1]), "r"(a[2]), "r"(a[3]), "r"(b[0]), "r"(b[1]));
}

// ---------------- bf16 tensor-core GEMM (BM=64, 4-stage pipeline) ----------------
// D[m,n] = sum_k' A[arow(m)+k'] * Bw[n*bpitch+k']; chunk = 64 bf16 of k'.
// Optional split-K: blockIdx.z handles chunks [z*ksplit, min(NC,(z+1)*ksplit)),
// writing f32 output at C + z*zoff (no bias/act/accum in that mode).
template<int BN>
__global__ void __launch_bounds__(256, 2) bgemm_k(
        const __nv_bfloat16* __restrict__ A,
        const __nv_bfloat16* __restrict__ Bw,
        const float* __restrict__ bias,
        void* __restrict__ Cv,
        int NC, int bpitch,
        int a_rpb, long long a_bs, int a_rs,
        int o_rpb, long long o_bs, int o_rs,
        int act, int outmode, int accum,
        int ksplit, long long zoff) {
    extern __shared__ char smem_raw[];
    uint32_t sb = (smem_u32(smem_raw) + 1023) & ~1023u;
    constexpr uint32_t STG = 8192u + BN * 128u;   // A stage (64x128B) + B stage

    int tid = threadIdx.x, wid = tid >> 5, lane = tid & 31;
    int bm = blockIdx.y * 64, bn = blockIdx.x * BN;
    int c0 = blockIdx.z * ksplit;
    int c1 = min(NC, c0 + ksplit);

    // global->smem loader precompute (16B granules; tile row = 128B = 64 bf16)
    constexpr int AG = 2;            // 512 granules / 256 threads
    constexpr int BG = (BN * 8) / 256;
    const char* abase[AG]; uint32_t adst[AG];
#pragma unroll
    for (int i = 0; i < AG; i++) {
        int G = tid + i * 256;
        int row = G >> 3;
        int gm = bm + row;
        long long aoff = (long long)(gm / a_rpb) * a_bs + (long long)(gm % a_rpb) * a_rs;
        abase[i] = (const char*)(A + aoff + (G & 7) * 8);
        adst[i] = SW128((uint32_t)(row * 128 + (G & 7) * 16));
    }
    const char* bbase[BG]; uint32_t bdst[BG];
#pragma unroll
    for (int i = 0; i < BG; i++) {
        int G = tid + i * 256;
        int row = G >> 3;
        bbase[i] = (const char*)(Bw + (long long)(bn + row) * bpitch + (G & 7) * 8);
        bdst[i] = SW128((uint32_t)(row * 128 + (G & 7) * 16));
    }

    auto issue = [&](int c) {
        uint32_t Ax = sb + (uint32_t)(c & 3) * STG;
        uint32_t Bx = Ax + 8192u;
        long long kb = (long long)c * 128;   // 64 bf16 = 128 bytes
#pragma unroll
        for (int i = 0; i < AG; i++) cp16(Ax + adst[i], abase[i] + kb);
#pragma unroll
        for (int i = 0; i < BG; i++) cp16(Bx + bdst[i], bbase[i] + kb);
        asm volatile("cp.async.commit_group;" ::: "memory");
    };

    // warp tiling: 2 m-strips of 32 rows, 4 n-strips of BN/4 cols
    int wm = wid & 1, wn = wid >> 1;
    constexpr int NT = BN / 32;      // 4 (BN=128) or 2 (BN=64)
    float acc[2][NT][4];
#pragma unroll
    for (int i = 0; i < 2; i++)
#pragma unroll
        for (int j = 0; j < NT; j++)
#pragma unroll
            for (int r = 0; r < 4; r++) acc[i][j][r] = 0.0f;

    // ldmatrix per-thread address components
    int a_trow = (lane & 7) + ((lane >> 3) & 1) * 8;
    int a_tcol = (lane >> 4) * 16;
    int b_trow = ((lane >> 4) << 3) + (lane & 7);
    int b_tcol = ((lane >> 3) & 1) * 16;

    issue(c0);
    if (c0 + 1 < c1) issue(c0 + 1);
    if (c0 + 2 < c1) issue(c0 + 2);

    for (int c = c0; c < c1; c++) {
        int rem = c1 - 1 - c;
        if (rem >= 2)      asm volatile("cp.async.wait_group 2;" ::: "memory");
        else if (rem == 1) asm volatile("cp.async.wait_group 1;" ::: "memory");
        else               asm volatile("cp.async.wait_group 0;" ::: "memory");
        __syncthreads();
        if (c + 3 < c1) issue(c + 3);

        uint32_t Ax = sb + (uint32_t)(c & 3) * STG;
        uint32_t Bx = Ax + 8192u;
#pragma unroll
        for (int ks = 0; ks < 4; ks++) {
            uint32_t a[2][4];
#pragma unroll
            for (int i = 0; i < 2; i++) {
                int trow = wm * 32 + i * 16 + a_trow;
                ldsm4(a[i], Ax + SW128((uint32_t)(trow * 128 + ks * 32 + a_tcol)));
            }
            uint32_t b[NT][2];
#pragma unroll
            for (int jp = 0; jp < NT / 2; jp++) {
                int trow = wn * (BN / 4) + jp * 16 + b_trow;
                uint32_t r[4];
                ldsm4(r, Bx + SW128((uint32_t)(trow * 128 + ks * 32 + b_tcol)));
                b[2 * jp][0] = r[0]; b[2 * jp][1] = r[1];
                b[2 * jp + 1][0] = r[2]; b[2 * jp + 1][1] = r[3];
            }
#pragma unroll
            for (int i = 0; i < 2; i++)
#pragma unroll
                for (int j = 0; j < NT; j++) mma16(acc[i][j], a[i], b[j]);
        }
    }

    // ---------------- epilogue (direct from registers) ----------------
    float* Cz = (float*)Cv + blockIdx.z * zoff;
#pragma unroll
    for (int i = 0; i < 2; i++) {
#pragma unroll
        for (int h = 0; h < 2; h++) {   // row halves (+0 / +8)
            int gm = bm + wm * 32 + i * 16 + (lane >> 2) + h * 8;
            long long orow = (long long)(gm / o_rpb) * o_bs + (long long)(gm % o_rpb) * o_rs;
#pragma unroll
            for (int j = 0; j < NT; j++) {
                int gn = bn + wn * (BN / 4) + j * 8 + (lane & 3) * 2;
#pragma unroll
                for (int e = 0; e < 2; e++) {
                    float v = acc[i][j][h * 2 + e];
                    int gne = gn + e;
                    if (bias) v += bias[gne];
                    if (act == 1) v = gelu_f(v);
                    else if (act == 2) v = softplus_f(v);
                    if (outmode == 0) {
                        long long o = orow + gne;
                        if (accum) v += Cz[o];
                        Cz[o] = v;
                    } else {
                        __nv_bfloat16* C = (__nv_bfloat16*)Cv;
                        long long o = orow + (long long)gne * 3;
                        __nv_bfloat16 hh = __float2bfloat16(v);
                        C[o] = hh; C[o + 1] = hh;
                        C[o + 2] = __float2bfloat16(v - __bfloat162float(hh));
                    }
                }
            }
        }
    }
}

// ---------------- converters / prep ----------------
__global__ void prep_feats_t_k(const float* __restrict__ feats, __nv_bfloat16* __restrict__ fp) {
    int i = blockIdx.x * 256 + threadIdx.x;
    if (i < Bsz * Tfull * 80) {
        int c = i % 80;
        int t = (i / 80) % Tfull;
        int b = i / (80 * Tfull);
        atrip(feats[i], fp + ((long long)(b * 1602 + t + 1) * 240 + c * 3));
    }
    if (i < Bsz * 2 * 240) {
        int e = i % 240; int r = i / 240;
        int b = r >> 1; int t = (r & 1) ? 1601 : 0;
        fp[(long long)(b * 1602 + t) * 240 + e] = __float2bfloat16(0.0f);
    }
}

__global__ void zero_out1p_t_k(__nv_bfloat16* __restrict__ op) {
    int i = blockIdx.x * 256 + threadIdx.x;
    if (i < Bsz * 2 * 1536) {
        int e = i % 1536; int r = i / 1536;
        int b = r >> 1; int t = (r & 1) ? 801 : 0;
        op[(long long)(b * 802 + t) * 1536 + e] = __float2bfloat16(0.0f);
    }
}

// conv1 weights: rows n (512), kpitch 768 (kp>=720 zero)
__global__ void wconv1_k(const float* __restrict__ w, __nv_bfloat16* __restrict__ wt) {
    int i = blockIdx.x * 256 + threadIdx.x;
    if (i >= 512 * 768) return;
    int n = i / 768, kp = i % 768;
    __nv_bfloat16 v = __float2bfloat16(0.0f);
    if (kp < 720) {
        int k = kp / 3, r = kp % 3;
        int tap = k / 80, c = k % 80;
        v = bsplit(w[n * 240 + c * 3 + tap], r);
    }
    wt[i] = v;
}
// conv2 weights: rows n (512), kpitch 4608
__global__ void wconv2_k(const float* __restrict__ w, __nv_bfloat16* __restrict__ wt) {
    int i = blockIdx.x * 256 + threadIdx.x;
    if (i >= 512 * 4608) return;
    int n = i / 4608, kp = i % 4608;
    int k = kp / 3, r = kp % 3;
    int tap = k / 512, c = k % 512;
    wt[i] = bsplit(w[n * 1536 + c * 3 + tap], r);
}

#define S0 (2048*1536)
#define S1 (64*3072)
#define S2 (1024*128)
#define S3 (512*3072)
__global__ void layer_wconv_k(const float* __restrict__ inw, const float* __restrict__ xw,
                              const float* __restrict__ dtw, const float* __restrict__ outw,
                              __nv_bfloat16* __restrict__ o_in, __nv_bfloat16* __restrict__ o_x,
                              __nv_bfloat16* __restrict__ o_dt, __nv_bfloat16* __restrict__ o_out) {
    int i = blockIdx.x * 256 + threadIdx.x;
    if (i < S0) {
        int n = i / 1536, kp = i % 1536;
        int k = kp / 3, r = kp % 3;
        o_in[i] = bsplit(inw[k * 2048 + n], r);
        return;
    }
    i -= S0;
    if (i < S1) {
        int n = i / 3072, kp = i % 3072;
        int k = kp / 3, r = kp % 3;
        o_x[i] = bsplit(xw[k * 64 + n], r);
        return;
    }
    i -= S1;
    if (i < S2) {
        int n = i / 128, kp = i % 128;
        __nv_bfloat16 v = __float2bfloat16(0.0f);
        if (kp < 96) {
            int k = kp / 3, r = kp % 3;
            v = bsplit(dtw[k * 1024 + n], r);
        }
        o_dt[i] = v;
        return;
    }
    i -= S2;
    if (i < S3) {
        int n = i / 3072, kp = i % 3072;
        int k = kp / 3, r = kp % 3;
        o_out[i] = bsplit(outw[k * 512 + n], r);
    }
}

__global__ void whead_k(const float* __restrict__ w, __nv_bfloat16* __restrict__ wt) {
    int i = blockIdx.x * 256 + threadIdx.x;
    if (i >= 1024 * 1536) return;
    int n = i / 1536, kp = i % 1536;
    int k = kp / 3, r = kp % 3;
    wt[i] = bsplit(w[k * 1024 + n], r);
}

// combine split-K partials -> proj f32 (ALL 64 cols) + proj_t (A-side triple of cols 0..31)
__global__ void xcomb_k(const float* __restrict__ parts, float* __restrict__ proj,
                        __nv_bfloat16* __restrict__ pt) {
    int i = blockIdx.x * 256 + threadIdx.x;
    if (i >= M4 * 128) return;
    int m = i >> 7, kp = i & 127;
    // full f32 proj (cols 0..63), one writer per column: threads kp<64
    if (kp < 64) {
        int o = m * 64 + kp;
        proj[o] = parts[o] + parts[204800 + o] + parts[2 * 204800 + o] + parts[3 * 204800 + o];
    }
    // triple for dt GEMM input (cols 0..31 -> 96 triples, padded to 128)
    if (kp < 96) {
        int k = kp / 3, r = kp % 3;
        int o = m * 64 + k;
        float s = parts[o] + parts[204800 + o] + parts[2 * 204800 + o] + parts[3 * 204800 + o];
        __nv_bfloat16 h = __float2bfloat16(s);
        pt[i] = (r == 2) ? __float2bfloat16(s - __bfloat162float(h)) : h;
    } else {
        pt[i] = __float2bfloat16(0.0f);
    }
}

__global__ void x_t_k(const float* __restrict__ x, __nv_bfloat16* __restrict__ xt) {
    int i = blockIdx.x * 256 + threadIdx.x;
    if (i >= M4 * Dm) return;
    atrip(x[i], xt + (long long)i * 3);
}

// ---------------- RMSNorm -> bf16 triple ----------------
__global__ void rmsnorm_t_k(const float* __restrict__ x, const float* __restrict__ w,
                            __nv_bfloat16* __restrict__ xnt) {
    int row = blockIdx.x;
    int tid = threadIdx.x;   // 128
    const float* xr = x + row * Dm;
    float v[4];
    float s = 0.0f;
#pragma unroll
    for (int i = 0; i < 4; i++) { v[i] = xr[tid + 128 * i]; s += v[i] * v[i]; }
#pragma unroll
    for (int o = 16; o; o >>= 1) s += __shfl_xor_sync(0xffffffffu, s, o);
    __shared__ float ws[4];
    if ((tid & 31) == 0) ws[tid >> 5] = s;
    __syncthreads();
    float tot = ws[0] + ws[1] + ws[2] + ws[3];
    float rs = rsqrtf(tot * (1.0f / Dm) + 1e-5f);
#pragma unroll
    for (int i = 0; i < 4; i++) {
        int c = tid + 128 * i;
        atrip(v[i] * rs * w[c], xnt + (long long)row * 1536 + c * 3);
    }
}

// ---------------- depthwise causal conv (K=4) + SiLU ----------------
__global__ void dwconv_k(const float* __restrict__ xz, const float* __restrict__ cw,
                         const float* __restrict__ cb, float* __restrict__ xi,
                         __nv_bfloat16* __restrict__ xit) {
    int idx = blockIdx.x * 256 + threadIdx.x;
    if (idx >= M4 * DIc) return;
    int d = idx & (DIc - 1);
    int m = idx >> 10;
    int t = m % T4;
    float w0 = cw[d * 4 + 0], w1 = cw[d * 4 + 1], w2 = cw[d * 4 + 2], w3 = cw[d * 4 + 3];
    const float* base = xz + (long long)m * 2048 + d;
    float acc = w3 * base[0];
    if (t >= 1) acc = fmaf(w2, base[-2048], acc);
    if (t >= 2) acc = fmaf(w1, base[-2 * 2048], acc);
    if (t >= 3) acc = fmaf(w0, base[-3 * 2048], acc);
    acc += cb[d];
    float s = acc / (1.0f + expf(-acc));
    xi[idx] = s;
    atrip(s, xit + (long long)m * 3072 + d * 3);
}

// ---------------- selective scan -> yc triple ----------------
__global__ void scan_k(const float* __restrict__ dt, const float* __restrict__ xi,
                       const float* __restrict__ proj, const float* __restrict__ xz,
                       const float* __restrict__ A_log, const float* __restrict__ dskip,
                       __nv_bfloat16* __restrict__ yct) {
    int w = (blockIdx.x * blockDim.x + threadIdx.x) >> 5;
    int lane = threadIdx.x & 31;
    int b = w >> 9;
    int dp = w & 511;
    int d = dp * 2 + (lane >> 4);
    int n = lane & 15;
    float Ac = -expf(A_log[d * Nst + n]);
    float dsk = dskip[d];
    float h = 0.0f;
    int mb = b * T4;
    for (int t = 0; t < T4; t++) {
        int m = mb + t;
        float dtv = dt[m * DIc + d];
        float xiv = xi[m * DIc + d];
        float Bv = proj[m * 64 + 32 + n];
        float Cv = proj[m * 64 + 48 + n];
        float dA = __expf(dtv * Ac);
        h = fmaf(dA, h, dtv * xiv * Bv);
        float p = h * Cv;
        p += __shfl_xor_sync(0xffffffffu, p, 8);
        p += __shfl_xor_sync(0xffffffffu, p, 4);
        p += __shfl_xor_sync(0xffffffffu, p, 2);
        p += __shfl_xor_sync(0xffffffffu, p, 1);
        if (n == 0) {
            float zv = xz[(long long)m * 2048 + DIc + d];
            float yv = p + dsk * xiv;
            atrip(yv * zv / (1.0f + __expf(-zv)), yct + (long long)m * 3072 + d * 3);
        }
    }
}

__global__ void lens_k(const int* __restrict__ fl, float* __restrict__ out, int out_size) {
    int b = threadIdx.x;
    if (b < Bsz && out_size >= M4 * Vv + Bsz) {
        int v = fl[b] >> 2;
        if (v < 1) v = 1;
        out[M4 * Vv + b] = (float)v;
    }
}

// ---------------- launcher ----------------
extern "C" void kernel_launch(void* const* d_in, const int* in_sizes, int n_in,
                              void* d_out, int out_size) {
    (void)in_sizes; (void)n_in;
    const float* feats    = (const float*)d_in[0];
    const int*   feat_lens= (const int*)  d_in[1];
    const float* conv1_w  = (const float*)d_in[2];
    const float* conv1_b  = (const float*)d_in[3];
    const float* conv2_w  = (const float*)d_in[4];
    const float* conv2_b  = (const float*)d_in[5];
    const float* norm_w   = (const float*)d_in[6];
    const float* in_proj  = (const float*)d_in[7];
    const float* dwc_w    = (const float*)d_in[8];
    const float* dwc_b    = (const float*)d_in[9];
    const float* x_proj   = (const float*)d_in[10];
    const float* dt_w     = (const float*)d_in[11];
    const float* dt_b     = (const float*)d_in[12];
    const float* A_log    = (const float*)d_in[13];
    const float* D_skip   = (const float*)d_in[14];
    const float* out_proj = (const float*)d_in[15];
    const float* head_w   = (const float*)d_in[16];
    const float* head_b   = (const float*)d_in[17];
    float* out = (float*)d_out;

    void* sym = nullptr;
    cudaGetSymbolAddress(&sym, g_buf);
    float* gb = (float*)sym;
    __nv_bfloat16* featsp_t = (__nv_bfloat16*)(gb + OFF_FEATSP_T);
    __nv_bfloat16* out1p_t  = (__nv_bfloat16*)(gb + OFF_OUT1P_T);
    __nv_bfloat16* xn_t     = (__nv_bfloat16*)(gb + OFF_XN_T);
    float*         xz       = gb + OFF_XZ;
    float*         xi       = gb + OFF_XI;
    __nv_bfloat16* xi_t     = (__nv_bfloat16*)(gb + OFF_XI_T);
    float*         dtbuf    = gb + OFF_DT;
    float*         proj     = gb + OFF_PROJ;
    __nv_bfloat16* proj_t   = (__nv_bfloat16*)(gb + OFF_PROJ_T);
    __nv_bfloat16* yc_t     = (__nv_bfloat16*)(gb + OFF_YC_T);
    float*         x        = gb + OFF_X;
    __nv_bfloat16* x_t      = (__nv_bfloat16*)(gb + OFF_X_T);
    __nv_bfloat16* w1t      = (__nv_bfloat16*)(gb + OFF_W1T);
    __nv_bfloat16* w2t      = (__nv_bfloat16*)(gb + OFF_W2T);
    __nv_bfloat16* inW      = (__nv_bfloat16*)(gb + OFF_INW);
    __nv_bfloat16* xW       = (__nv_bfloat16*)(gb + OFF_XW);
    __nv_bfloat16* dtW      = (__nv_bfloat16*)(gb + OFF_DTW);
    __nv_bfloat16* outW     = (__nv_bfloat16*)(gb + OFF_OUTW);
    __nv_bfloat16* headW    = (__nv_bfloat16*)(gb + OFF_HEADW);
    float*         xpart    = gb + OFF_XPART;

    const int SM128 = 1024 + 4 * (8192 + 128 * 128);  // 99328
    const int SM64  = 1024 + 4 * (8192 + 64 * 128);   // 66560
    cudaFuncSetAttribute(bgemm_k<128>, cudaFuncAttributeMaxDynamicSharedMemorySize, SM128);
    cudaFuncSetAttribute(bgemm_k<64>,  cudaFuncAttributeMaxDynamicSharedMemorySize, SM64);

    // prep + weight conversion
    wconv1_k<<<(512 * 768 + 255) / 256, 256>>>(conv1_w, w1t);
    wconv2_k<<<(512 * 4608 + 255) / 256, 256>>>(conv2_w, w2t);
    prep_feats_t_k<<<(Bsz * Tfull * 80 + 255) / 256, 256>>>(feats, featsp_t);

    // conv1: M=6400, N=512, K'=768 -> out1p_t (triple, rows shifted by +1 pad row)
    bgemm_k<128><<<dim3(4, 100), 256, SM128>>>(
        featsp_t, w1t, conv1_b, out1p_t + 1536,
        12, 768,
        800, 1602LL * 240, 480,
        800, 802LL * 1536, 1536,
        1, 1, 0, 1 << 30, 0);

    zero_out1p_t_k<<<(Bsz * 2 * 1536 + 255) / 256, 256>>>(out1p_t);

    // conv2: M=3200, N=512, K'=4608 -> x f32
    bgemm_k<64><<<dim3(8, 50), 256, SM64>>>(
        out1p_t, w2t, conv2_b, x,
        72, 4608,
        400, 802LL * 1536, 3072,
        M4, 0, 512,
        1, 0, 0, 1 << 30, 0);

    for (int l = 0; l < Ll; l++)
        layer_wconv_k<<<(S0 + S1 + S2 + S3 + 255) / 256, 256>>>(
            in_proj + (size_t)l * Dm * 2048, x_proj + (size_t)l * DIc * 64,
            dt_w + (size_t)l * 32 * DIc, out_proj + (size_t)l * DIc * Dm,
            inW + (size_t)l * S0, xW + (size_t)l * S1,
            dtW + (size_t)l * S2, outW + (size_t)l * S3);
    whead_k<<<(1024 * 1536 + 255) / 256, 256>>>(head_w, headW);

    for (int l = 0; l < Ll; l++) {
        rmsnorm_t_k<<<M4, 128>>>(x, norm_w + l * Dm, xn_t);

        // xz = xn @ in_proj  (3200x2048, K'=1536)
        bgemm_k<128><<<dim3(16, 50), 256, SM128>>>(
            xn_t, inW + (size_t)l * S0, nullptr, xz,
            24, 1536,
            M4, 0, 1536,
            M4, 0, 2048,
            0, 0, 0, 1 << 30, 0);

        dwconv_k<<<(M4 * DIc + 255) / 256, 256>>>(
            xz, dwc_w + l * DIc * 4, dwc_b + l * DIc, xi, xi_t);

        // proj partials = xi @ x_proj  (3200x64, K'=3072, split-K x4)
        bgemm_k<64><<<dim3(1, 50, 4), 256, SM64>>>(
            xi_t, xW + (size_t)l * S1, nullptr, xpart,
            48, 3072,
            M4, 0, 3072,
            M4, 0, 64,
            0, 0, 0, 12, 204800);

        xcomb_k<<<(M4 * 128 + 255) / 256, 256>>>(xpart, proj, proj_t);

        // dt = softplus(proj @ dt_w + dt_b)  (3200x1024, K'=128)
        bgemm_k<128><<<dim3(8, 50), 256, SM128>>>(
            proj_t, dtW + (size_t)l * S2, dt_b + l * DIc, dtbuf,
            2, 128,
            M4, 0, 128,
            M4, 0, 1024,
            2, 0, 0, 1 << 30, 0);

        scan_k<<<512, 256>>>(dtbuf, xi, proj, xz,
                             A_log + (size_t)l * DIc * Nst, D_skip + l * DIc, yc_t);

        // x += yc @ out_proj  (3200x512, K'=3072)
        bgemm_k<64><<<dim3(8, 50), 256, SM64>>>(
            yc_t, outW + (size_t)l * S3, nullptr, x,
            48, 3072,
            M4, 0, 3072,
            M4, 0, 512,
            0, 0, 1, 1 << 30, 0);
    }

    x_t_k<<<(M4 * Dm + 255) / 256, 256>>>(x, x_t);

    // logits = x @ head_w + head_b  (3200x1024, K'=1536)
    bgemm_k<128><<<dim3(8, 50), 256, SM128>>>(
        x_t, headW, head_b, out,
        24, 1536,
        M4, 0, 1536,
        M4, 0, 1024,
        0, 0, 0, 1 << 30, 0);

    lens_k<<<1, 32>>>(feat_lens, out, out_size);
}

// round 11
// speedup vs baseline: 1.0988x; 1.0079x over previous
#include <cuda_runtime.h>
#include <cuda_bf16.h>
#include <math.h>
#include <stdint.h>

// ---------------- problem constants ----------------
#define Bsz   8
#define Tfull 1600
#define Dm    512
#define DIc   1024
#define Nst   16
#define Ll    8
#define Vv    1024
#define T4    400
#define M4    (Bsz*T4)    // 3200
#define M2    (Bsz*800)   // 6400

// ---------------- scratch (single __device__ array, ~238MB) ----------------
__device__ float g_buf[59533184];

#define OFF_FEATSP_T 0
#define OFF_OUT1P_T  1537920
#define OFF_XN_T     6465408
#define OFF_XZ       8923008
#define OFF_XI       15476608
#define OFF_XI_T     18753408
#define OFF_DT       23668608
#define OFF_PROJ     26945408
#define OFF_PROJ_T   27150208
#define OFF_YC_T     27355008
#define OFF_X        32270208
#define OFF_X_T      33908608
#define OFF_W1T      36366208
#define OFF_W2T      36562816
#define OFF_INW      37742464
#define OFF_XW       50325376
#define OFF_DTW      51111808
#define OFF_OUTW     51636096
#define OFF_HEADW    57927552
#define OFF_XPART    58713984

// ---------------- math helpers ----------------
__device__ __forceinline__ float gelu_f(float x) {
    return 0.5f * x * (1.0f + erff(x * 0.70710678118654752f));
}
__device__ __forceinline__ float softplus_f(float x) {
    return fmaxf(x, 0.0f) + log1pf(expf(-fabsf(x)));
}
// A-side triple (hi, hi, md)
__device__ __forceinline__ void atrip(float v, __nv_bfloat16* p) {
    __nv_bfloat16 h = __float2bfloat16(v);
    p[0] = h; p[1] = h;
    p[2] = __float2bfloat16(v - __bfloat162float(h));
}
// B-side value for position r in (hi, md, hi)
__device__ __forceinline__ __nv_bfloat16 bsplit(float w, int r) {
    __nv_bfloat16 h = __float2bfloat16(w);
    if (r == 1) return __float2bfloat16(w - __bfloat162float(h));
    return h;
}

// ---------------- PTX helpers ----------------
__device__ __forceinline__ uint32_t smem_u32(const void* p) {
    uint32_t a;
    asm("{ .reg .u64 t; cvta.to.shared.u64 t, %1; cvt.u32.u64 %0, t; }" : "=r"(a) : "l"(p));
    return a;
}
#define SW128(x) ((x) ^ (((x) >> 3) & 0x70))
__device__ __forceinline__ void cp16(uint32_t dst, const void* src) {
    asm volatile("cp.async.cg.shared.global [%0], [%1], 16;" :: "r"(dst), "l"(src) : "memory");
}
__device__ __forceinline__ void ldsm4(uint32_t* r, uint32_t addr) {
    asm volatile("ldmatrix.sync.aligned.m8n8.x4.shared.b16 {%0,%1,%2,%3}, [%4];"
                 : "=r"(r[0]), "=r"(r[1]), "=r"(r[2]), "=r"(r[3]) : "r"(addr));
}
__device__ __forceinline__ void mma16(float* c, const uint32_t* a, const uint32_t* b) {
    asm volatile(
        "mma.sync.aligned.m16n8k16.row.col.f32.bf16.bf16.f32 "
        "{%0,%1,%2,%3},{%4,%5,%6,%7},{%8,%9},{%0,%1,%2,%3};"
        : "+f"(c[0]), "+f"(c[1]), "+f"(c[2]), "+f"(c[3])
        : "r"(a[0]), "r"(a[1]), "r"(a[2]), "r"(a[3]), "r"(b[0]), "r"(b[1]));
}

// ---------------- bf16 tensor-core GEMM (BM=64, BN=64, 4-stage, 3 CTAs/SM) ------
// D[m,n] = sum_k' A[arow(m)+k'] * Bw[n*bpitch+k']; chunk = 64 bf16 of k'.
// Split-K: blockIdx.z handles chunks [z*ksplit, min(NC,(z+1)*ksplit)),
// f32 out at C + z*zoff (no bias/act/accum in that mode).
template<int BN>
__global__ void __launch_bounds__(256, 3) bgemm_k(
        const __nv_bfloat16* __restrict__ A,
        const __nv_bfloat16* __restrict__ Bw,
        const float* __restrict__ bias,
        void* __restrict__ Cv,
        int NC, int bpitch,
        int a_rpb, long long a_bs, int a_rs,
        int o_rpb, long long o_bs, int o_rs,
        int act, int outmode, int accum,
        int ksplit, long long zoff) {
    extern __shared__ char smem_raw[];
    uint32_t sb = (smem_u32(smem_raw) + 1023) & ~1023u;
    constexpr uint32_t STG = 8192u + BN * 128u;   // A stage (64x128B) + B stage

    int tid = threadIdx.x, wid = tid >> 5, lane = tid & 31;
    int bm = blockIdx.y * 64, bn = blockIdx.x * BN;
    int c0 = blockIdx.z * ksplit;
    int c1 = min(NC, c0 + ksplit);

    // global->smem loader precompute (16B granules; tile row = 128B = 64 bf16)
    constexpr int AG = 2;            // 512 granules / 256 threads
    constexpr int BG = (BN * 8) / 256;
    const char* abase[AG]; uint32_t adst[AG];
#pragma unroll
    for (int i = 0; i < AG; i++) {
        int G = tid + i * 256;
        int row = G >> 3;
        int gm = bm + row;
        long long aoff = (long long)(gm / a_rpb) * a_bs + (long long)(gm % a_rpb) * a_rs;
        abase[i] = (const char*)(A + aoff + (G & 7) * 8);
        adst[i] = SW128((uint32_t)(row * 128 + (G & 7) * 16));
    }
    const char* bbase[BG]; uint32_t bdst[BG];
#pragma unroll
    for (int i = 0; i < BG; i++) {
        int G = tid + i * 256;
        int row = G >> 3;
        bbase[i] = (const char*)(Bw + (long long)(bn + row) * bpitch + (G & 7) * 8);
        bdst[i] = SW128((uint32_t)(row * 128 + (G & 7) * 16));
    }

    auto issue = [&](int c) {
        uint32_t Ax = sb + (uint32_t)(c & 3) * STG;
        uint32_t Bx = Ax + 8192u;
        long long kb = (long long)c * 128;   // 64 bf16 = 128 bytes
#pragma unroll
        for (int i = 0; i < AG; i++) cp16(Ax + adst[i], abase[i] + kb);
#pragma unroll
        for (int i = 0; i < BG; i++) cp16(Bx + bdst[i], bbase[i] + kb);
        asm volatile("cp.async.commit_group;" ::: "memory");
    };

    // warp tiling: 2 m-strips of 32 rows, 4 n-strips of BN/4 cols
    int wm = wid & 1, wn = wid >> 1;
    constexpr int NT = BN / 32;      // 2 (BN=64)
    float acc[2][NT][4];
#pragma unroll
    for (int i = 0; i < 2; i++)
#pragma unroll
        for (int j = 0; j < NT; j++)
#pragma unroll
            for (int r = 0; r < 4; r++) acc[i][j][r] = 0.0f;

    // ldmatrix per-thread address components
    int a_trow = (lane & 7) + ((lane >> 3) & 1) * 8;
    int a_tcol = (lane >> 4) * 16;
    int b_trow = ((lane >> 4) << 3) + (lane & 7);
    int b_tcol = ((lane >> 3) & 1) * 16;

    issue(c0);
    if (c0 + 1 < c1) issue(c0 + 1);
    if (c0 + 2 < c1) issue(c0 + 2);

    for (int c = c0; c < c1; c++) {
        int rem = c1 - 1 - c;
        if (rem >= 2)      asm volatile("cp.async.wait_group 2;" ::: "memory");
        else if (rem == 1) asm volatile("cp.async.wait_group 1;" ::: "memory");
        else               asm volatile("cp.async.wait_group 0;" ::: "memory");
        __syncthreads();
        if (c + 3 < c1) issue(c + 3);

        uint32_t Ax = sb + (uint32_t)(c & 3) * STG;
        uint32_t Bx = Ax + 8192u;
#pragma unroll
        for (int ks = 0; ks < 4; ks++) {
            uint32_t a[2][4];
#pragma unroll
            for (int i = 0; i < 2; i++) {
                int trow = wm * 32 + i * 16 + a_trow;
                ldsm4(a[i], Ax + SW128((uint32_t)(trow * 128 + ks * 32 + a_tcol)));
            }
            uint32_t b[NT][2];
#pragma unroll
            for (int jp = 0; jp < NT / 2; jp++) {
                int trow = wn * (BN / 4) + jp * 16 + b_trow;
                uint32_t r[4];
                ldsm4(r, Bx + SW128((uint32_t)(trow * 128 + ks * 32 + b_tcol)));
                b[2 * jp][0] = r[0]; b[2 * jp][1] = r[1];
                b[2 * jp + 1][0] = r[2]; b[2 * jp + 1][1] = r[3];
            }
#pragma unroll
            for (int i = 0; i < 2; i++)
#pragma unroll
                for (int j = 0; j < NT; j++) mma16(acc[i][j], a[i], b[j]);
        }
    }

    // ---------------- epilogue (direct from registers) ----------------
    float* Cz = (float*)Cv + blockIdx.z * zoff;
#pragma unroll
    for (int i = 0; i < 2; i++) {
#pragma unroll
        for (int h = 0; h < 2; h++) {   // row halves (+0 / +8)
            int gm = bm + wm * 32 + i * 16 + (lane >> 2) + h * 8;
            long long orow = (long long)(gm / o_rpb) * o_bs + (long long)(gm % o_rpb) * o_rs;
#pragma unroll
            for (int j = 0; j < NT; j++) {
                int gn = bn + wn * (BN / 4) + j * 8 + (lane & 3) * 2;
#pragma unroll
                for (int e = 0; e < 2; e++) {
                    float v = acc[i][j][h * 2 + e];
                    int gne = gn + e;
                    if (bias) v += bias[gne];
                    if (act == 1) v = gelu_f(v);
                    else if (act == 2) v = softplus_f(v);
                    if (outmode == 0) {
                        long long o = orow + gne;
                        if (accum) v += Cz[o];
                        Cz[o] = v;
                    } else {
                        __nv_bfloat16* C = (__nv_bfloat16*)Cv;
                        long long o = orow + (long long)gne * 3;
                        __nv_bfloat16 hh = __float2bfloat16(v);
                        C[o] = hh; C[o + 1] = hh;
                        C[o + 2] = __float2bfloat16(v - __bfloat162float(hh));
                    }
                }
            }
        }
    }
}

// ---------------- converters / prep ----------------
__global__ void prep_feats_t_k(const float* __restrict__ feats, __nv_bfloat16* __restrict__ fp) {
    int i = blockIdx.x * 256 + threadIdx.x;
    if (i < Bsz * Tfull * 80) {
        int c = i % 80;
        int t = (i / 80) % Tfull;
        int b = i / (80 * Tfull);
        atrip(feats[i], fp + ((long long)(b * 1602 + t + 1) * 240 + c * 3));
    }
    if (i < Bsz * 2 * 240) {
        int e = i % 240; int r = i / 240;
        int b = r >> 1; int t = (r & 1) ? 1601 : 0;
        fp[(long long)(b * 1602 + t) * 240 + e] = __float2bfloat16(0.0f);
    }
}

__global__ void zero_out1p_t_k(__nv_bfloat16* __restrict__ op) {
    int i = blockIdx.x * 256 + threadIdx.x;
    if (i < Bsz * 2 * 1536) {
        int e = i % 1536; int r = i / 1536;
        int b = r >> 1; int t = (r & 1) ? 801 : 0;
        op[(long long)(b * 802 + t) * 1536 + e] = __float2bfloat16(0.0f);
    }
}

// conv1 weights: rows n (512), kpitch 768 (kp>=720 zero)
__global__ void wconv1_k(const float* __restrict__ w, __nv_bfloat16* __restrict__ wt) {
    int i = blockIdx.x * 256 + threadIdx.x;
    if (i >= 512 * 768) return;
    int n = i / 768, kp = i % 768;
    __nv_bfloat16 v = __float2bfloat16(0.0f);
    if (kp < 720) {
        int k = kp / 3, r = kp % 3;
        int tap = k / 80, c = k % 80;
        v = bsplit(w[n * 240 + c * 3 + tap], r);
    }
    wt[i] = v;
}
// conv2 weights: rows n (512), kpitch 4608
__global__ void wconv2_k(const float* __restrict__ w, __nv_bfloat16* __restrict__ wt) {
    int i = blockIdx.x * 256 + threadIdx.x;
    if (i >= 512 * 4608) return;
    int n = i / 4608, kp = i % 4608;
    int k = kp / 3, r = kp % 3;
    int tap = k / 512, c = k % 512;
    wt[i] = bsplit(w[n * 1536 + c * 3 + tap], r);
}

#define S0 (2048*1536)
#define S1 (64*3072)
#define S2 (1024*128)
#define S3 (512*3072)
__global__ void layer_wconv_k(const float* __restrict__ inw, const float* __restrict__ xw,
                              const float* __restrict__ dtw, const float* __restrict__ outw,
                              __nv_bfloat16* __restrict__ o_in, __nv_bfloat16* __restrict__ o_x,
                              __nv_bfloat16* __restrict__ o_dt, __nv_bfloat16* __restrict__ o_out) {
    int i = blockIdx.x * 256 + threadIdx.x;
    if (i < S0) {
        int n = i / 1536, kp = i % 1536;
        int k = kp / 3, r = kp % 3;
        o_in[i] = bsplit(inw[k * 2048 + n], r);
        return;
    }
    i -= S0;
    if (i < S1) {
        int n = i / 3072, kp = i % 3072;
        int k = kp / 3, r = kp % 3;
        o_x[i] = bsplit(xw[k * 64 + n], r);
        return;
    }
    i -= S1;
    if (i < S2) {
        int n = i / 128, kp = i % 128;
        __nv_bfloat16 v = __float2bfloat16(0.0f);
        if (kp < 96) {
            int k = kp / 3, r = kp % 3;
            v = bsplit(dtw[k * 1024 + n], r);
        }
        o_dt[i] = v;
        return;
    }
    i -= S2;
    if (i < S3) {
        int n = i / 3072, kp = i % 3072;
        int k = kp / 3, r = kp % 3;
        o_out[i] = bsplit(outw[k * 512 + n], r);
    }
}

__global__ void whead_k(const float* __restrict__ w, __nv_bfloat16* __restrict__ wt) {
    int i = blockIdx.x * 256 + threadIdx.x;
    if (i >= 1024 * 1536) return;
    int n = i / 1536, kp = i % 1536;
    int k = kp / 3, r = kp % 3;
    wt[i] = bsplit(w[k * 1024 + n], r);
}

// combine split-K partials -> proj f32 (ALL 64 cols) + proj_t (A-side triple of cols 0..31)
__global__ void xcomb_k(const float* __restrict__ parts, float* __restrict__ proj,
                        __nv_bfloat16* __restrict__ pt) {
    int i = blockIdx.x * 256 + threadIdx.x;
    if (i >= M4 * 128) return;
    int m = i >> 7, kp = i & 127;
    if (kp < 64) {
        int o = m * 64 + kp;
        proj[o] = parts[o] + parts[204800 + o] + parts[2 * 204800 + o] + parts[3 * 204800 + o];
    }
    if (kp < 96) {
        int k = kp / 3, r = kp % 3;
        int o = m * 64 + k;
        float s = parts[o] + parts[204800 + o] + parts[2 * 204800 + o] + parts[3 * 204800 + o];
        __nv_bfloat16 h = __float2bfloat16(s);
        pt[i] = (r == 2) ? __float2bfloat16(s - __bfloat162float(h)) : h;
    } else {
        pt[i] = __float2bfloat16(0.0f);
    }
}

__global__ void x_t_k(const float* __restrict__ x, __nv_bfloat16* __restrict__ xt) {
    int i = blockIdx.x * 256 + threadIdx.x;
    if (i >= M4 * Dm) return;
    atrip(x[i], xt + (long long)i * 3);
}

// ---------------- RMSNorm -> bf16 triple ----------------
__global__ void rmsnorm_t_k(const float* __restrict__ x, const float* __restrict__ w,
                            __nv_bfloat16* __restrict__ xnt) {
    int row = blockIdx.x;
    int tid = threadIdx.x;   // 128
    const float* xr = x + row * Dm;
    float v[4];
    float s = 0.0f;
#pragma unroll
    for (int i = 0; i < 4; i++) { v[i] = xr[tid + 128 * i]; s += v[i] * v[i]; }
#pragma unroll
    for (int o = 16; o; o >>= 1) s += __shfl_xor_sync(0xffffffffu, s, o);
    __shared__ float ws[4];
    if ((tid & 31) == 0) ws[tid >> 5] = s;
    __syncthreads();
    float tot = ws[0] + ws[1] + ws[2] + ws[3];
    float rs = rsqrtf(tot * (1.0f / Dm) + 1e-5f);
#pragma unroll
    for (int i = 0; i < 4; i++) {
        int c = tid + 128 * i;
        atrip(v[i] * rs * w[c], xnt + (long long)row * 1536 + c * 3);
    }
}

// ---------------- depthwise causal conv (K=4) + SiLU ----------------
__global__ void dwconv_k(const float* __restrict__ xz, const float* __restrict__ cw,
                         const float* __restrict__ cb, float* __restrict__ xi,
                         __nv_bfloat16* __restrict__ xit) {
    int idx = blockIdx.x * 256 + threadIdx.x;
    if (idx >= M4 * DIc) return;
    int d = idx & (DIc - 1);
    int m = idx >> 10;
    int t = m % T4;
    float w0 = cw[d * 4 + 0], w1 = cw[d * 4 + 1], w2 = cw[d * 4 + 2], w3 = cw[d * 4 + 3];
    const float* base = xz + (long long)m * 2048 + d;
    float acc = w3 * base[0];
    if (t >= 1) acc = fmaf(w2, base[-2048], acc);
    if (t >= 2) acc = fmaf(w1, base[-2 * 2048], acc);
    if (t >= 3) acc = fmaf(w0, base[-3 * 2048], acc);
    acc += cb[d];
    float s = acc / (1.0f + expf(-acc));
    xi[idx] = s;
    atrip(s, xit + (long long)m * 3072 + d * 3);
}

// ---------------- selective scan -> yc triple ----------------
__global__ void scan_k(const float* __restrict__ dt, const float* __restrict__ xi,
                       const float* __restrict__ proj, const float* __restrict__ xz,
                       const float* __restrict__ A_log, const float* __restrict__ dskip,
                       __nv_bfloat16* __restrict__ yct) {
    int w = (blockIdx.x * blockDim.x + threadIdx.x) >> 5;
    int lane = threadIdx.x & 31;
    int b = w >> 9;
    int dp = w & 511;
    int d = dp * 2 + (lane >> 4);
    int n = lane & 15;
    float Ac = -expf(A_log[d * Nst + n]);
    float dsk = dskip[d];
    float h = 0.0f;
    int mb = b * T4;
    for (int t = 0; t < T4; t++) {
        int m = mb + t;
        float dtv = dt[m * DIc + d];
        float xiv = xi[m * DIc + d];
        float Bv = proj[m * 64 + 32 + n];
        float Cv = proj[m * 64 + 48 + n];
        float dA = __expf(dtv * Ac);
        h = fmaf(dA, h, dtv * xiv * Bv);
        float p = h * Cv;
        p += __shfl_xor_sync(0xffffffffu, p, 8);
        p += __shfl_xor_sync(0xffffffffu, p, 4);
        p += __shfl_xor_sync(0xffffffffu, p, 2);
        p += __shfl_xor_sync(0xffffffffu, p, 1);
        if (n == 0) {
            float zv = xz[(long long)m * 2048 + DIc + d];
            float yv = p + dsk * xiv;
            atrip(yv * zv / (1.0f + __expf(-zv)), yct + (long long)m * 3072 + d * 3);
        }
    }
}

__global__ void lens_k(const int* __restrict__ fl, float* __restrict__ out, int out_size) {
    int b = threadIdx.x;
    if (b < Bsz && out_size >= M4 * Vv + Bsz) {
        int v = fl[b] >> 2;
        if (v < 1) v = 1;
        out[M4 * Vv + b] = (float)v;
    }
}

// ---------------- launcher ----------------
extern "C" void kernel_launch(void* const* d_in, const int* in_sizes, int n_in,
                              void* d_out, int out_size) {
    (void)in_sizes; (void)n_in;
    const float* feats    = (const float*)d_in[0];
    const int*   feat_lens= (const int*)  d_in[1];
    const float* conv1_w  = (const float*)d_in[2];
    const float* conv1_b  = (const float*)d_in[3];
    const float* conv2_w  = (const float*)d_in[4];
    const float* conv2_b  = (const float*)d_in[5];
    const float* norm_w   = (const float*)d_in[6];
    const float* in_proj  = (const float*)d_in[7];
    const float* dwc_w    = (const float*)d_in[8];
    const float* dwc_b    = (const float*)d_in[9];
    const float* x_proj   = (const float*)d_in[10];
    const float* dt_w     = (const float*)d_in[11];
    const float* dt_b     = (const float*)d_in[12];
    const float* A_log    = (const float*)d_in[13];
    const float* D_skip   = (const float*)d_in[14];
    const float* out_proj = (const float*)d_in[15];
    const float* head_w   = (const float*)d_in[16];
    const float* head_b   = (const float*)d_in[17];
    float* out = (float*)d_out;

    void* sym = nullptr;
    cudaGetSymbolAddress(&sym, g_buf);
    float* gb = (float*)sym;
    __nv_bfloat16* featsp_t = (__nv_bfloat16*)(gb + OFF_FEATSP_T);
    __nv_bfloat16* out1p_t  = (__nv_bfloat16*)(gb + OFF_OUT1P_T);
    __nv_bfloat16* xn_t     = (__nv_bfloat16*)(gb + OFF_XN_T);
    float*         xz       = gb + OFF_XZ;
    float*         xi       = gb + OFF_XI;
    __nv_bfloat16* xi_t     = (__nv_bfloat16*)(gb + OFF_XI_T);
    float*         dtbuf    = gb + OFF_DT;
    float*         proj     = gb + OFF_PROJ;
    __nv_bfloat16* proj_t   = (__nv_bfloat16*)(gb + OFF_PROJ_T);
    __nv_bfloat16* yc_t     = (__nv_bfloat16*)(gb + OFF_YC_T);
    float*         x        = gb + OFF_X;
    __nv_bfloat16* x_t      = (__nv_bfloat16*)(gb + OFF_X_T);
    __nv_bfloat16* w1t      = (__nv_bfloat16*)(gb + OFF_W1T);
    __nv_bfloat16* w2t      = (__nv_bfloat16*)(gb + OFF_W2T);
    __nv_bfloat16* inW      = (__nv_bfloat16*)(gb + OFF_INW);
    __nv_bfloat16* xW       = (__nv_bfloat16*)(gb + OFF_XW);
    __nv_bfloat16* dtW      = (__nv_bfloat16*)(gb + OFF_DTW);
    __nv_bfloat16* outW     = (__nv_bfloat16*)(gb + OFF_OUTW);
    __nv_bfloat16* headW    = (__nv_bfloat16*)(gb + OFF_HEADW);
    float*         xpart    = gb + OFF_XPART;

    const int SM64 = 1024 + 4 * (8192 + 64 * 128);   // 66560
    cudaFuncSetAttribute(bgemm_k<64>, cudaFuncAttributeMaxDynamicSharedMemorySize, SM64);

    // prep + weight conversion
    wconv1_k<<<(512 * 768 + 255) / 256, 256>>>(conv1_w, w1t);
    wconv2_k<<<(512 * 4608 + 255) / 256, 256>>>(conv2_w, w2t);
    prep_feats_t_k<<<(Bsz * Tfull * 80 + 255) / 256, 256>>>(feats, featsp_t);

    // conv1: M=6400, N=512, K'=768 -> out1p_t (triple, rows shifted by +1 pad row)
    bgemm_k<64><<<dim3(8, 100), 256, SM64>>>(
        featsp_t, w1t, conv1_b, out1p_t + 1536,
        12, 768,
        800, 1602LL * 240, 480,
        800, 802LL * 1536, 1536,
        1, 1, 0, 1 << 28, 0);

    zero_out1p_t_k<<<(Bsz * 2 * 1536 + 255) / 256, 256>>>(out1p_t);

    // conv2: M=3200, N=512, K'=4608 -> x f32
    bgemm_k<64><<<dim3(8, 50), 256, SM64>>>(
        out1p_t, w2t, conv2_b, x,
        72, 4608,
        400, 802LL * 1536, 3072,
        M4, 0, 512,
        1, 0, 0, 1 << 28, 0);

    for (int l = 0; l < Ll; l++)
        layer_wconv_k<<<(S0 + S1 + S2 + S3 + 255) / 256, 256>>>(
            in_proj + (size_t)l * Dm * 2048, x_proj + (size_t)l * DIc * 64,
            dt_w + (size_t)l * 32 * DIc, out_proj + (size_t)l * DIc * Dm,
            inW + (size_t)l * S0, xW + (size_t)l * S1,
            dtW + (size_t)l * S2, outW + (size_t)l * S3);
    whead_k<<<(1024 * 1536 + 255) / 256, 256>>>(head_w, headW);

    for (int l = 0; l < Ll; l++) {
        rmsnorm_t_k<<<M4, 128>>>(x, norm_w + l * Dm, xn_t);

        // xz = xn @ in_proj  (3200x2048, K'=1536)
        bgemm_k<64><<<dim3(32, 50), 256, SM64>>>(
            xn_t, inW + (size_t)l * S0, nullptr, xz,
            24, 1536,
            M4, 0, 1536,
            M4, 0, 2048,
            0, 0, 0, 1 << 28, 0);

        dwconv_k<<<(M4 * DIc + 255) / 256, 256>>>(
            xz, dwc_w + l * DIc * 4, dwc_b + l * DIc, xi, xi_t);

        // proj partials = xi @ x_proj  (3200x64, K'=3072, split-K x4: 12 chunks each)
        bgemm_k<64><<<dim3(1, 50, 4), 256, SM64>>>(
            xi_t, xW + (size_t)l * S1, nullptr, xpart,
            48, 3072,
            M4, 0, 3072,
            M4, 0, 64,
            0, 0, 0, 12, 204800);

        xcomb_k<<<(M4 * 128 + 255) / 256, 256>>>(xpart, proj, proj_t);

        // dt = softplus(proj @ dt_w + dt_b)  (3200x1024, K'=128)
        bgemm_k<64><<<dim3(16, 50), 256, SM64>>>(
            proj_t, dtW + (size_t)l * S2, dt_b + l * DIc, dtbuf,
            2, 128,
            M4, 0, 128,
            M4, 0, 1024,
            2, 0, 0, 1 << 28, 0);

        scan_k<<<512, 256>>>(dtbuf, xi, proj, xz,
                             A_log + (size_t)l * DIc * Nst, D_skip + l * DIc, yc_t);

        // x += yc @ out_proj  (3200x512, K'=3072)
        bgemm_k<64><<<dim3(8, 50), 256, SM64>>>(
            yc_t, outW + (size_t)l * S3, nullptr, x,
            48, 3072,
            M4, 0, 3072,
            M4, 0, 512,
            0, 0, 1, 1 << 28, 0);
    }

    x_t_k<<<(M4 * Dm + 255) / 256, 256>>>(x, x_t);

    // logits = x @ head_w + head_b  (3200x1024, K'=1536)
    bgemm_k<64><<<dim3(16, 50), 256, SM64>>>(
        x_t, headW, head_b, out,
        24, 1536,
        M4, 0, 1536,
        M4, 0, 1024,
        0, 0, 0, 1 << 28, 0);

    lens_k<<<1, 32>>>(feat_lens, out, out_size);
}

// round 12
// speedup vs baseline: 1.2185x; 1.1089x over previous
#include <cuda_runtime.h>
#include <cuda_bf16.h>
#include <math.h>
#include <stdint.h>

// ---------------- problem constants ----------------
#define Bsz   8
#define Tfull 1600
#define Dm    512
#define DIc   1024
#define Nst   16
#define Ll    8
#define Vv    1024
#define T4    400
#define M4    (Bsz*T4)    // 3200
#define M2    (Bsz*800)   // 6400

// ---------------- scratch (single __device__ array, ~183MB) ----------------
__device__ float g_buf[45801472];

// offsets in floats
#define OFF_FEATSPA  0
#define OFF_OUT1P    1638400
#define OFF_XN_T     4923392
#define OFF_XZ       6561792
#define OFF_XI       13115392
#define OFF_XI_T     16392192
#define OFF_DT       19668992
#define OFF_PROJ     22945792
#define OFF_PROJ_T   23150592
#define OFF_YC_T     23355392
#define OFF_X        26632192
#define OFF_X_T      28270592
#define OFF_W1T      29908992
#define OFF_W2T      30040064
#define OFF_INW      30826496
#define OFF_XW       39215104
#define OFF_DTW      39739392
#define OFF_OUTW     40263680
#define OFF_HEADW    44457984
#define OFF_XPART    44982272

// layer weight sizes in bf16 elements
#define S0E (2048*1024)
#define S1E (64*2048)
#define S2E (1024*128)
#define S3E (512*2048)

// ---------------- math helpers ----------------
__device__ __forceinline__ float gelu_f(float x) {
    return 0.5f * x * (1.0f + erff(x * 0.70710678118654752f));
}
__device__ __forceinline__ float softplus_f(float x) {
    return fmaxf(x, 0.0f) + log1pf(expf(-fabsf(x)));
}
// value for plane p (0 = hi, 1 = md)
__device__ __forceinline__ __nv_bfloat16 planeval(float v, int plane) {
    __nv_bfloat16 h = __float2bfloat16(v);
    if (plane == 0) return h;
    return __float2bfloat16(v - __bfloat162float(h));
}
// write hi at buf[base], md at buf[base+64]
__device__ __forceinline__ void planewrite(float v, __nv_bfloat16* buf, long long base) {
    __nv_bfloat16 h = __float2bfloat16(v);
    buf[base] = h;
    buf[base + 64] = __float2bfloat16(v - __bfloat162float(h));
}

// ---------------- PTX helpers ----------------
__device__ __forceinline__ uint32_t smem_u32(const void* p) {
    uint32_t a;
    asm("{ .reg .u64 t; cvta.to.shared.u64 t, %1; cvt.u32.u64 %0, t; }" : "=r"(a) : "l"(p));
    return a;
}
#define SW128(x) ((x) ^ (((x) >> 3) & 0x70))
__device__ __forceinline__ void cp16(uint32_t dst, const void* src) {
    asm volatile("cp.async.cg.shared.global [%0], [%1], 16;" :: "r"(dst), "l"(src) : "memory");
}
__device__ __forceinline__ void ldsm4(uint32_t* r, uint32_t addr) {
    asm volatile("ldmatrix.sync.aligned.m8n8.x4.shared.b16 {%0,%1,%2,%3}, [%4];"
                 : "=r"(r[0]), "=r"(r[1]), "=r"(r[2]), "=r"(r[3]) : "r"(addr));
}
__device__ __forceinline__ void mma16(float* c, const uint32_t* a, const uint32_t* b) {
    asm volatile(
        "mma.sync.aligned.m16n8k16.row.col.f32.bf16.bf16.f32 "
        "{%0,%1,%2,%3},{%4,%5,%6,%7},{%8,%9},{%0,%1,%2,%3};"
        : "+f"(c[0]), "+f"(c[1]), "+f"(c[2]), "+f"(c[3])
        : "r"(a[0]), "r"(a[1]), "r"(a[2]), "r"(a[3]), "r"(b[0]), "r"(b[1]));
}

// ---------------- bf16 tensor-core GEMM (hi/md planes, BM=64, BN=64) ----------
// Data layout per row: K/64 blocks of 256B: [128B hi(64 elems) | 128B md(64)].
// Row pitch (a_rs etc.) is in bf16 ELEMENTS and equals 2*K (or more).
// D = sum over k of (Ahi+Amd)(Bhi+Bmd) dropping md*md:
//   per chunk: mma(ahi,bhi) + mma(ahi,bmd) + mma(amd,bhi).
// NC = K/64 chunks. Split-K: blockIdx.z covers [z*ksplit, min(NC,(z+1)*ksplit)),
// f32 out at C + z*zoff.
__global__ void __launch_bounds__(256, 2) bgemm_k(
        const __nv_bfloat16* __restrict__ A,
        const __nv_bfloat16* __restrict__ Bw,
        const float* __restrict__ bias,
        void* __restrict__ Cv,
        int NC, int bpitch,
        int a_rpb, long long a_bs, int a_rs,
        int o_rpb, long long o_bs, int o_rs,
        int act, int outmode, int accum,
        int ksplit, long long zoff) {
    extern __shared__ char smem_raw[];
    uint32_t sb = (smem_u32(smem_raw) + 1023) & ~1023u;
    const uint32_t STG = 32768u;   // A hi 8K | A md 8K | B hi 8K | B md 8K

    int tid = threadIdx.x, wid = tid >> 5, lane = tid & 31;
    int bm = blockIdx.y * 64, bn = blockIdx.x * 64;
    int c0 = blockIdx.z * ksplit;
    int c1 = min(NC, c0 + ksplit);

    // loader precompute: per thread 4 A granules + 4 B granules (16B each)
    const char* abase[4]; uint32_t adst[4];
    const char* bbase[4]; uint32_t bdst[4];
#pragma unroll
    for (int i = 0; i < 4; i++) {
        int G = tid + i * 256;          // 0..1023
        int row = G >> 4, sub = G & 15;
        int gm = bm + row;
        long long aoffE = (long long)(gm / a_rpb) * a_bs + (long long)(gm % a_rpb) * a_rs;
        abase[i] = (const char*)A + 2 * aoffE + sub * 16;
        adst[i] = (uint32_t)((sub >> 3) * 8192) + SW128((uint32_t)(row * 128 + (sub & 7) * 16));
        bbase[i] = (const char*)Bw + 2LL * (bn + row) * bpitch + sub * 16;
        bdst[i] = 16384u + (uint32_t)((sub >> 3) * 8192) + SW128((uint32_t)(row * 128 + (sub & 7) * 16));
    }

    auto issue = [&](int c) {
        uint32_t base = sb + (uint32_t)(c % 3) * STG;
        long long kb = (long long)c * 256;   // 256 bytes per chunk per row
#pragma unroll
        for (int i = 0; i < 4; i++) cp16(base + adst[i], abase[i] + kb);
#pragma unroll
        for (int i = 0; i < 4; i++) cp16(base + bdst[i], bbase[i] + kb);
        asm volatile("cp.async.commit_group;" ::: "memory");
    };

    // warp tiling: 2 m-strips x 4 n-strips; warp tile 32m x 16n
    int wm = wid & 1, wn = wid >> 1;
    float acc[2][2][4];
#pragma unroll
    for (int i = 0; i < 2; i++)
#pragma unroll
        for (int j = 0; j < 2; j++)
#pragma unroll
            for (int r = 0; r < 4; r++) acc[i][j][r] = 0.0f;

    int a_trow = (lane & 7) + ((lane >> 3) & 1) * 8;
    int a_tcol = (lane >> 4) * 16;
    int b_trow = ((lane >> 4) << 3) + (lane & 7);
    int b_tcol = ((lane >> 3) & 1) * 16;

    issue(c0);
    if (c0 + 1 < c1) issue(c0 + 1);

    for (int c = c0; c < c1; c++) {
        if (c + 1 < c1) asm volatile("cp.async.wait_group 1;" ::: "memory");
        else            asm volatile("cp.async.wait_group 0;" ::: "memory");
        __syncthreads();
        if (c + 2 < c1) issue(c + 2);

        uint32_t base = sb + (uint32_t)(c % 3) * STG;
#pragma unroll
        for (int ks = 0; ks < 4; ks++) {
            uint32_t ahi[2][4], amd[2][4];
#pragma unroll
            for (int i = 0; i < 2; i++) {
                int trow = wm * 32 + i * 16 + a_trow;
                uint32_t off = SW128((uint32_t)(trow * 128 + ks * 32 + a_tcol));
                ldsm4(ahi[i], base + off);
                ldsm4(amd[i], base + 8192u + off);
            }
            uint32_t bhi[2][2], bmd[2][2];
            {
                int trow = wn * 16 + b_trow;
                uint32_t off = SW128((uint32_t)(trow * 128 + ks * 32 + b_tcol));
                uint32_t r[4];
                ldsm4(r, base + 16384u + off);
                bhi[0][0] = r[0]; bhi[0][1] = r[1]; bhi[1][0] = r[2]; bhi[1][1] = r[3];
                ldsm4(r, base + 24576u + off);
                bmd[0][0] = r[0]; bmd[0][1] = r[1]; bmd[1][0] = r[2]; bmd[1][1] = r[3];
            }
#pragma unroll
            for (int i = 0; i < 2; i++)
#pragma unroll
                for (int j = 0; j < 2; j++) {
                    mma16(acc[i][j], ahi[i], bhi[j]);
                    mma16(acc[i][j], ahi[i], bmd[j]);
                    mma16(acc[i][j], amd[i], bhi[j]);
                }
        }
    }

    // ---------------- epilogue ----------------
    float* Cz = (float*)Cv + blockIdx.z * zoff;
#pragma unroll
    for (int i = 0; i < 2; i++) {
#pragma unroll
        for (int h = 0; h < 2; h++) {
            int gm = bm + wm * 32 + i * 16 + (lane >> 2) + h * 8;
            long long orow = (long long)(gm / o_rpb) * o_bs + (long long)(gm % o_rpb) * o_rs;
#pragma unroll
            for (int j = 0; j < 2; j++) {
                int gn = bn + wn * 16 + j * 8 + (lane & 3) * 2;
#pragma unroll
                for (int e = 0; e < 2; e++) {
                    float v = acc[i][j][h * 2 + e];
                    int gne = gn + e;
                    if (bias) v += bias[gne];
                    if (act == 1) v = gelu_f(v);
                    else if (act == 2) v = softplus_f(v);
                    if (outmode == 0) {
                        long long o = orow + gne;
                        if (accum) v += Cz[o];
                        Cz[o] = v;
                    } else {
                        __nv_bfloat16* C = (__nv_bfloat16*)Cv;
                        long long o = orow + ((gne >> 6) * 128 + (gne & 63));
                        planewrite(v, C, o);
                    }
                }
            }
        }
    }
}

// ---------------- converters / prep ----------------
// materialized conv1 im2col A: 6400 rows x 512 elems (Kpad=256, planes)
__global__ void conv1a_k(const float* __restrict__ feats, __nv_bfloat16* __restrict__ fa) {
    int i = blockIdx.x * 256 + threadIdx.x;
    if (i >= M2 * 512) return;
    int m = i >> 9, e = i & 511;
    int sub = e & 127, plane = sub >> 6;
    int k = (e >> 7) * 64 + (sub & 63);
    float val = 0.0f;
    if (k < 240) {
        int tap = k / 80, c = k % 80;
        int b = m / 800, p = m % 800;
        int tin = 2 * p - 1 + tap;
        if (tin >= 0 && tin < 1600)
            val = feats[((long long)b * 1600 + tin) * 80 + c];
    }
    fa[i] = planeval(val, plane);
}

__global__ void zero_out1p_k(__nv_bfloat16* __restrict__ op) {
    int i = blockIdx.x * 256 + threadIdx.x;
    if (i < Bsz * 2 * 1024) {
        int e = i & 1023; int r = i >> 10;
        int b = r >> 1; int t = (r & 1) ? 801 : 0;
        op[(long long)(b * 802 + t) * 1024 + e] = __float2bfloat16(0.0f);
    }
}

// conv1 weights: [512 n][512 elems] (Kpad=256)
__global__ void wconv1_k(const float* __restrict__ w, __nv_bfloat16* __restrict__ wt) {
    int i = blockIdx.x * 256 + threadIdx.x;
    if (i >= 512 * 512) return;
    int n = i >> 9, e = i & 511;
    int sub = e & 127, plane = sub >> 6;
    int k = (e >> 7) * 64 + (sub & 63);
    float val = 0.0f;
    if (k < 240) val = w[n * 240 + (k % 80) * 3 + (k / 80)];
    wt[i] = planeval(val, plane);
}
// conv2 weights: [512 n][3072 elems] (K=1536)
__global__ void wconv2_k(const float* __restrict__ w, __nv_bfloat16* __restrict__ wt) {
    int i = blockIdx.x * 256 + threadIdx.x;
    if (i >= 512 * 3072) return;
    int n = i / 3072, e = i % 3072;
    int sub = e & 127, plane = sub >> 6;
    int k = (e >> 7) * 64 + (sub & 63);
    int tap = k / 512, c = k & 511;
    wt[i] = planeval(w[n * 1536 + c * 3 + tap], plane);
}

__global__ void layer_wconv_k(const float* __restrict__ inw, const float* __restrict__ xw,
                              const float* __restrict__ dtw, const float* __restrict__ outw,
                              __nv_bfloat16* __restrict__ o_in, __nv_bfloat16* __restrict__ o_x,
                              __nv_bfloat16* __restrict__ o_dt, __nv_bfloat16* __restrict__ o_out) {
    int i = blockIdx.x * 256 + threadIdx.x;
    if (i < S0E) {   // in_proj [512 k][2048 n] -> [2048 n][1024 elems]
        int n = i >> 10, e = i & 1023;
        int sub = e & 127, plane = sub >> 6;
        int k = (e >> 7) * 64 + (sub & 63);
        o_in[i] = planeval(inw[k * 2048 + n], plane);
        return;
    }
    i -= S0E;
    if (i < S1E) {   // x_proj [1024 k][64 n] -> [64 n][2048 elems]
        int n = i >> 11, e = i & 2047;
        int sub = e & 127, plane = sub >> 6;
        int k = (e >> 7) * 64 + (sub & 63);
        o_x[i] = planeval(xw[k * 64 + n], plane);
        return;
    }
    i -= S1E;
    if (i < S2E) {   // dt_w [32 k][1024 n] -> [1024 n][128 elems] (Kpad=64)
        int n = i >> 7, e = i & 127;
        int plane = e >> 6, k = e & 63;
        float val = (k < 32) ? dtw[k * 1024 + n] : 0.0f;
        o_dt[i] = planeval(val, plane);
        return;
    }
    i -= S2E;
    if (i < S3E) {   // out_proj [1024 k][512 n] -> [512 n][2048 elems]
        int n = i >> 11, e = i & 2047;
        int sub = e & 127, plane = sub >> 6;
        int k = (e >> 7) * 64 + (sub & 63);
        o_out[i] = planeval(outw[k * 512 + n], plane);
    }
}

__global__ void whead_k(const float* __restrict__ w, __nv_bfloat16* __restrict__ wt) {
    int i = blockIdx.x * 256 + threadIdx.x;
    if (i >= 1024 * 1024) return;   // [512 k][1024 n] -> [1024 n][1024 elems]
    int n = i >> 10, e = i & 1023;
    int sub = e & 127, plane = sub >> 6;
    int k = (e >> 7) * 64 + (sub & 63);
    wt[i] = planeval(w[k * 1024 + n], plane);
}

// split-K combine -> proj f32 (all 64 cols) + proj_t planes [3200][128]
__global__ void xcomb_k(const float* __restrict__ parts, float* __restrict__ proj,
                        __nv_bfloat16* __restrict__ pt) {
    int i = blockIdx.x * 256 + threadIdx.x;
    if (i >= M4 * 128) return;
    int m = i >> 7, e = i & 127;
    if (e < 64) {
        int o = m * 64 + e;
        proj[o] = parts[o] + parts[204800 + o] + parts[2 * 204800 + o] + parts[3 * 204800 + o];
    }
    int plane = e >> 6, k = e & 63;
    float v = 0.0f;
    if (k < 32) {
        int o = m * 64 + k;
        v = parts[o] + parts[204800 + o] + parts[2 * 204800 + o] + parts[3 * 204800 + o];
    }
    pt[i] = planeval(v, plane);
}

__global__ void x_t_k(const float* __restrict__ x, __nv_bfloat16* __restrict__ xt) {
    int i = blockIdx.x * 256 + threadIdx.x;
    if (i >= M4 * Dm) return;
    int m = i >> 9, c = i & 511;
    planewrite(x[i], xt, (long long)m * 1024 + ((c >> 6) * 128 + (c & 63)));
}

// ---------------- RMSNorm -> planes ----------------
__global__ void rmsnorm_t_k(const float* __restrict__ x, const float* __restrict__ w,
                            __nv_bfloat16* __restrict__ xnt) {
    int row = blockIdx.x;
    int tid = threadIdx.x;   // 128
    const float* xr = x + (long long)row * Dm;
    float v[4];
    float s = 0.0f;
#pragma unroll
    for (int i = 0; i < 4; i++) { v[i] = xr[tid + 128 * i]; s += v[i] * v[i]; }
#pragma unroll
    for (int o = 16; o; o >>= 1) s += __shfl_xor_sync(0xffffffffu, s, o);
    __shared__ float ws[4];
    if ((tid & 31) == 0) ws[tid >> 5] = s;
    __syncthreads();
    float tot = ws[0] + ws[1] + ws[2] + ws[3];
    float rs = rsqrtf(tot * (1.0f / Dm) + 1e-5f);
#pragma unroll
    for (int i = 0; i < 4; i++) {
        int c = tid + 128 * i;
        planewrite(v[i] * rs * w[c], xnt, (long long)row * 1024 + ((c >> 6) * 128 + (c & 63)));
    }
}

// ---------------- depthwise causal conv (K=4) + SiLU ----------------
__global__ void dwconv_k(const float* __restrict__ xz, const float* __restrict__ cw,
                         const float* __restrict__ cb, float* __restrict__ xi,
                         __nv_bfloat16* __restrict__ xit) {
    int idx = blockIdx.x * 256 + threadIdx.x;
    if (idx >= M4 * DIc) return;
    int d = idx & (DIc - 1);
    int m = idx >> 10;
    int t = m % T4;
    float w0 = cw[d * 4 + 0], w1 = cw[d * 4 + 1], w2 = cw[d * 4 + 2], w3 = cw[d * 4 + 3];
    const float* base = xz + (long long)m * 2048 + d;
    float acc = w3 * base[0];
    if (t >= 1) acc = fmaf(w2, base[-2048], acc);
    if (t >= 2) acc = fmaf(w1, base[-2 * 2048], acc);
    if (t >= 3) acc = fmaf(w0, base[-3 * 2048], acc);
    acc += cb[d];
    float s = acc / (1.0f + expf(-acc));
    xi[idx] = s;
    planewrite(s, xit, (long long)m * 2048 + ((d >> 6) * 128 + (d & 63)));
}

// ---------------- selective scan -> yc planes ----------------
__global__ void scan_k(const float* __restrict__ dt, const float* __restrict__ xi,
                       const float* __restrict__ proj, const float* __restrict__ xz,
                       const float* __restrict__ A_log, const float* __restrict__ dskip,
                       __nv_bfloat16* __restrict__ yct) {
    int w = (blockIdx.x * blockDim.x + threadIdx.x) >> 5;
    int lane = threadIdx.x & 31;
    int b = w >> 9;
    int dp = w & 511;
    int d = dp * 2 + (lane >> 4);
    int n = lane & 15;
    float Ac = -expf(A_log[d * Nst + n]);
    float dsk = dskip[d];
    float h = 0.0f;
    int mb = b * T4;
    for (int t = 0; t < T4; t++) {
        int m = mb + t;
        float dtv = dt[m * DIc + d];
        float xiv = xi[m * DIc + d];
        float Bv = proj[m * 64 + 32 + n];
        float Cv = proj[m * 64 + 48 + n];
        float dA = __expf(dtv * Ac);
        h = fmaf(dA, h, dtv * xiv * Bv);
        float p = h * Cv;
        p += __shfl_xor_sync(0xffffffffu, p, 8);
        p += __shfl_xor_sync(0xffffffffu, p, 4);
        p += __shfl_xor_sync(0xffffffffu, p, 2);
        p += __shfl_xor_sync(0xffffffffu, p, 1);
        if (n == 0) {
            float zv = xz[(long long)m * 2048 + DIc + d];
            float yv = p + dsk * xiv;
            planewrite(yv * zv / (1.0f + __expf(-zv)), yct,
                       (long long)m * 2048 + ((d >> 6) * 128 + (d & 63)));
        }
    }
}

__global__ void lens_k(const int* __restrict__ fl, float* __restrict__ out, int out_size) {
    int b = threadIdx.x;
    if (b < Bsz && out_size >= M4 * Vv + Bsz) {
        int v = fl[b] >> 2;
        if (v < 1) v = 1;
        out[M4 * Vv + b] = (float)v;
    }
}

// ---------------- launcher ----------------
extern "C" void kernel_launch(void* const* d_in, const int* in_sizes, int n_in,
                              void* d_out, int out_size) {
    (void)in_sizes; (void)n_in;
    const float* feats    = (const float*)d_in[0];
    const int*   feat_lens= (const int*)  d_in[1];
    const float* conv1_w  = (const float*)d_in[2];
    const float* conv1_b  = (const float*)d_in[3];
    const float* conv2_w  = (const float*)d_in[4];
    const float* conv2_b  = (const float*)d_in[5];
    const float* norm_w   = (const float*)d_in[6];
    const float* in_proj  = (const float*)d_in[7];
    const float* dwc_w    = (const float*)d_in[8];
    const float* dwc_b    = (const float*)d_in[9];
    const float* x_proj   = (const float*)d_in[10];
    const float* dt_w     = (const float*)d_in[11];
    const float* dt_b     = (const float*)d_in[12];
    const float* A_log    = (const float*)d_in[13];
    const float* D_skip   = (const float*)d_in[14];
    const float* out_proj = (const float*)d_in[15];
    const float* head_w   = (const float*)d_in[16];
    const float* head_b   = (const float*)d_in[17];
    float* out = (float*)d_out;

    void* sym = nullptr;
    cudaGetSymbolAddress(&sym, g_buf);
    float* gb = (float*)sym;
    __nv_bfloat16* featspA = (__nv_bfloat16*)(gb + OFF_FEATSPA);
    __nv_bfloat16* out1p   = (__nv_bfloat16*)(gb + OFF_OUT1P);
    __nv_bfloat16* xn_t    = (__nv_bfloat16*)(gb + OFF_XN_T);
    float*         xz      = gb + OFF_XZ;
    float*         xi      = gb + OFF_XI;
    __nv_bfloat16* xi_t    = (__nv_bfloat16*)(gb + OFF_XI_T);
    float*         dtbuf   = gb + OFF_DT;
    float*         proj    = gb + OFF_PROJ;
    __nv_bfloat16* proj_t  = (__nv_bfloat16*)(gb + OFF_PROJ_T);
    __nv_bfloat16* yc_t    = (__nv_bfloat16*)(gb + OFF_YC_T);
    float*         x       = gb + OFF_X;
    __nv_bfloat16* x_t     = (__nv_bfloat16*)(gb + OFF_X_T);
    __nv_bfloat16* w1t     = (__nv_bfloat16*)(gb + OFF_W1T);
    __nv_bfloat16* w2t     = (__nv_bfloat16*)(gb + OFF_W2T);
    __nv_bfloat16* inW     = (__nv_bfloat16*)(gb + OFF_INW);
    __nv_bfloat16* xW      = (__nv_bfloat16*)(gb + OFF_XW);
    __nv_bfloat16* dtW     = (__nv_bfloat16*)(gb + OFF_DTW);
    __nv_bfloat16* outW    = (__nv_bfloat16*)(gb + OFF_OUTW);
    __nv_bfloat16* headW   = (__nv_bfloat16*)(gb + OFF_HEADW);
    float*         xpart   = gb + OFF_XPART;

    const int SMB = 1024 + 3 * 32768;   // 99328
    cudaFuncSetAttribute(bgemm_k, cudaFuncAttributeMaxDynamicSharedMemorySize, SMB);
    const int BIGK = 1 << 28;

    // prep + weight conversion
    wconv1_k<<<(512 * 512 + 255) / 256, 256>>>(conv1_w, w1t);
    wconv2_k<<<(512 * 3072 + 255) / 256, 256>>>(conv2_w, w2t);
    conv1a_k<<<(M2 * 512 + 255) / 256, 256>>>(feats, featspA);

    // conv1: M=6400, N=512, K=256 -> out1p planes (skip pad row t=0)
    bgemm_k<<<dim3(8, 100), 256, SMB>>>(
        featspA, w1t, conv1_b, out1p + 1024,
        4, 512,
        M2, 0, 512,
        800, 802LL * 1024, 1024,
        1, 1, 0, BIGK, 0);

    zero_out1p_k<<<(Bsz * 2 * 1024 + 255) / 256, 256>>>(out1p);

    // conv2: M=3200, N=512, K=1536 -> x f32
    bgemm_k<<<dim3(8, 50), 256, SMB>>>(
        out1p, w2t, conv2_b, x,
        24, 3072,
        400, 802LL * 1024, 2048,
        M4, 0, 512,
        1, 0, 0, BIGK, 0);

    for (int l = 0; l < Ll; l++)
        layer_wconv_k<<<(S0E + S1E + S2E + S3E + 255) / 256, 256>>>(
            in_proj + (size_t)l * Dm * 2048, x_proj + (size_t)l * DIc * 64,
            dt_w + (size_t)l * 32 * DIc, out_proj + (size_t)l * DIc * Dm,
            inW + (size_t)l * S0E, xW + (size_t)l * S1E,
            dtW + (size_t)l * S2E, outW + (size_t)l * S3E);
    whead_k<<<(1024 * 1024 + 255) / 256, 256>>>(head_w, headW);

    for (int l = 0; l < Ll; l++) {
        rmsnorm_t_k<<<M4, 128>>>(x, norm_w + l * Dm, xn_t);

        // xz = xn @ in_proj  (3200x2048, K=512)
        bgemm_k<<<dim3(32, 50), 256, SMB>>>(
            xn_t, inW + (size_t)l * S0E, nullptr, xz,
            8, 1024,
            M4, 0, 1024,
            M4, 0, 2048,
            0, 0, 0, BIGK, 0);

        dwconv_k<<<(M4 * DIc + 255) / 256, 256>>>(
            xz, dwc_w + l * DIc * 4, dwc_b + l * DIc, xi, xi_t);

        // proj partials = xi @ x_proj  (3200x64, K=1024, split-K x4)
        bgemm_k<<<dim3(1, 50, 4), 256, SMB>>>(
            xi_t, xW + (size_t)l * S1E, nullptr, xpart,
            16, 2048,
            M4, 0, 2048,
            M4, 0, 64,
            0, 0, 0, 4, 204800);

        xcomb_k<<<(M4 * 128 + 255) / 256, 256>>>(xpart, proj, proj_t);

        // dt = softplus(proj @ dt_w + dt_b)  (3200x1024, K=64)
        bgemm_k<<<dim3(16, 50), 256, SMB>>>(
            proj_t, dtW + (size_t)l * S2E, dt_b + l * DIc, dtbuf,
            1, 128,
            M4, 0, 128,
            M4, 0, 1024,
            2, 0, 0, BIGK, 0);

        scan_k<<<512, 256>>>(dtbuf, xi, proj, xz,
                             A_log + (size_t)l * DIc * Nst, D_skip + l * DIc, yc_t);

        // x += yc @ out_proj  (3200x512, K=1024)
        bgemm_k<<<dim3(8, 50), 256, SMB>>>(
            yc_t, outW + (size_t)l * S3E, nullptr, x,
            16, 2048,
            M4, 0, 2048,
            M4, 0, 512,
            0, 0, 1, BIGK, 0);
    }

    x_t_k<<<(M4 * Dm + 255) / 256, 256>>>(x, x_t);

    // logits = x @ head_w + head_b  (3200x1024, K=512)
    bgemm_k<<<dim3(16, 50), 256, SMB>>>(
        x_t, headW, head_b, out,
        8, 1024,
        M4, 0, 1024,
        M4, 0, 1024,
        0, 0, 0, BIGK, 0);

    lens_k<<<1, 32>>>(feat_lens, out, out_size);
}

// round 14
// speedup vs baseline: 1.2479x; 1.0242x over previous
#include <cuda_runtime.h>
#include <cuda_bf16.h>
#include <math.h>
#include <stdint.h>

// ---------------- problem constants ----------------
#define Bsz   8
#define Tfull 1600
#define Dm    512
#define DIc   1024
#define Nst   16
#define Ll    8
#define Vv    1024
#define T4    400
#define M4    (Bsz*T4)    // 3200
#define M2    (Bsz*800)   // 6400

// ---------------- scratch (single __device__ array, ~183MB) ----------------
__device__ float g_buf[45801472];

// offsets in floats
#define OFF_FEATSPA  0
#define OFF_OUT1P    1638400
#define OFF_XN_T     4923392
#define OFF_XZ       6561792
#define OFF_XI       13115392
#define OFF_XI_T     16392192
#define OFF_DT       19668992
#define OFF_PROJ     22945792
#define OFF_PROJ_T   23150592
#define OFF_YC_T     23355392
#define OFF_X        26632192
#define OFF_X_T      28270592
#define OFF_W1T      29908992
#define OFF_W2T      30040064
#define OFF_INW      30826496
#define OFF_XW       39215104
#define OFF_DTW      39739392
#define OFF_OUTW     40263680
#define OFF_HEADW    44457984
#define OFF_XPART    44982272

// layer weight sizes in bf16 elements
#define S0E (2048*1024)
#define S1E (64*2048)
#define S2E (1024*128)
#define S3E (512*2048)

// ---------------- math helpers ----------------
__device__ __forceinline__ float gelu_f(float x) {
    return 0.5f * x * (1.0f + erff(x * 0.70710678118654752f));
}
__device__ __forceinline__ float softplus_f(float x) {
    return fmaxf(x, 0.0f) + log1pf(expf(-fabsf(x)));
}
// value for plane p (0 = hi, 1 = md)
__device__ __forceinline__ __nv_bfloat16 planeval(float v, int plane) {
    __nv_bfloat16 h = __float2bfloat16(v);
    if (plane == 0) return h;
    return __float2bfloat16(v - __bfloat162float(h));
}
// write hi at buf[base], md at buf[base+64]
__device__ __forceinline__ void planewrite(float v, __nv_bfloat16* buf, long long base) {
    __nv_bfloat16 h = __float2bfloat16(v);
    buf[base] = h;
    buf[base + 64] = __float2bfloat16(v - __bfloat162float(h));
}

// ---------------- PTX helpers ----------------
__device__ __forceinline__ uint32_t smem_u32(const void* p) {
    uint32_t a;
    asm("{ .reg .u64 t; cvta.to.shared.u64 t, %1; cvt.u32.u64 %0, t; }" : "=r"(a) : "l"(p));
    return a;
}
#define SW128(x) ((x) ^ (((x) >> 3) & 0x70))
__device__ __forceinline__ void cp16(uint32_t dst, const void* src) {
    asm volatile("cp.async.cg.shared.global [%0], [%1], 16;" :: "r"(dst), "l"(src) : "memory");
}
__device__ __forceinline__ void ldsm4(uint32_t* r, uint32_t addr) {
    asm volatile("ldmatrix.sync.aligned.m8n8.x4.shared.b16 {%0,%1,%2,%3}, [%4];"
                 : "=r"(r[0]), "=r"(r[1]), "=r"(r[2]), "=r"(r[3]) : "r"(addr));
}
__device__ __forceinline__ void mma16(float* c, const uint32_t* a, const uint32_t* b) {
    asm volatile(
        "mma.sync.aligned.m16n8k16.row.col.f32.bf16.bf16.f32 "
        "{%0,%1,%2,%3},{%4,%5,%6,%7},{%8,%9},{%0,%1,%2,%3};"
        : "+f"(c[0]), "+f"(c[1]), "+f"(c[2]), "+f"(c[3])
        : "r"(a[0]), "r"(a[1]), "r"(a[2]), "r"(a[3]), "r"(b[0]), "r"(b[1]));
}

// ---------------- bf16 tensor-core GEMM (hi/md planes, BM=64, BN=64) ----------
// Data per row: K/64 blocks of 256B: [128B hi | 128B md]. Row pitch in ELEMENTS.
// Per chunk: mma(ahi,bhi) + mma(ahi,bmd) + mma(amd,bhi).  NC = K/64.
// 2-stage pipeline, 3 CTAs/SM. Split-K via blockIdx.z (f32 out at C + z*zoff).
__global__ void __launch_bounds__(256, 3) bgemm_k(
        const __nv_bfloat16* __restrict__ A,
        const __nv_bfloat16* __restrict__ Bw,
        const float* __restrict__ bias,
        void* __restrict__ Cv,
        int NC, int bpitch,
        int a_rpb, long long a_bs, int a_rs,
        int o_rpb, long long o_bs, int o_rs,
        int act, int outmode, int accum,
        int ksplit, long long zoff) {
    extern __shared__ char smem_raw[];
    uint32_t sb = (smem_u32(smem_raw) + 1023) & ~1023u;
    const uint32_t STG = 32768u;   // A hi 8K | A md 8K | B hi 8K | B md 8K

    int tid = threadIdx.x, wid = tid >> 5, lane = tid & 31;
    int bm = blockIdx.y * 64, bn = blockIdx.x * 64;
    int c0 = blockIdx.z * ksplit;
    int c1 = min(NC, c0 + ksplit);

    // loader precompute: base pointer + int byte-deltas (register-slim)
    const char* aptr0; int adel[4]; uint32_t adst[4];
    const char* bptr0; int bdel[4]; uint32_t bdst[4];
    {
        long long aref = 0;
#pragma unroll
        for (int i = 0; i < 4; i++) {
            int G = tid + i * 256;          // 0..1023
            int row = G >> 4, sub = G & 15;
            int gm = bm + row;
            long long off = 2 * ((long long)(gm / a_rpb) * a_bs + (long long)(gm % a_rpb) * a_rs)
                          + sub * 16;
            if (i == 0) { aref = off; aptr0 = (const char*)A + off; }
            adel[i] = (int)(off - aref);
            adst[i] = (uint32_t)((sub >> 3) * 8192) + SW128((uint32_t)(row * 128 + (sub & 7) * 16));
        }
        long long bref = 0;
#pragma unroll
        for (int i = 0; i < 4; i++) {
            int G = tid + i * 256;
            int row = G >> 4, sub = G & 15;
            long long off = 2LL * (bn + row) * bpitch + sub * 16;
            if (i == 0) { bref = off; bptr0 = (const char*)Bw + off; }
            bdel[i] = (int)(off - bref);
            bdst[i] = 16384u + (uint32_t)((sub >> 3) * 8192) + SW128((uint32_t)(row * 128 + (sub & 7) * 16));
        }
    }

    auto issue = [&](int c) {
        uint32_t base = sb + (uint32_t)(c & 1) * STG;
        long long kb = (long long)c * 256;
#pragma unroll
        for (int i = 0; i < 4; i++) cp16(base + adst[i], aptr0 + adel[i] + kb);
#pragma unroll
        for (int i = 0; i < 4; i++) cp16(base + bdst[i], bptr0 + bdel[i] + kb);
        asm volatile("cp.async.commit_group;" ::: "memory");
    };

    // warp tiling: 2 m-strips x 4 n-strips; warp tile 32m x 16n
    int wm = wid & 1, wn = wid >> 1;
    float acc[2][2][4];
#pragma unroll
    for (int i = 0; i < 2; i++)
#pragma unroll
        for (int j = 0; j < 2; j++)
#pragma unroll
            for (int r = 0; r < 4; r++) acc[i][j][r] = 0.0f;

    int a_trow = (lane & 7) + ((lane >> 3) & 1) * 8;
    int a_tcol = (lane >> 4) * 16;
    int b_trow = ((lane >> 4) << 3) + (lane & 7);
    int b_tcol = ((lane >> 3) & 1) * 16;

    issue(c0);
    if (c0 + 1 < c1) issue(c0 + 1);

    for (int c = c0; c < c1; c++) {
        if (c + 1 < c1) asm volatile("cp.async.wait_group 1;" ::: "memory");
        else            asm volatile("cp.async.wait_group 0;" ::: "memory");
        __syncthreads();

        uint32_t base = sb + (uint32_t)(c & 1) * STG;
#pragma unroll
        for (int ks = 0; ks < 4; ks++) {
            uint32_t ahi[2][4], amd[2][4];
#pragma unroll
            for (int i = 0; i < 2; i++) {
                int trow = wm * 32 + i * 16 + a_trow;
                uint32_t off = SW128((uint32_t)(trow * 128 + ks * 32 + a_tcol));
                ldsm4(ahi[i], base + off);
                ldsm4(amd[i], base + 8192u + off);
            }
            uint32_t bhi[2][2], bmd[2][2];
            {
                int trow = wn * 16 + b_trow;
                uint32_t off = SW128((uint32_t)(trow * 128 + ks * 32 + b_tcol));
                uint32_t r[4];
                ldsm4(r, base + 16384u + off);
                bhi[0][0] = r[0]; bhi[0][1] = r[1]; bhi[1][0] = r[2]; bhi[1][1] = r[3];
                ldsm4(r, base + 24576u + off);
                bmd[0][0] = r[0]; bmd[0][1] = r[1]; bmd[1][0] = r[2]; bmd[1][1] = r[3];
            }
#pragma unroll
            for (int i = 0; i < 2; i++)
#pragma unroll
                for (int j = 0; j < 2; j++) {
                    mma16(acc[i][j], ahi[i], bhi[j]);
                    mma16(acc[i][j], ahi[i], bmd[j]);
                    mma16(acc[i][j], amd[i], bhi[j]);
                }
        }

        if (c + 2 < c1) {
            __syncthreads();   // all warps done reading stage (c&1) before refill
            issue(c + 2);
        }
    }

    // ---------------- epilogue ----------------
    float* Cz = (float*)Cv + blockIdx.z * zoff;
#pragma unroll
    for (int i = 0; i < 2; i++) {
#pragma unroll
        for (int h = 0; h < 2; h++) {
            int gm = bm + wm * 32 + i * 16 + (lane >> 2) + h * 8;
            long long orow = (long long)(gm / o_rpb) * o_bs + (long long)(gm % o_rpb) * o_rs;
#pragma unroll
            for (int j = 0; j < 2; j++) {
                int gn = bn + wn * 16 + j * 8 + (lane & 3) * 2;
#pragma unroll
                for (int e = 0; e < 2; e++) {
                    float v = acc[i][j][h * 2 + e];
                    int gne = gn + e;
                    if (bias) v += bias[gne];
                    if (act == 1) v = gelu_f(v);
                    else if (act == 2) v = softplus_f(v);
                    if (outmode == 0) {
                        long long o = orow + gne;
                        if (accum) v += Cz[o];
                        Cz[o] = v;
                    } else {
                        __nv_bfloat16* C = (__nv_bfloat16*)Cv;
                        long long o = orow + ((gne >> 6) * 128 + (gne & 63));
                        planewrite(v, C, o);
                    }
                }
            }
        }
    }
}

// ---------------- converters / prep ----------------
__global__ void conv1a_k(const float* __restrict__ feats, __nv_bfloat16* __restrict__ fa) {
    int i = blockIdx.x * 256 + threadIdx.x;
    if (i >= M2 * 512) return;
    int m = i >> 9, e = i & 511;
    int sub = e & 127, plane = sub >> 6;
    int k = (e >> 7) * 64 + (sub & 63);
    float val = 0.0f;
    if (k < 240) {
        int tap = k / 80, c = k % 80;
        int b = m / 800, p = m % 800;
        int tin = 2 * p - 1 + tap;
        if (tin >= 0 && tin < 1600)
            val = feats[((long long)b * 1600 + tin) * 80 + c];
    }
    fa[i] = planeval(val, plane);
}

__global__ void zero_out1p_k(__nv_bfloat16* __restrict__ op) {
    int i = blockIdx.x * 256 + threadIdx.x;
    if (i < Bsz * 2 * 1024) {
        int e = i & 1023; int r = i >> 10;
        int b = r >> 1; int t = (r & 1) ? 801 : 0;
        op[(long long)(b * 802 + t) * 1024 + e] = __float2bfloat16(0.0f);
    }
}

__global__ void wconv1_k(const float* __restrict__ w, __nv_bfloat16* __restrict__ wt) {
    int i = blockIdx.x * 256 + threadIdx.x;
    if (i >= 512 * 512) return;
    int n = i >> 9, e = i & 511;
    int sub = e & 127, plane = sub >> 6;
    int k = (e >> 7) * 64 + (sub & 63);
    float val = 0.0f;
    if (k < 240) val = w[n * 240 + (k % 80) * 3 + (k / 80)];
    wt[i] = planeval(val, plane);
}
__global__ void wconv2_k(const float* __restrict__ w, __nv_bfloat16* __restrict__ wt) {
    int i = blockIdx.x * 256 + threadIdx.x;
    if (i >= 512 * 3072) return;
    int n = i / 3072, e = i % 3072;
    int sub = e & 127, plane = sub >> 6;
    int k = (e >> 7) * 64 + (sub & 63);
    int tap = k / 512, c = k & 511;
    wt[i] = planeval(w[n * 1536 + c * 3 + tap], plane);
}

__global__ void layer_wconv_k(const float* __restrict__ inw, const float* __restrict__ xw,
                              const float* __restrict__ dtw, const float* __restrict__ outw,
                              __nv_bfloat16* __restrict__ o_in, __nv_bfloat16* __restrict__ o_x,
                              __nv_bfloat16* __restrict__ o_dt, __nv_bfloat16* __restrict__ o_out) {
    int i = blockIdx.x * 256 + threadIdx.x;
    if (i < S0E) {
        int n = i >> 10, e = i & 1023;
        int sub = e & 127, plane = sub >> 6;
        int k = (e >> 7) * 64 + (sub & 63);
        o_in[i] = planeval(inw[k * 2048 + n], plane);
        return;
    }
    i -= S0E;
    if (i < S1E) {
        int n = i >> 11, e = i & 2047;
        int sub = e & 127, plane = sub >> 6;
        int k = (e >> 7) * 64 + (sub & 63);
        o_x[i] = planeval(xw[k * 64 + n], plane);
        return;
    }
    i -= S1E;
    if (i < S2E) {
        int n = i >> 7, e = i & 127;
        int plane = e >> 6, k = e & 63;
        float val = (k < 32) ? dtw[k * 1024 + n] : 0.0f;
        o_dt[i] = planeval(val, plane);
        return;
    }
    i -= S2E;
    if (i < S3E) {
        int n = i >> 11, e = i & 2047;
        int sub = e & 127, plane = sub >> 6;
        int k = (e >> 7) * 64 + (sub & 63);
        o_out[i] = planeval(outw[k * 512 + n], plane);
    }
}

__global__ void whead_k(const float* __restrict__ w, __nv_bfloat16* __restrict__ wt) {
    int i = blockIdx.x * 256 + threadIdx.x;
    if (i >= 1024 * 1024) return;
    int n = i >> 10, e = i & 1023;
    int sub = e & 127, plane = sub >> 6;
    int k = (e >> 7) * 64 + (sub & 63);
    wt[i] = planeval(w[k * 1024 + n], plane);
}

__global__ void xcomb_k(const float* __restrict__ parts, float* __restrict__ proj,
                        __nv_bfloat16* __restrict__ pt) {
    int i = blockIdx.x * 256 + threadIdx.x;
    if (i >= M4 * 128) return;
    int m = i >> 7, e = i & 127;
    if (e < 64) {
        int o = m * 64 + e;
        proj[o] = parts[o] + parts[204800 + o] + parts[2 * 204800 + o] + parts[3 * 204800 + o];
    }
    int plane = e >> 6, k = e & 63;
    float v = 0.0f;
    if (k < 32) {
        int o = m * 64 + k;
        v = parts[o] + parts[204800 + o] + parts[2 * 204800 + o] + parts[3 * 204800 + o];
    }
    pt[i] = planeval(v, plane);
}

__global__ void x_t_k(const float* __restrict__ x, __nv_bfloat16* __restrict__ xt) {
    int i = blockIdx.x * 256 + threadIdx.x;
    if (i >= M4 * Dm) return;
    int m = i >> 9, c = i & 511;
    planewrite(x[i], xt, (long long)m * 1024 + ((c >> 6) * 128 + (c & 63)));
}

// ---------------- RMSNorm -> planes ----------------
__global__ void rmsnorm_t_k(const float* __restrict__ x, const float* __restrict__ w,
                            __nv_bfloat16* __restrict__ xnt) {
    int row = blockIdx.x;
    int tid = threadIdx.x;   // 128
    const float* xr = x + (long long)row * Dm;
    float v[4];
    float s = 0.0f;
#pragma unroll
    for (int i = 0; i < 4; i++) { v[i] = xr[tid + 128 * i]; s += v[i] * v[i]; }
#pragma unroll
    for (int o = 16; o; o >>= 1) s += __shfl_xor_sync(0xffffffffu, s, o);
    __shared__ float ws[4];
    if ((tid & 31) == 0) ws[tid >> 5] = s;
    __syncthreads();
    float tot = ws[0] + ws[1] + ws[2] + ws[3];
    float rs = rsqrtf(tot * (1.0f / Dm) + 1e-5f);
#pragma unroll
    for (int i = 0; i < 4; i++) {
        int c = tid + 128 * i;
        planewrite(v[i] * rs * w[c], xnt, (long long)row * 1024 + ((c >> 6) * 128 + (c & 63)));
    }
}

// ---------------- depthwise causal conv (K=4) + SiLU ----------------
__global__ void dwconv_k(const float* __restrict__ xz, const float* __restrict__ cw,
                         const float* __restrict__ cb, float* __restrict__ xi,
                         __nv_bfloat16* __restrict__ xit) {
    int idx = blockIdx.x * 256 + threadIdx.x;
    if (idx >= M4 * DIc) return;
    int d = idx & (DIc - 1);
    int m = idx >> 10;
    int t = m % T4;
    float w0 = cw[d * 4 + 0], w1 = cw[d * 4 + 1], w2 = cw[d * 4 + 2], w3 = cw[d * 4 + 3];
    const float* base = xz + (long long)m * 2048 + d;
    float acc = w3 * base[0];
    if (t >= 1) acc = fmaf(w2, base[-2048], acc);
    if (t >= 2) acc = fmaf(w1, base[-2 * 2048], acc);
    if (t >= 3) acc = fmaf(w0, base[-3 * 2048], acc);
    acc += cb[d];
    float s = acc / (1.0f + expf(-acc));
    xi[idx] = s;
    planewrite(s, xit, (long long)m * 2048 + ((d >> 6) * 128 + (d & 63)));
}

// ---------------- selective scan -> yc planes ----------------
__global__ void scan_k(const float* __restrict__ dt, const float* __restrict__ xi,
                       const float* __restrict__ proj, const float* __restrict__ xz,
                       const float* __restrict__ A_log, const float* __restrict__ dskip,
                       __nv_bfloat16* __restrict__ yct) {
    int w = (blockIdx.x * blockDim.x + threadIdx.x) >> 5;
    int lane = threadIdx.x & 31;
    int b = w >> 9;
    int dp = w & 511;
    int d = dp * 2 + (lane >> 4);
    int n = lane & 15;
    float Ac = -expf(A_log[d * Nst + n]);
    float dsk = dskip[d];
    float h = 0.0f;
    int mb = b * T4;
    for (int t = 0; t < T4; t++) {
        int m = mb + t;
        float dtv = dt[m * DIc + d];
        float xiv = xi[m * DIc + d];
        float Bv = proj[m * 64 + 32 + n];
        float Cv = proj[m * 64 + 48 + n];
        float dA = __expf(dtv * Ac);
        h = fmaf(dA, h, dtv * xiv * Bv);
        float p = h * Cv;
        p += __shfl_xor_sync(0xffffffffu, p, 8);
        p += __shfl_xor_sync(0xffffffffu, p, 4);
        p += __shfl_xor_sync(0xffffffffu, p, 2);
        p += __shfl_xor_sync(0xffffffffu, p, 1);
        if (n == 0) {
            float zv = xz[(long long)m * 2048 + DIc + d];
            float yv = p + dsk * xiv;
            planewrite(yv * zv / (1.0f + __expf(-zv)), yct,
                       (long long)m * 2048 + ((d >> 6) * 128 + (d & 63)));
        }
    }
}

__global__ void lens_k(const int* __restrict__ fl, float* __restrict__ out, int out_size) {
    int b = threadIdx.x;
    if (b < Bsz && out_size >= M4 * Vv + Bsz) {
        int v = fl[b] >> 2;
        if (v < 1) v = 1;
        out[M4 * Vv + b] = (float)v;
    }
}

// ---------------- launcher ----------------
extern "C" void kernel_launch(void* const* d_in, const int* in_sizes, int n_in,
                              void* d_out, int out_size) {
    (void)in_sizes; (void)n_in;
    const float* feats    = (const float*)d_in[0];
    const int*   feat_lens= (const int*)  d_in[1];
    const float* conv1_w  = (const float*)d_in[2];
    const float* conv1_b  = (const float*)d_in[3];
    const float* conv2_w  = (const float*)d_in[4];
    const float* conv2_b  = (const float*)d_in[5];
    const float* norm_w   = (const float*)d_in[6];
    const float* in_proj  = (const float*)d_in[7];
    const float* dwc_w    = (const float*)d_in[8];
    const float* dwc_b    = (const float*)d_in[9];
    const float* x_proj   = (const float*)d_in[10];
    const float* dt_w     = (const float*)d_in[11];
    const float* dt_b     = (const float*)d_in[12];
    const float* A_log    = (const float*)d_in[13];
    const float* D_skip   = (const float*)d_in[14];
    const float* out_proj = (const float*)d_in[15];
    const float* head_w   = (const float*)d_in[16];
    const float* head_b   = (const float*)d_in[17];
    float* out = (float*)d_out;

    void* sym = nullptr;
    cudaGetSymbolAddress(&sym, g_buf);
    float* gb = (float*)sym;
    __nv_bfloat16* featspA = (__nv_bfloat16*)(gb + OFF_FEATSPA);
    __nv_bfloat16* out1p   = (__nv_bfloat16*)(gb + OFF_OUT1P);
    __nv_bfloat16* xn_t    = (__nv_bfloat16*)(gb + OFF_XN_T);
    float*         xz      = gb + OFF_XZ;
    float*         xi      = gb + OFF_XI;
    __nv_bfloat16* xi_t    = (__nv_bfloat16*)(gb + OFF_XI_T);
    float*         dtbuf   = gb + OFF_DT;
    float*         proj    = gb + OFF_PROJ;
    __nv_bfloat16* proj_t  = (__nv_bfloat16*)(gb + OFF_PROJ_T);
    __nv_bfloat16* yc_t    = (__nv_bfloat16*)(gb + OFF_YC_T);
    float*         x       = gb + OFF_X;
    __nv_bfloat16* x_t     = (__nv_bfloat16*)(gb + OFF_X_T);
    __nv_bfloat16* w1t     = (__nv_bfloat16*)(gb + OFF_W1T);
    __nv_bfloat16* w2t     = (__nv_bfloat16*)(gb + OFF_W2T);
    __nv_bfloat16* inW     = (__nv_bfloat16*)(gb + OFF_INW);
    __nv_bfloat16* xW      = (__nv_bfloat16*)(gb + OFF_XW);
    __nv_bfloat16* dtW     = (__nv_bfloat16*)(gb + OFF_DTW);
    __nv_bfloat16* outW    = (__nv_bfloat16*)(gb + OFF_OUTW);
    __nv_bfloat16* headW   = (__nv_bfloat16*)(gb + OFF_HEADW);
    float*         xpart   = gb + OFF_XPART;

    const int SMB = 1024 + 2 * 32768;   // 66560 -> 3 CTAs/SM
    cudaFuncSetAttribute(bgemm_k, cudaFuncAttributeMaxDynamicSharedMemorySize, SMB);
    const int BIGK = 1 << 28;

    // prep + weight conversion
    wconv1_k<<<(512 * 512 + 255) / 256, 256>>>(conv1_w, w1t);
    wconv2_k<<<(512 * 3072 + 255) / 256, 256>>>(conv2_w, w2t);
    conv1a_k<<<(M2 * 512 + 255) / 256, 256>>>(feats, featspA);

    // conv1: M=6400, N=512, K=256 -> out1p planes (skip pad row t=0)
    bgemm_k<<<dim3(8, 100), 256, SMB>>>(
        featspA, w1t, conv1_b, out1p + 1024,
        4, 512,
        M2, 0, 512,
        800, 802LL * 1024, 1024,
        1, 1, 0, BIGK, 0);

    zero_out1p_k<<<(Bsz * 2 * 1024 + 255) / 256, 256>>>(out1p);

    // conv2: M=3200, N=512, K=1536 -> x f32
    bgemm_k<<<dim3(8, 50), 256, SMB>>>(
        out1p, w2t, conv2_b, x,
        24, 3072,
        400, 802LL * 1024, 2048,
        M4, 0, 512,
        1, 0, 0, BIGK, 0);

    for (int l = 0; l < Ll; l++)
        layer_wconv_k<<<(S0E + S1E + S2E + S3E + 255) / 256, 256>>>(
            in_proj + (size_t)l * Dm * 2048, x_proj + (size_t)l * DIc * 64,
            dt_w + (size_t)l * 32 * DIc, out_proj + (size_t)l * DIc * Dm,
            inW + (size_t)l * S0E, xW + (size_t)l * S1E,
            dtW + (size_t)l * S2E, outW + (size_t)l * S3E);
    whead_k<<<(1024 * 1024 + 255) / 256, 256>>>(head_w, headW);

    for (int l = 0; l < Ll; l++) {
        rmsnorm_t_k<<<M4, 128>>>(x, norm_w + l * Dm, xn_t);

        // xz = xn @ in_proj  (3200x2048, K=512)
        bgemm_k<<<dim3(32, 50), 256, SMB>>>(
            xn_t, inW + (size_t)l * S0E, nullptr, xz,
            8, 1024,
            M4, 0, 1024,
            M4, 0, 2048,
            0, 0, 0, BIGK, 0);

        dwconv_k<<<(M4 * DIc + 255) / 256, 256>>>(
            xz, dwc_w + l * DIc * 4, dwc_b + l * DIc, xi, xi_t);

        // proj partials = xi @ x_proj  (3200x64, K=1024, split-K x4)
        bgemm_k<<<dim3(1, 50, 4), 256, SMB>>>(
            xi_t, xW + (size_t)l * S1E, nullptr, xpart,
            16, 2048,
            M4, 0, 2048,
            M4, 0, 64,
            0, 0, 0, 4, 204800);

        xcomb_k<<<(M4 * 128 + 255) / 256, 256>>>(xpart, proj, proj_t);

        // dt = softplus(proj @ dt_w + dt_b)  (3200x1024, K=64)
        bgemm_k<<<dim3(16, 50), 256, SMB>>>(
            proj_t, dtW + (size_t)l * S2E, dt_b + l * DIc, dtbuf,
            1, 128,
            M4, 0, 128,
            M4, 0, 1024,
            2, 0, 0, BIGK, 0);

        scan_k<<<512, 256>>>(dtbuf, xi, proj, xz,
                             A_log + (size_t)l * DIc * Nst, D_skip + l * DIc, yc_t);

        // x += yc @ out_proj  (3200x512, K=1024)
        bgemm_k<<<dim3(8, 50), 256, SMB>>>(
            yc_t, outW + (size_t)l * S3E, nullptr, x,
            16, 2048,
            M4, 0, 2048,
            M4, 0, 512,
            0, 0, 1, BIGK, 0);
    }

    x_t_k<<<(M4 * Dm + 255) / 256, 256>>>(x, x_t);

    // logits = x @ head_w + head_b  (3200x1024, K=512)
    bgemm_k<<<dim3(16, 50), 256, SMB>>>(
        x_t, headW, head_b, out,
        8, 1024,
        M4, 0, 1024,
        M4, 0, 1024,
        0, 0, 0, BIGK, 0);

    lens_k<<<1, 32>>>(feat_lens, out, out_size);
}

// round 15
// speedup vs baseline: 1.2501x; 1.0017x over previous
#include <cuda_runtime.h>
#include <cuda_bf16.h>
#include <math.h>
#include <stdint.h>

// ---------------- problem constants ----------------
#define Bsz   8
#define Tfull 1600
#define Dm    512
#define DIc   1024
#define Nst   16
#define Ll    8
#define Vv    1024
#define T4    400
#define M4    (Bsz*T4)    // 3200
#define M2    (Bsz*800)   // 6400

// ---------------- scratch (single __device__ array, ~183MB) ----------------
__device__ float g_buf[45801472];

// offsets in floats
#define OFF_FEATSPA  0
#define OFF_OUT1P    1638400
#define OFF_XN_T     4923392
#define OFF_XZ       6561792
#define OFF_XI       13115392
#define OFF_XI_T     16392192
#define OFF_DT       19668992
#define OFF_PROJ     22945792
#define OFF_PROJ_T   23150592
#define OFF_YC_T     23355392
#define OFF_X        26632192
#define OFF_X_T      28270592
#define OFF_W1T      29908992
#define OFF_W2T      30040064
#define OFF_INW      30826496
#define OFF_XW       39215104
#define OFF_DTW      39739392
#define OFF_OUTW     40263680
#define OFF_HEADW    44457984
#define OFF_XPART    44982272

// layer weight sizes in bf16 elements
#define S0E (2048*1024)
#define S1E (64*2048)
#define S2E (1024*128)
#define S3E (512*2048)

// ---------------- math helpers ----------------
__device__ __forceinline__ float gelu_f(float x) {
    return 0.5f * x * (1.0f + erff(x * 0.70710678118654752f));
}
__device__ __forceinline__ float softplus_f(float x) {
    return fmaxf(x, 0.0f) + log1pf(expf(-fabsf(x)));
}
// value for plane p (0 = hi, 1 = md)
__device__ __forceinline__ __nv_bfloat16 planeval(float v, int plane) {
    __nv_bfloat16 h = __float2bfloat16(v);
    if (plane == 0) return h;
    return __float2bfloat16(v - __bfloat162float(h));
}
// write hi at buf[base], md at buf[base+64]
__device__ __forceinline__ void planewrite(float v, __nv_bfloat16* buf, long long base) {
    __nv_bfloat16 h = __float2bfloat16(v);
    buf[base] = h;
    buf[base + 64] = __float2bfloat16(v - __bfloat162float(h));
}

// ---------------- PTX helpers ----------------
__device__ __forceinline__ uint32_t smem_u32(const void* p) {
    uint32_t a;
    asm("{ .reg .u64 t; cvta.to.shared.u64 t, %1; cvt.u32.u64 %0, t; }" : "=r"(a) : "l"(p));
    return a;
}
#define SW128(x) ((x) ^ (((x) >> 3) & 0x70))
__device__ __forceinline__ void cp16(uint32_t dst, const void* src) {
    asm volatile("cp.async.cg.shared.global [%0], [%1], 16;" :: "r"(dst), "l"(src) : "memory");
}
__device__ __forceinline__ void ldsm4(uint32_t* r, uint32_t addr) {
    asm volatile("ldmatrix.sync.aligned.m8n8.x4.shared.b16 {%0,%1,%2,%3}, [%4];"
                 : "=r"(r[0]), "=r"(r[1]), "=r"(r[2]), "=r"(r[3]) : "r"(addr));
}
__device__ __forceinline__ void mma16(float* c, const uint32_t* a, const uint32_t* b) {
    asm volatile(
        "mma.sync.aligned.m16n8k16.row.col.f32.bf16.bf16.f32 "
        "{%0,%1,%2,%3},{%4,%5,%6,%7},{%8,%9},{%0,%1,%2,%3};"
        : "+f"(c[0]), "+f"(c[1]), "+f"(c[2]), "+f"(c[3])
        : "r"(a[0]), "r"(a[1]), "r"(a[2]), "r"(a[3]), "r"(b[0]), "r"(b[1]));
}

// ---------------- bf16 tensor-core GEMM (hi/md planes, BM=64, BN=64) ----------
// Data per row: K/64 blocks of 256B: [128B hi | 128B md]. Row pitch in ELEMENTS.
// Per chunk: mma(ahi,bhi) + mma(ahi,bmd) + mma(amd,bhi).  NC = K/64.
// 2-stage pipeline, 3 CTAs/SM. Split-K via blockIdx.z (f32 out at C + z*zoff).
// Swizzle factorization: for trow*128 + low (low<128),
//   SW128 = trow*128 + (low ^ swb), swb = ((trow*128)>>3)&0x70 (thread-const).
__global__ void __launch_bounds__(256, 3) bgemm_k(
        const __nv_bfloat16* __restrict__ A,
        const __nv_bfloat16* __restrict__ Bw,
        const float* __restrict__ bias,
        void* __restrict__ Cv,
        int NC, int bpitch,
        int a_rpb, long long a_bs, int a_rs,
        int o_rpb, long long o_bs, int o_rs,
        int act, int outmode, int accum,
        int ksplit, long long zoff) {
    extern __shared__ char smem_raw[];
    uint32_t sb = (smem_u32(smem_raw) + 1023) & ~1023u;
    const uint32_t STG = 32768u;   // A hi 8K | A md 8K | B hi 8K | B md 8K

    int tid = threadIdx.x, wid = tid >> 5, lane = tid & 31;
    int bm = blockIdx.y * 64, bn = blockIdx.x * 64;
    int c0 = blockIdx.z * ksplit;
    int c1 = min(NC, c0 + ksplit);

    // loader precompute: base pointer + int byte-deltas (register-slim)
    const char* aptr0; int adel[4]; uint32_t adst[4];
    const char* bptr0; int bdel[4]; uint32_t bdst[4];
    {
        long long aref = 0;
#pragma unroll
        for (int i = 0; i < 4; i++) {
            int G = tid + i * 256;          // 0..1023
            int row = G >> 4, sub = G & 15;
            int gm = bm + row;
            long long off = 2 * ((long long)(gm / a_rpb) * a_bs + (long long)(gm % a_rpb) * a_rs)
                          + sub * 16;
            if (i == 0) { aref = off; aptr0 = (const char*)A + off; }
            adel[i] = (int)(off - aref);
            adst[i] = (uint32_t)((sub >> 3) * 8192) + SW128((uint32_t)(row * 128 + (sub & 7) * 16));
        }
        long long bref = 0;
#pragma unroll
        for (int i = 0; i < 4; i++) {
            int G = tid + i * 256;
            int row = G >> 4, sub = G & 15;
            long long off = 2LL * (bn + row) * bpitch + sub * 16;
            if (i == 0) { bref = off; bptr0 = (const char*)Bw + off; }
            bdel[i] = (int)(off - bref);
            bdst[i] = 16384u + (uint32_t)((sub >> 3) * 8192) + SW128((uint32_t)(row * 128 + (sub & 7) * 16));
        }
    }

    auto issue = [&](int c) {
        uint32_t base = sb + (uint32_t)(c & 1) * STG;
        const char* ap = aptr0 + (long long)c * 256;
        const char* bp = bptr0 + (long long)c * 256;
#pragma unroll
        for (int i = 0; i < 4; i++) cp16(base + adst[i], ap + adel[i]);
#pragma unroll
        for (int i = 0; i < 4; i++) cp16(base + bdst[i], bp + bdel[i]);
        asm volatile("cp.async.commit_group;" ::: "memory");
    };

    // warp tiling: 2 m-strips x 4 n-strips; warp tile 32m x 16n
    int wm = wid & 1, wn = wid >> 1;
    float acc[2][2][4];
#pragma unroll
    for (int i = 0; i < 2; i++)
#pragma unroll
        for (int j = 0; j < 2; j++)
#pragma unroll
            for (int r = 0; r < 4; r++) acc[i][j][r] = 0.0f;

    // ldsm address components (factored swizzle):
    //   A row i: trow = wm*32 + i*16 + ((lane&7) + ((lane>>3)&1)*8)
    //   addr = base + trow*128 + ((ks<<5) ^ atsw)   with atsw = tcol ^ swb(trow)
    uint32_t arp[2], atsw[2];
    {
        int a_trow = (lane & 7) + ((lane >> 3) & 1) * 8;
        uint32_t a_tcol = (uint32_t)((lane >> 4) * 16);
#pragma unroll
        for (int i = 0; i < 2; i++) {
            uint32_t rp = (uint32_t)((wm * 32 + i * 16 + a_trow) * 128);
            arp[i] = rp;
            atsw[i] = a_tcol ^ ((rp >> 3) & 0x70);
        }
    }
    uint32_t brp, btsw;
    {
        int b_trow = ((lane >> 4) << 3) + (lane & 7);
        uint32_t b_tcol = (uint32_t)(((lane >> 3) & 1) * 16);
        uint32_t rp = (uint32_t)((wn * 16 + b_trow) * 128);
        brp = rp;
        btsw = b_tcol ^ ((rp >> 3) & 0x70);
    }

    issue(c0);
    if (c0 + 1 < c1) issue(c0 + 1);

    for (int c = c0; c < c1; c++) {
        if (c + 1 < c1) asm volatile("cp.async.wait_group 1;" ::: "memory");
        else            asm volatile("cp.async.wait_group 0;" ::: "memory");
        __syncthreads();

        uint32_t base = sb + (uint32_t)(c & 1) * STG;
        uint32_t abase0 = base + arp[0];
        uint32_t abase1 = base + arp[1];
        uint32_t bbase  = base + 16384u + brp;
#pragma unroll
        for (int ks = 0; ks < 4; ks++) {
            uint32_t klo = (uint32_t)(ks << 5);
            uint32_t ahi[2][4], amd[2][4];
            {
                uint32_t lo0 = klo ^ atsw[0];
                ldsm4(ahi[0], abase0 + lo0);
                ldsm4(amd[0], abase0 + 8192u + lo0);
                uint32_t lo1 = klo ^ atsw[1];
                ldsm4(ahi[1], abase1 + lo1);
                ldsm4(amd[1], abase1 + 8192u + lo1);
            }
            uint32_t bhi[2][2], bmd[2][2];
            {
                uint32_t lob = klo ^ btsw;
                uint32_t r[4];
                ldsm4(r, bbase + lob);
                bhi[0][0] = r[0]; bhi[0][1] = r[1]; bhi[1][0] = r[2]; bhi[1][1] = r[3];
                ldsm4(r, bbase + 8192u + lob);
                bmd[0][0] = r[0]; bmd[0][1] = r[1]; bmd[1][0] = r[2]; bmd[1][1] = r[3];
            }
#pragma unroll
            for (int i = 0; i < 2; i++)
#pragma unroll
                for (int j = 0; j < 2; j++) {
                    mma16(acc[i][j], ahi[i], bhi[j]);
                    mma16(acc[i][j], ahi[i], bmd[j]);
                    mma16(acc[i][j], amd[i], bhi[j]);
                }
        }

        if (c + 2 < c1) {
            __syncthreads();   // all warps done reading stage (c&1) before refill
            issue(c + 2);
        }
    }

    // ---------------- epilogue ----------------
    float* Cz = (float*)Cv + blockIdx.z * zoff;
#pragma unroll
    for (int i = 0; i < 2; i++) {
#pragma unroll
        for (int h = 0; h < 2; h++) {
            int gm = bm + wm * 32 + i * 16 + (lane >> 2) + h * 8;
            long long orow = (long long)(gm / o_rpb) * o_bs + (long long)(gm % o_rpb) * o_rs;
#pragma unroll
            for (int j = 0; j < 2; j++) {
                int gn = bn + wn * 16 + j * 8 + (lane & 3) * 2;
#pragma unroll
                for (int e = 0; e < 2; e++) {
                    float v = acc[i][j][h * 2 + e];
                    int gne = gn + e;
                    if (bias) v += bias[gne];
                    if (act == 1) v = gelu_f(v);
                    else if (act == 2) v = softplus_f(v);
                    if (outmode == 0) {
                        long long o = orow + gne;
                        if (accum) v += Cz[o];
                        Cz[o] = v;
                    } else {
                        __nv_bfloat16* C = (__nv_bfloat16*)Cv;
                        long long o = orow + ((gne >> 6) * 128 + (gne & 63));
                        planewrite(v, C, o);
                    }
                }
            }
        }
    }
}

// ---------------- converters / prep ----------------
__global__ void conv1a_k(const float* __restrict__ feats, __nv_bfloat16* __restrict__ fa) {
    int i = blockIdx.x * 256 + threadIdx.x;
    if (i >= M2 * 512) return;
    int m = i >> 9, e = i & 511;
    int sub = e & 127, plane = sub >> 6;
    int k = (e >> 7) * 64 + (sub & 63);
    float val = 0.0f;
    if (k < 240) {
        int tap = k / 80, c = k % 80;
        int b = m / 800, p = m % 800;
        int tin = 2 * p - 1 + tap;
        if (tin >= 0 && tin < 1600)
            val = feats[((long long)b * 1600 + tin) * 80 + c];
    }
    fa[i] = planeval(val, plane);
}

__global__ void zero_out1p_k(__nv_bfloat16* __restrict__ op) {
    int i = blockIdx.x * 256 + threadIdx.x;
    if (i < Bsz * 2 * 1024) {
        int e = i & 1023; int r = i >> 10;
        int b = r >> 1; int t = (r & 1) ? 801 : 0;
        op[(long long)(b * 802 + t) * 1024 + e] = __float2bfloat16(0.0f);
    }
}

__global__ void wconv1_k(const float* __restrict__ w, __nv_bfloat16* __restrict__ wt) {
    int i = blockIdx.x * 256 + threadIdx.x;
    if (i >= 512 * 512) return;
    int n = i >> 9, e = i & 511;
    int sub = e & 127, plane = sub >> 6;
    int k = (e >> 7) * 64 + (sub & 63);
    float val = 0.0f;
    if (k < 240) val = w[n * 240 + (k % 80) * 3 + (k / 80)];
    wt[i] = planeval(val, plane);
}
__global__ void wconv2_k(const float* __restrict__ w, __nv_bfloat16* __restrict__ wt) {
    int i = blockIdx.x * 256 + threadIdx.x;
    if (i >= 512 * 3072) return;
    int n = i / 3072, e = i % 3072;
    int sub = e & 127, plane = sub >> 6;
    int k = (e >> 7) * 64 + (sub & 63);
    int tap = k / 512, c = k & 511;
    wt[i] = planeval(w[n * 1536 + c * 3 + tap], plane);
}

__global__ void layer_wconv_k(const float* __restrict__ inw, const float* __restrict__ xw,
                              const float* __restrict__ dtw, const float* __restrict__ outw,
                              __nv_bfloat16* __restrict__ o_in, __nv_bfloat16* __restrict__ o_x,
                              __nv_bfloat16* __restrict__ o_dt, __nv_bfloat16* __restrict__ o_out) {
    int i = blockIdx.x * 256 + threadIdx.x;
    if (i < S0E) {
        int n = i >> 10, e = i & 1023;
        int sub = e & 127, plane = sub >> 6;
        int k = (e >> 7) * 64 + (sub & 63);
        o_in[i] = planeval(inw[k * 2048 + n], plane);
        return;
    }
    i -= S0E;
    if (i < S1E) {
        int n = i >> 11, e = i & 2047;
        int sub = e & 127, plane = sub >> 6;
        int k = (e >> 7) * 64 + (sub & 63);
        o_x[i] = planeval(xw[k * 64 + n], plane);
        return;
    }
    i -= S1E;
    if (i < S2E) {
        int n = i >> 7, e = i & 127;
        int plane = e >> 6, k = e & 63;
        float val = (k < 32) ? dtw[k * 1024 + n] : 0.0f;
        o_dt[i] = planeval(val, plane);
        return;
    }
    i -= S2E;
    if (i < S3E) {
        int n = i >> 11, e = i & 2047;
        int sub = e & 127, plane = sub >> 6;
        int k = (e >> 7) * 64 + (sub & 63);
        o_out[i] = planeval(outw[k * 512 + n], plane);
    }
}

__global__ void whead_k(const float* __restrict__ w, __nv_bfloat16* __restrict__ wt) {
    int i = blockIdx.x * 256 + threadIdx.x;
    if (i >= 1024 * 1024) return;
    int n = i >> 10, e = i & 1023;
    int sub = e & 127, plane = sub >> 6;
    int k = (e >> 7) * 64 + (sub & 63);
    wt[i] = planeval(w[k * 1024 + n], plane);
}

__global__ void xcomb_k(const float* __restrict__ parts, float* __restrict__ proj,
                        __nv_bfloat16* __restrict__ pt) {
    int i = blockIdx.x * 256 + threadIdx.x;
    if (i >= M4 * 128) return;
    int m = i >> 7, e = i & 127;
    if (e < 64) {
        int o = m * 64 + e;
        proj[o] = parts[o] + parts[204800 + o] + parts[2 * 204800 + o] + parts[3 * 204800 + o];
    }
    int plane = e >> 6, k = e & 63;
    float v = 0.0f;
    if (k < 32) {
        int o = m * 64 + k;
        v = parts[o] + parts[204800 + o] + parts[2 * 204800 + o] + parts[3 * 204800 + o];
    }
    pt[i] = planeval(v, plane);
}

__global__ void x_t_k(const float* __restrict__ x, __nv_bfloat16* __restrict__ xt) {
    int i = blockIdx.x * 256 + threadIdx.x;
    if (i >= M4 * Dm) return;
    int m = i >> 9, c = i & 511;
    planewrite(x[i], xt, (long long)m * 1024 + ((c >> 6) * 128 + (c & 63)));
}

// ---------------- RMSNorm -> planes ----------------
__global__ void rmsnorm_t_k(const float* __restrict__ x, const float* __restrict__ w,
                            __nv_bfloat16* __restrict__ xnt) {
    int row = blockIdx.x;
    int tid = threadIdx.x;   // 128
    const float* xr = x + (long long)row * Dm;
    float v[4];
    float s = 0.0f;
#pragma unroll
    for (int i = 0; i < 4; i++) { v[i] = xr[tid + 128 * i]; s += v[i] * v[i]; }
#pragma unroll
    for (int o = 16; o; o >>= 1) s += __shfl_xor_sync(0xffffffffu, s, o);
    __shared__ float ws[4];
    if ((tid & 31) == 0) ws[tid >> 5] = s;
    __syncthreads();
    float tot = ws[0] + ws[1] + ws[2] + ws[3];
    float rs = rsqrtf(tot * (1.0f / Dm) + 1e-5f);
#pragma unroll
    for (int i = 0; i < 4; i++) {
        int c = tid + 128 * i;
        planewrite(v[i] * rs * w[c], xnt, (long long)row * 1024 + ((c >> 6) * 128 + (c & 63)));
    }
}

// ---------------- depthwise causal conv (K=4) + SiLU ----------------
__global__ void dwconv_k(const float* __restrict__ xz, const float* __restrict__ cw,
                         const float* __restrict__ cb, float* __restrict__ xi,
                         __nv_bfloat16* __restrict__ xit) {
    int idx = blockIdx.x * 256 + threadIdx.x;
    if (idx >= M4 * DIc) return;
    int d = idx & (DIc - 1);
    int m = idx >> 10;
    int t = m % T4;
    float w0 = cw[d * 4 + 0], w1 = cw[d * 4 + 1], w2 = cw[d * 4 + 2], w3 = cw[d * 4 + 3];
    const float* base = xz + (long long)m * 2048 + d;
    float acc = w3 * base[0];
    if (t >= 1) acc = fmaf(w2, base[-2048], acc);
    if (t >= 2) acc = fmaf(w1, base[-2 * 2048], acc);
    if (t >= 3) acc = fmaf(w0, base[-3 * 2048], acc);
    acc += cb[d];
    float s = acc / (1.0f + expf(-acc));
    xi[idx] = s;
    planewrite(s, xit, (long long)m * 2048 + ((d >> 6) * 128 + (d & 63)));
}

// ---------------- selective scan -> yc planes ----------------
__global__ void scan_k(const float* __restrict__ dt, const float* __restrict__ xi,
                       const float* __restrict__ proj, const float* __restrict__ xz,
                       const float* __restrict__ A_log, const float* __restrict__ dskip,
                       __nv_bfloat16* __restrict__ yct) {
    int w = (blockIdx.x * blockDim.x + threadIdx.x) >> 5;
    int lane = threadIdx.x & 31;
    int b = w >> 9;
    int dp = w & 511;
    int d = dp * 2 + (lane >> 4);
    int n = lane & 15;
    float Ac = -expf(A_log[d * Nst + n]);
    float dsk = dskip[d];
    float h = 0.0f;
    int mb = b * T4;
    for (int t = 0; t < T4; t++) {
        int m = mb + t;
        float dtv = dt[m * DIc + d];
        float xiv = xi[m * DIc + d];
        float Bv = proj[m * 64 + 32 + n];
        float Cv = proj[m * 64 + 48 + n];
        float dA = __expf(dtv * Ac);
        h = fmaf(dA, h, dtv * xiv * Bv);
        float p = h * Cv;
        p += __shfl_xor_sync(0xffffffffu, p, 8);
        p += __shfl_xor_sync(0xffffffffu, p, 4);
        p += __shfl_xor_sync(0xffffffffu, p, 2);
        p += __shfl_xor_sync(0xffffffffu, p, 1);
        if (n == 0) {
            float zv = xz[(long long)m * 2048 + DIc + d];
            float yv = p + dsk * xiv;
            planewrite(yv * zv / (1.0f + __expf(-zv)), yct,
                       (long long)m * 2048 + ((d >> 6) * 128 + (d & 63)));
        }
    }
}

__global__ void lens_k(const int* __restrict__ fl, float* __restrict__ out, int out_size) {
    int b = threadIdx.x;
    if (b < Bsz && out_size >= M4 * Vv + Bsz) {
        int v = fl[b] >> 2;
        if (v < 1) v = 1;
        out[M4 * Vv + b] = (float)v;
    }
}

// ---------------- launcher ----------------
extern "C" void kernel_launch(void* const* d_in, const int* in_sizes, int n_in,
                              void* d_out, int out_size) {
    (void)in_sizes; (void)n_in;
    const float* feats    = (const float*)d_in[0];
    const int*   feat_lens= (const int*)  d_in[1];
    const float* conv1_w  = (const float*)d_in[2];
    const float* conv1_b  = (const float*)d_in[3];
    const float* conv2_w  = (const float*)d_in[4];
    const float* conv2_b  = (const float*)d_in[5];
    const float* norm_w   = (const float*)d_in[6];
    const float* in_proj  = (const float*)d_in[7];
    const float* dwc_w    = (const float*)d_in[8];
    const float* dwc_b    = (const float*)d_in[9];
    const float* x_proj   = (const float*)d_in[10];
    const float* dt_w     = (const float*)d_in[11];
    const float* dt_b     = (const float*)d_in[12];
    const float* A_log    = (const float*)d_in[13];
    const float* D_skip   = (const float*)d_in[14];
    const float* out_proj = (const float*)d_in[15];
    const float* head_w   = (const float*)d_in[16];
    const float* head_b   = (const float*)d_in[17];
    float* out = (float*)d_out;

    void* sym = nullptr;
    cudaGetSymbolAddress(&sym, g_buf);
    float* gb = (float*)sym;
    __nv_bfloat16* featspA = (__nv_bfloat16*)(gb + OFF_FEATSPA);
    __nv_bfloat16* out1p   = (__nv_bfloat16*)(gb + OFF_OUT1P);
    __nv_bfloat16* xn_t    = (__nv_bfloat16*)(gb + OFF_XN_T);
    float*         xz      = gb + OFF_XZ;
    float*         xi      = gb + OFF_XI;
    __nv_bfloat16* xi_t    = (__nv_bfloat16*)(gb + OFF_XI_T);
    float*         dtbuf   = gb + OFF_DT;
    float*         proj    = gb + OFF_PROJ;
    __nv_bfloat16* proj_t  = (__nv_bfloat16*)(gb + OFF_PROJ_T);
    __nv_bfloat16* yc_t    = (__nv_bfloat16*)(gb + OFF_YC_T);
    float*         x       = gb + OFF_X;
    __nv_bfloat16* x_t     = (__nv_bfloat16*)(gb + OFF_X_T);
    __nv_bfloat16* w1t     = (__nv_bfloat16*)(gb + OFF_W1T);
    __nv_bfloat16* w2t     = (__nv_bfloat16*)(gb + OFF_W2T);
    __nv_bfloat16* inW     = (__nv_bfloat16*)(gb + OFF_INW);
    __nv_bfloat16* xW      = (__nv_bfloat16*)(gb + OFF_XW);
    __nv_bfloat16* dtW     = (__nv_bfloat16*)(gb + OFF_DTW);
    __nv_bfloat16* outW    = (__nv_bfloat16*)(gb + OFF_OUTW);
    __nv_bfloat16* headW   = (__nv_bfloat16*)(gb + OFF_HEADW);
    float*         xpart   = gb + OFF_XPART;

    const int SMB = 1024 + 2 * 32768;   // 66560 -> 3 CTAs/SM
    cudaFuncSetAttribute(bgemm_k, cudaFuncAttributeMaxDynamicSharedMemorySize, SMB);
    const int BIGK = 1 << 28;

    // prep + weight conversion
    wconv1_k<<<(512 * 512 + 255) / 256, 256>>>(conv1_w, w1t);
    wconv2_k<<<(512 * 3072 + 255) / 256, 256>>>(conv2_w, w2t);
    conv1a_k<<<(M2 * 512 + 255) / 256, 256>>>(feats, featspA);

    // conv1: M=6400, N=512, K=256 -> out1p planes (skip pad row t=0)
    bgemm_k<<<dim3(8, 100), 256, SMB>>>(
        featspA, w1t, conv1_b, out1p + 1024,
        4, 512,
        M2, 0, 512,
        800, 802LL * 1024, 1024,
        1, 1, 0, BIGK, 0);

    zero_out1p_k<<<(Bsz * 2 * 1024 + 255) / 256, 256>>>(out1p);

    // conv2: M=3200, N=512, K=1536 -> x f32
    bgemm_k<<<dim3(8, 50), 256, SMB>>>(
        out1p, w2t, conv2_b, x,
        24, 3072,
        400, 802LL * 1024, 2048,
        M4, 0, 512,
        1, 0, 0, BIGK, 0);

    for (int l = 0; l < Ll; l++)
        layer_wconv_k<<<(S0E + S1E + S2E + S3E + 255) / 256, 256>>>(
            in_proj + (size_t)l * Dm * 2048, x_proj + (size_t)l * DIc * 64,
            dt_w + (size_t)l * 32 * DIc, out_proj + (size_t)l * DIc * Dm,
            inW + (size_t)l * S0E, xW + (size_t)l * S1E,
            dtW + (size_t)l * S2E, outW + (size_t)l * S3E);
    whead_k<<<(1024 * 1024 + 255) / 256, 256>>>(head_w, headW);

    for (int l = 0; l < Ll; l++) {
        rmsnorm_t_k<<<M4, 128>>>(x, norm_w + l * Dm, xn_t);

        // xz = xn @ in_proj  (3200x2048, K=512)
        bgemm_k<<<dim3(32, 50), 256, SMB>>>(
            xn_t, inW + (size_t)l * S0E, nullptr, xz,
            8, 1024,
            M4, 0, 1024,
            M4, 0, 2048,
            0, 0, 0, BIGK, 0);

        dwconv_k<<<(M4 * DIc + 255) / 256, 256>>>(
            xz, dwc_w + l * DIc * 4, dwc_b + l * DIc, xi, xi_t);

        // proj partials = xi @ x_proj  (3200x64, K=1024, split-K x4)
        bgemm_k<<<dim3(1, 50, 4), 256, SMB>>>(
            xi_t, xW + (size_t)l * S1E, nullptr, xpart,
            16, 2048,
            M4, 0, 2048,
            M4, 0, 64,
            0, 0, 0, 4, 204800);

        xcomb_k<<<(M4 * 128 + 255) / 256, 256>>>(xpart, proj, proj_t);

        // dt = softplus(proj @ dt_w + dt_b)  (3200x1024, K=64)
        bgemm_k<<<dim3(16, 50), 256, SMB>>>(
            proj_t, dtW + (size_t)l * S2E, dt_b + l * DIc, dtbuf,
            1, 128,
            M4, 0, 128,
            M4, 0, 1024,
            2, 0, 0, BIGK, 0);

        scan_k<<<512, 256>>>(dtbuf, xi, proj, xz,
                             A_log + (size_t)l * DIc * Nst, D_skip + l * DIc, yc_t);

        // x += yc @ out_proj  (3200x512, K=1024)
        bgemm_k<<<dim3(8, 50), 256, SMB>>>(
            yc_t, outW + (size_t)l * S3E, nullptr, x,
            16, 2048,
            M4, 0, 2048,
            M4, 0, 512,
            0, 0, 1, BIGK, 0);
    }

    x_t_k<<<(M4 * Dm + 255) / 256, 256>>>(x, x_t);

    // logits = x @ head_w + head_b  (3200x1024, K=512)
    bgemm_k<<<dim3(16, 50), 256, SMB>>>(
        x_t, headW, head_b, out,
        8, 1024,
        M4, 0, 1024,
        M4, 0, 1024,
        0, 0, 0, BIGK, 0);

    lens_k<<<1, 32>>>(feat_lens, out, out_size);
}

// round 16
// speedup vs baseline: 1.3634x; 1.0906x over previous
#include <cuda_runtime.h>
#include <cuda_bf16.h>
#include <math.h>
#include <stdint.h>

// ---------------- problem constants ----------------
#define Bsz   8
#define Tfull 1600
#define Dm    512
#define DIc   1024
#define Nst   16
#define Ll    8
#define Vv    1024
#define T4    400
#define M4    (Bsz*T4)    // 3200
#define M2    (Bsz*800)   // 6400

// ---------------- scratch (single __device__ array, ~183MB) ----------------
__device__ float g_buf[45801472];

// offsets in floats
#define OFF_FEATSPA  0
#define OFF_OUT1P    1638400
#define OFF_XN_T     4923392
#define OFF_XZ       6561792
#define OFF_XI       13115392
#define OFF_XI_T     16392192
#define OFF_DT       19668992
#define OFF_PROJ     22945792
#define OFF_PROJ_T   23150592
#define OFF_YC_T     23355392
#define OFF_X        26632192
#define OFF_X_T      28270592
#define OFF_W1T      29908992
#define OFF_W2T      30040064
#define OFF_INW      30826496
#define OFF_XW       39215104
#define OFF_DTW      39739392
#define OFF_OUTW     40263680
#define OFF_HEADW    44457984
#define OFF_XPART    44982272

// layer weight sizes in bf16 elements
#define S0E (2048*1024)
#define S1E (64*2048)
#define S2E (1024*128)
#define S3E (512*2048)
#define SLAYER (S0E+S1E+S2E+S3E)   // 3407872

// prep_all region sizes
#define R_W1   (512*512)
#define R_W2   (512*3072)
#define R_C1A  (M2*512)
#define R_ZP   (Bsz*2*1024)
#define R_HEAD (1024*1024)
#define R_LAY  (Ll*SLAYER)
#define R_TOT  (R_W1+R_W2+R_C1A+R_ZP+R_HEAD+R_LAY)

// ---------------- math helpers ----------------
__device__ __forceinline__ float gelu_f(float x) {
    return 0.5f * x * (1.0f + erff(x * 0.70710678118654752f));
}
__device__ __forceinline__ float softplus_f(float x) {
    return fmaxf(x, 0.0f) + log1pf(expf(-fabsf(x)));
}
// value for plane p (0 = hi, 1 = md)
__device__ __forceinline__ __nv_bfloat16 planeval(float v, int plane) {
    __nv_bfloat16 h = __float2bfloat16(v);
    if (plane == 0) return h;
    return __float2bfloat16(v - __bfloat162float(h));
}
// write hi at buf[base], md at buf[base+64]
__device__ __forceinline__ void planewrite(float v, __nv_bfloat16* buf, long long base) {
    __nv_bfloat16 h = __float2bfloat16(v);
    buf[base] = h;
    buf[base + 64] = __float2bfloat16(v - __bfloat162float(h));
}

// ---------------- PTX helpers ----------------
__device__ __forceinline__ uint32_t smem_u32(const void* p) {
    uint32_t a;
    asm("{ .reg .u64 t; cvta.to.shared.u64 t, %1; cvt.u32.u64 %0, t; }" : "=r"(a) : "l"(p));
    return a;
}
#define SW128(x) ((x) ^ (((x) >> 3) & 0x70))
__device__ __forceinline__ void cp16(uint32_t dst, const void* src) {
    asm volatile("cp.async.cg.shared.global [%0], [%1], 16;" :: "r"(dst), "l"(src) : "memory");
}
__device__ __forceinline__ void ldsm4(uint32_t* r, uint32_t addr) {
    asm volatile("ldmatrix.sync.aligned.m8n8.x4.shared.b16 {%0,%1,%2,%3}, [%4];"
                 : "=r"(r[0]), "=r"(r[1]), "=r"(r[2]), "=r"(r[3]) : "r"(addr));
}
__device__ __forceinline__ void mma16(float* c, const uint32_t* a, const uint32_t* b) {
    asm volatile(
        "mma.sync.aligned.m16n8k16.row.col.f32.bf16.bf16.f32 "
        "{%0,%1,%2,%3},{%4,%5,%6,%7},{%8,%9},{%0,%1,%2,%3};"
        : "+f"(c[0]), "+f"(c[1]), "+f"(c[2]), "+f"(c[3])
        : "r"(a[0]), "r"(a[1]), "r"(a[2]), "r"(a[3]), "r"(b[0]), "r"(b[1]));
}

// ---------------- bf16 tensor-core GEMM (hi/md planes, BM=64, BN=64) ----------
// UNCHANGED from the 4324us round-15 build.
__global__ void __launch_bounds__(256, 3) bgemm_k(
        const __nv_bfloat16* __restrict__ A,
        const __nv_bfloat16* __restrict__ Bw,
        const float* __restrict__ bias,
        void* __restrict__ Cv,
        int NC, int bpitch,
        int a_rpb, long long a_bs, int a_rs,
        int o_rpb, long long o_bs, int o_rs,
        int act, int outmode, int accum,
        int ksplit, long long zoff) {
    extern __shared__ char smem_raw[];
    uint32_t sb = (smem_u32(smem_raw) + 1023) & ~1023u;
    const uint32_t STG = 32768u;

    int tid = threadIdx.x, wid = tid >> 5, lane = tid & 31;
    int bm = blockIdx.y * 64, bn = blockIdx.x * 64;
    int c0 = blockIdx.z * ksplit;
    int c1 = min(NC, c0 + ksplit);

    const char* aptr0; int adel[4]; uint32_t adst[4];
    const char* bptr0; int bdel[4]; uint32_t bdst[4];
    {
        long long aref = 0;
#pragma unroll
        for (int i = 0; i < 4; i++) {
            int G = tid + i * 256;
            int row = G >> 4, sub = G & 15;
            int gm = bm + row;
            long long off = 2 * ((long long)(gm / a_rpb) * a_bs + (long long)(gm % a_rpb) * a_rs)
                          + sub * 16;
            if (i == 0) { aref = off; aptr0 = (const char*)A + off; }
            adel[i] = (int)(off - aref);
            adst[i] = (uint32_t)((sub >> 3) * 8192) + SW128((uint32_t)(row * 128 + (sub & 7) * 16));
        }
        long long bref = 0;
#pragma unroll
        for (int i = 0; i < 4; i++) {
            int G = tid + i * 256;
            int row = G >> 4, sub = G & 15;
            long long off = 2LL * (bn + row) * bpitch + sub * 16;
            if (i == 0) { bref = off; bptr0 = (const char*)Bw + off; }
            bdel[i] = (int)(off - bref);
            bdst[i] = 16384u + (uint32_t)((sub >> 3) * 8192) + SW128((uint32_t)(row * 128 + (sub & 7) * 16));
        }
    }

    auto issue = [&](int c) {
        uint32_t base = sb + (uint32_t)(c & 1) * STG;
        const char* ap = aptr0 + (long long)c * 256;
        const char* bp = bptr0 + (long long)c * 256;
#pragma unroll
        for (int i = 0; i < 4; i++) cp16(base + adst[i], ap + adel[i]);
#pragma unroll
        for (int i = 0; i < 4; i++) cp16(base + bdst[i], bp + bdel[i]);
        asm volatile("cp.async.commit_group;" ::: "memory");
    };

    int wm = wid & 1, wn = wid >> 1;
    float acc[2][2][4];
#pragma unroll
    for (int i = 0; i < 2; i++)
#pragma unroll
        for (int j = 0; j < 2; j++)
#pragma unroll
            for (int r = 0; r < 4; r++) acc[i][j][r] = 0.0f;

    uint32_t arp[2], atsw[2];
    {
        int a_trow = (lane & 7) + ((lane >> 3) & 1) * 8;
        uint32_t a_tcol = (uint32_t)((lane >> 4) * 16);
#pragma unroll
        for (int i = 0; i < 2; i++) {
            uint32_t rp = (uint32_t)((wm * 32 + i * 16 + a_trow) * 128);
            arp[i] = rp;
            atsw[i] = a_tcol ^ ((rp >> 3) & 0x70);
        }
    }
    uint32_t brp, btsw;
    {
        int b_trow = ((lane >> 4) << 3) + (lane & 7);
        uint32_t b_tcol = (uint32_t)(((lane >> 3) & 1) * 16);
        uint32_t rp = (uint32_t)((wn * 16 + b_trow) * 128);
        brp = rp;
        btsw = b_tcol ^ ((rp >> 3) & 0x70);
    }

    issue(c0);
    if (c0 + 1 < c1) issue(c0 + 1);

    for (int c = c0; c < c1; c++) {
        if (c + 1 < c1) asm volatile("cp.async.wait_group 1;" ::: "memory");
        else            asm volatile("cp.async.wait_group 0;" ::: "memory");
        __syncthreads();

        uint32_t base = sb + (uint32_t)(c & 1) * STG;
        uint32_t abase0 = base + arp[0];
        uint32_t abase1 = base + arp[1];
        uint32_t bbase  = base + 16384u + brp;
#pragma unroll
        for (int ks = 0; ks < 4; ks++) {
            uint32_t klo = (uint32_t)(ks << 5);
            uint32_t ahi[2][4], amd[2][4];
            {
                uint32_t lo0 = klo ^ atsw[0];
                ldsm4(ahi[0], abase0 + lo0);
                ldsm4(amd[0], abase0 + 8192u + lo0);
                uint32_t lo1 = klo ^ atsw[1];
                ldsm4(ahi[1], abase1 + lo1);
                ldsm4(amd[1], abase1 + 8192u + lo1);
            }
            uint32_t bhi[2][2], bmd[2][2];
            {
                uint32_t lob = klo ^ btsw;
                uint32_t r[4];
                ldsm4(r, bbase + lob);
                bhi[0][0] = r[0]; bhi[0][1] = r[1]; bhi[1][0] = r[2]; bhi[1][1] = r[3];
                ldsm4(r, bbase + 8192u + lob);
                bmd[0][0] = r[0]; bmd[0][1] = r[1]; bmd[1][0] = r[2]; bmd[1][1] = r[3];
            }
#pragma unroll
            for (int i = 0; i < 2; i++)
#pragma unroll
                for (int j = 0; j < 2; j++) {
                    mma16(acc[i][j], ahi[i], bhi[j]);
                    mma16(acc[i][j], ahi[i], bmd[j]);
                    mma16(acc[i][j], amd[i], bhi[j]);
                }
        }

        if (c + 2 < c1) {
            __syncthreads();
            issue(c + 2);
        }
    }

    // epilogue
    float* Cz = (float*)Cv + blockIdx.z * zoff;
#pragma unroll
    for (int i = 0; i < 2; i++) {
#pragma unroll
        for (int h = 0; h < 2; h++) {
            int gm = bm + wm * 32 + i * 16 + (lane >> 2) + h * 8;
            long long orow = (long long)(gm / o_rpb) * o_bs + (long long)(gm % o_rpb) * o_rs;
#pragma unroll
            for (int j = 0; j < 2; j++) {
                int gn = bn + wn * 16 + j * 8 + (lane & 3) * 2;
#pragma unroll
                for (int e = 0; e < 2; e++) {
                    float v = acc[i][j][h * 2 + e];
                    int gne = gn + e;
                    if (bias) v += bias[gne];
                    if (act == 1) v = gelu_f(v);
                    else if (act == 2) v = softplus_f(v);
                    if (outmode == 0) {
                        long long o = orow + gne;
                        if (accum) v += Cz[o];
                        Cz[o] = v;
                    } else {
                        __nv_bfloat16* C = (__nv_bfloat16*)Cv;
                        long long o = orow + ((gne >> 6) * 128 + (gne & 63));
                        planewrite(v, C, o);
                    }
                }
            }
        }
    }
}

// ---------------- ONE fused prep/conversion kernel ----------------
__global__ void prep_all_k(const float* __restrict__ feats,
                           const float* __restrict__ conv1_w,
                           const float* __restrict__ conv2_w,
                           const float* __restrict__ head_w,
                           const float* __restrict__ in_proj,
                           const float* __restrict__ x_proj,
                           const float* __restrict__ dt_w,
                           const float* __restrict__ out_proj,
                           __nv_bfloat16* __restrict__ w1t,
                           __nv_bfloat16* __restrict__ w2t,
                           __nv_bfloat16* __restrict__ fa,
                           __nv_bfloat16* __restrict__ out1p,
                           __nv_bfloat16* __restrict__ headW,
                           __nv_bfloat16* __restrict__ inW,
                           __nv_bfloat16* __restrict__ xW,
                           __nv_bfloat16* __restrict__ dtW,
                           __nv_bfloat16* __restrict__ outW) {
    long long i = (long long)blockIdx.x * 256 + threadIdx.x;
    if (i >= R_TOT) return;
    if (i < R_W1) {
        int n = (int)(i >> 9), e = (int)(i & 511);
        int sub = e & 127, plane = sub >> 6;
        int k = (e >> 7) * 64 + (sub & 63);
        float val = 0.0f;
        if (k < 240) val = conv1_w[n * 240 + (k % 80) * 3 + (k / 80)];
        w1t[i] = planeval(val, plane);
        return;
    }
    i -= R_W1;
    if (i < R_W2) {
        int n = (int)(i / 3072), e = (int)(i % 3072);
        int sub = e & 127, plane = sub >> 6;
        int k = (e >> 7) * 64 + (sub & 63);
        int tap = k / 512, c = k & 511;
        w2t[i] = planeval(conv2_w[n * 1536 + c * 3 + tap], plane);
        return;
    }
    i -= R_W2;
    if (i < R_C1A) {
        int m = (int)(i >> 9), e = (int)(i & 511);
        int sub = e & 127, plane = sub >> 6;
        int k = (e >> 7) * 64 + (sub & 63);
        float val = 0.0f;
        if (k < 240) {
            int tap = k / 80, c = k % 80;
            int b = m / 800, p = m % 800;
            int tin = 2 * p - 1 + tap;
            if (tin >= 0 && tin < 1600)
                val = feats[((long long)b * 1600 + tin) * 80 + c];
        }
        fa[i] = planeval(val, plane);
        return;
    }
    i -= R_C1A;
    if (i < R_ZP) {
        int e = (int)(i & 1023); int r = (int)(i >> 10);
        int b = r >> 1; int t = (r & 1) ? 801 : 0;
        out1p[(long long)(b * 802 + t) * 1024 + e] = __float2bfloat16(0.0f);
        return;
    }
    i -= R_ZP;
    if (i < R_HEAD) {
        int n = (int)(i >> 10), e = (int)(i & 1023);
        int sub = e & 127, plane = sub >> 6;
        int k = (e >> 7) * 64 + (sub & 63);
        headW[i] = planeval(head_w[k * 1024 + n], plane);
        return;
    }
    i -= R_HEAD;
    // per-layer weights
    int li = (int)(i / SLAYER);
    long long r = i % SLAYER;
    const float* inw = in_proj + (long long)li * Dm * 2048;
    const float* xw  = x_proj + (long long)li * DIc * 64;
    const float* dtw = dt_w + (long long)li * 32 * DIc;
    const float* outw= out_proj + (long long)li * DIc * Dm;
    if (r < S0E) {
        int n = (int)(r >> 10), e = (int)(r & 1023);
        int sub = e & 127, plane = sub >> 6;
        int k = (e >> 7) * 64 + (sub & 63);
        inW[(long long)li * S0E + r] = planeval(inw[k * 2048 + n], plane);
        return;
    }
    r -= S0E;
    if (r < S1E) {
        int n = (int)(r >> 11), e = (int)(r & 2047);
        int sub = e & 127, plane = sub >> 6;
        int k = (e >> 7) * 64 + (sub & 63);
        xW[(long long)li * S1E + r] = planeval(xw[k * 64 + n], plane);
        return;
    }
    r -= S1E;
    if (r < S2E) {
        int n = (int)(r >> 7), e = (int)(r & 127);
        int plane = e >> 6, k = e & 63;
        float val = (k < 32) ? dtw[k * 1024 + n] : 0.0f;
        dtW[(long long)li * S2E + r] = planeval(val, plane);
        return;
    }
    r -= S2E;
    {
        int n = (int)(r >> 11), e = (int)(r & 2047);
        int sub = e & 127, plane = sub >> 6;
        int k = (e >> 7) * 64 + (sub & 63);
        outW[(long long)li * S3E + r] = planeval(outw[k * 512 + n], plane);
    }
}

// ---------------- split-K combine -> proj f32 + proj_t planes ----------------
__global__ void xcomb_k(const float* __restrict__ parts, float* __restrict__ proj,
                        __nv_bfloat16* __restrict__ pt) {
    int i = blockIdx.x * 256 + threadIdx.x;
    if (i >= M4 * 128) return;
    int m = i >> 7, e = i & 127;
    if (e < 64) {
        int o = m * 64 + e;
        proj[o] = parts[o] + parts[204800 + o] + parts[2 * 204800 + o] + parts[3 * 204800 + o];
    }
    int plane = e >> 6, k = e & 63;
    float v = 0.0f;
    if (k < 32) {
        int o = m * 64 + k;
        v = parts[o] + parts[204800 + o] + parts[2 * 204800 + o] + parts[3 * 204800 + o];
    }
    pt[i] = planeval(v, plane);
}

__global__ void x_t_k(const float* __restrict__ x, __nv_bfloat16* __restrict__ xt) {
    int i = blockIdx.x * 256 + threadIdx.x;
    if (i >= M4 * Dm) return;
    int m = i >> 9, c = i & 511;
    planewrite(x[i], xt, (long long)m * 1024 + ((c >> 6) * 128 + (c & 63)));
}

// ---------------- RMSNorm -> planes ----------------
__global__ void rmsnorm_t_k(const float* __restrict__ x, const float* __restrict__ w,
                            __nv_bfloat16* __restrict__ xnt) {
    int row = blockIdx.x;
    int tid = threadIdx.x;   // 128
    const float* xr = x + (long long)row * Dm;
    float v[4];
    float s = 0.0f;
#pragma unroll
    for (int i = 0; i < 4; i++) { v[i] = xr[tid + 128 * i]; s += v[i] * v[i]; }
#pragma unroll
    for (int o = 16; o; o >>= 1) s += __shfl_xor_sync(0xffffffffu, s, o);
    __shared__ float ws[4];
    if ((tid & 31) == 0) ws[tid >> 5] = s;
    __syncthreads();
    float tot = ws[0] + ws[1] + ws[2] + ws[3];
    float rs = rsqrtf(tot * (1.0f / Dm) + 1e-5f);
#pragma unroll
    for (int i = 0; i < 4; i++) {
        int c = tid + 128 * i;
        planewrite(v[i] * rs * w[c], xnt, (long long)row * 1024 + ((c >> 6) * 128 + (c & 63)));
    }
}

// ---------------- depthwise causal conv (K=4) + SiLU -> planes ONLY ----------
__global__ void dwconv_k(const float* __restrict__ xz, const float* __restrict__ cw,
                         const float* __restrict__ cb, __nv_bfloat16* __restrict__ xit) {
    int idx = blockIdx.x * 256 + threadIdx.x;
    if (idx >= M4 * DIc) return;
    int d = idx & (DIc - 1);
    int m = idx >> 10;
    int t = m % T4;
    float w0 = cw[d * 4 + 0], w1 = cw[d * 4 + 1], w2 = cw[d * 4 + 2], w3 = cw[d * 4 + 3];
    const float* base = xz + (long long)m * 2048 + d;
    float acc = w3 * base[0];
    if (t >= 1) acc = fmaf(w2, base[-2048], acc);
    if (t >= 2) acc = fmaf(w1, base[-2 * 2048], acc);
    if (t >= 3) acc = fmaf(w0, base[-3 * 2048], acc);
    acc += cb[d];
    float s = acc / (1.0f + expf(-acc));
    planewrite(s, xit, (long long)m * 2048 + ((d >> 6) * 128 + (d & 63)));
}

// ---------------- selective scan (xi from planes) -> yc planes ----------------
__global__ void scan_k(const float* __restrict__ dt, const __nv_bfloat16* __restrict__ xit,
                       const float* __restrict__ proj, const float* __restrict__ xz,
                       const float* __restrict__ A_log, const float* __restrict__ dskip,
                       __nv_bfloat16* __restrict__ yct) {
    int w = (blockIdx.x * blockDim.x + threadIdx.x) >> 5;
    int lane = threadIdx.x & 31;
    int b = w >> 9;
    int dp = w & 511;
    int d = dp * 2 + (lane >> 4);
    int n = lane & 15;
    float Ac = -expf(A_log[d * Nst + n]);
    float dsk = dskip[d];
    float h = 0.0f;
    int mb = b * T4;
    long long xibase = (long long)mb * 2048 + ((d >> 6) * 128 + (d & 63));
    for (int t = 0; t < T4; t++) {
        int m = mb + t;
        float dtv = dt[m * DIc + d];
        long long xio = xibase + (long long)t * 2048;
        float xiv = __bfloat162float(xit[xio]) + __bfloat162float(xit[xio + 64]);
        float Bv = proj[m * 64 + 32 + n];
        float Cv = proj[m * 64 + 48 + n];
        float dA = __expf(dtv * Ac);
        h = fmaf(dA, h, dtv * xiv * Bv);
        float p = h * Cv;
        p += __shfl_xor_sync(0xffffffffu, p, 8);
        p += __shfl_xor_sync(0xffffffffu, p, 4);
        p += __shfl_xor_sync(0xffffffffu, p, 2);
        p += __shfl_xor_sync(0xffffffffu, p, 1);
        if (n == 0) {
            float zv = xz[(long long)m * 2048 + DIc + d];
            float yv = p + dsk * xiv;
            planewrite(yv * zv / (1.0f + __expf(-zv)), yct,
                       (long long)m * 2048 + ((d >> 6) * 128 + (d & 63)));
        }
    }
}

__global__ void lens_k(const int* __restrict__ fl, float* __restrict__ out, int out_size) {
    int b = threadIdx.x;
    if (b < Bsz && out_size >= M4 * Vv + Bsz) {
        int v = fl[b] >> 2;
        if (v < 1) v = 1;
        out[M4 * Vv + b] = (float)v;
    }
}

// ---------------- launcher ----------------
extern "C" void kernel_launch(void* const* d_in, const int* in_sizes, int n_in,
                              void* d_out, int out_size) {
    (void)in_sizes; (void)n_in;
    const float* feats    = (const float*)d_in[0];
    const int*   feat_lens= (const int*)  d_in[1];
    const float* conv1_w  = (const float*)d_in[2];
    const float* conv1_b  = (const float*)d_in[3];
    const float* conv2_w  = (const float*)d_in[4];
    const float* conv2_b  = (const float*)d_in[5];
    const float* norm_w   = (const float*)d_in[6];
    const float* in_proj  = (const float*)d_in[7];
    const float* dwc_w    = (const float*)d_in[8];
    const float* dwc_b    = (const float*)d_in[9];
    const float* x_proj   = (const float*)d_in[10];
    const float* dt_w     = (const float*)d_in[11];
    const float* dt_b     = (const float*)d_in[12];
    const float* A_log    = (const float*)d_in[13];
    const float* D_skip   = (const float*)d_in[14];
    const float* out_proj = (const float*)d_in[15];
    const float* head_w   = (const float*)d_in[16];
    const float* head_b   = (const float*)d_in[17];
    float* out = (float*)d_out;

    void* sym = nullptr;
    cudaGetSymbolAddress(&sym, g_buf);
    float* gb = (float*)sym;
    __nv_bfloat16* featspA = (__nv_bfloat16*)(gb + OFF_FEATSPA);
    __nv_bfloat16* out1p   = (__nv_bfloat16*)(gb + OFF_OUT1P);
    __nv_bfloat16* xn_t    = (__nv_bfloat16*)(gb + OFF_XN_T);
    float*         xz      = gb + OFF_XZ;
    __nv_bfloat16* xi_t    = (__nv_bfloat16*)(gb + OFF_XI_T);
    float*         dtbuf   = gb + OFF_DT;
    float*         proj    = gb + OFF_PROJ;
    __nv_bfloat16* proj_t  = (__nv_bfloat16*)(gb + OFF_PROJ_T);
    __nv_bfloat16* yc_t    = (__nv_bfloat16*)(gb + OFF_YC_T);
    float*         x       = gb + OFF_X;
    __nv_bfloat16* x_t     = (__nv_bfloat16*)(gb + OFF_X_T);
    __nv_bfloat16* w1t     = (__nv_bfloat16*)(gb + OFF_W1T);
    __nv_bfloat16* w2t     = (__nv_bfloat16*)(gb + OFF_W2T);
    __nv_bfloat16* inW     = (__nv_bfloat16*)(gb + OFF_INW);
    __nv_bfloat16* xW      = (__nv_bfloat16*)(gb + OFF_XW);
    __nv_bfloat16* dtW     = (__nv_bfloat16*)(gb + OFF_DTW);
    __nv_bfloat16* outW    = (__nv_bfloat16*)(gb + OFF_OUTW);
    __nv_bfloat16* headW   = (__nv_bfloat16*)(gb + OFF_HEADW);
    float*         xpart   = gb + OFF_XPART;

    const int SMB = 1024 + 2 * 32768;   // 66560 -> 3 CTAs/SM
    cudaFuncSetAttribute(bgemm_k, cudaFuncAttributeMaxDynamicSharedMemorySize, SMB);
    const int BIGK = 1 << 28;

    // ONE fused prep/conversion launch
    prep_all_k<<<(int)((R_TOT + 255LL) / 256), 256>>>(
        feats, conv1_w, conv2_w, head_w, in_proj, x_proj, dt_w, out_proj,
        w1t, w2t, featspA, out1p, headW, inW, xW, dtW, outW);

    // conv1: M=6400, N=512, K=256 -> out1p planes (skip pad row t=0)
    bgemm_k<<<dim3(8, 100), 256, SMB>>>(
        featspA, w1t, conv1_b, out1p + 1024,
        4, 512,
        M2, 0, 512,
        800, 802LL * 1024, 1024,
        1, 1, 0, BIGK, 0);

    // conv2: M=3200, N=512, K=1536 -> x f32
    bgemm_k<<<dim3(8, 50), 256, SMB>>>(
        out1p, w2t, conv2_b, x,
        24, 3072,
        400, 802LL * 1024, 2048,
        M4, 0, 512,
        1, 0, 0, BIGK, 0);

    for (int l = 0; l < Ll; l++) {
        rmsnorm_t_k<<<M4, 128>>>(x, norm_w + l * Dm, xn_t);

        // xz = xn @ in_proj  (3200x2048, K=512)
        bgemm_k<<<dim3(32, 50), 256, SMB>>>(
            xn_t, inW + (size_t)l * S0E, nullptr, xz,
            8, 1024,
            M4, 0, 1024,
            M4, 0, 2048,
            0, 0, 0, BIGK, 0);

        dwconv_k<<<(M4 * DIc + 255) / 256, 256>>>(
            xz, dwc_w + l * DIc * 4, dwc_b + l * DIc, xi_t);

        // proj partials = xi @ x_proj  (3200x64, K=1024, split-K x4)
        bgemm_k<<<dim3(1, 50, 4), 256, SMB>>>(
            xi_t, xW + (size_t)l * S1E, nullptr, xpart,
            16, 2048,
            M4, 0, 2048,
            M4, 0, 64,
            0, 0, 0, 4, 204800);

        xcomb_k<<<(M4 * 128 + 255) / 256, 256>>>(xpart, proj, proj_t);

        // dt = softplus(proj @ dt_w + dt_b)  (3200x1024, K=64)
        bgemm_k<<<dim3(16, 50), 256, SMB>>>(
            proj_t, dtW + (size_t)l * S2E, dt_b + l * DIc, dtbuf,
            1, 128,
            M4, 0, 128,
            M4, 0, 1024,
            2, 0, 0, BIGK, 0);

        scan_k<<<512, 256>>>(dtbuf, xi_t, proj, xz,
                             A_log + (size_t)l * DIc * Nst, D_skip + l * DIc, yc_t);

        // x += yc @ out_proj  (3200x512, K=1024)
        bgemm_k<<<dim3(8, 50), 256, SMB>>>(
            yc_t, outW + (size_t)l * S3E, nullptr, x,
            16, 2048,
            M4, 0, 2048,
            M4, 0, 512,
            0, 0, 1, BIGK, 0);
    }

    x_t_k<<<(M4 * Dm + 255) / 256, 256>>>(x, x_t);

    // logits = x @ head_w + head_b  (3200x1024, K=512)
    bgemm_k<<<dim3(16, 50), 256, SMB>>>(
        x_t, headW, head_b, out,
        8, 1024,
        M4, 0, 1024,
        M4, 0, 1024,
        0, 0, 0, BIGK, 0);

    lens_k<<<1, 32>>>(feat_lens, out, out_size);
}